// round 3
// baseline (speedup 1.0000x reference)
#include <cuda_runtime.h>
#include <cuda_bf16.h>
#include <cstdint>

// Problem constants (dataset-fixed; runtime values read from in_sizes and guarded)
#define MAX_N 50000
#define MAX_E 800000
#define IN_CH 128
#define HID_CH 256
#define OUT_CH 128

// Scratch (device globals — allocation-free rule). Referenced ONLY from device
// code by symbol; host never queries their addresses.
__device__ float g_agg1[(size_t)MAX_N * IN_CH];    // 25.6 MB
__device__ float g_agg2[(size_t)MAX_N * HID_CH];   // 51.2 MB
__device__ float g_h[(size_t)MAX_N * HID_CH];      // 51.2 MB
__device__ float g_deg[MAX_N];
__device__ float g_inv[MAX_N];
__device__ int   g_is64;   // 1 if edge_index is int64, 0 if int32

// ---------------------------------------------------------------------------
// Detect edge_index dtype. For little-endian int64 values < 2^31, every odd
// 32-bit word is zero. For int32 data the odd words are random node indices.
// OR of 128 odd words == 0  =>  int64.  (P[false positive] ~ (1/50000)^128.)
// ---------------------------------------------------------------------------
__global__ void detect_dtype_kernel(const int* __restrict__ ei32, int E) {
    // single block, 128 threads; word count available >= 2*E >= 256 words
    __shared__ int red[128];
    int t = threadIdx.x;
    int v = ei32[2 * t + 1];           // odd words of the first 256 words
    red[t] = v;
    __syncthreads();
    for (int s = 64; s > 0; s >>= 1) {
        if (t < s) red[t] |= red[t + s];
        __syncthreads();
    }
    if (t == 0) g_is64 = (red[0] == 0) ? 1 : 0;
}

// ---------------------------------------------------------------------------
// Zero the accumulators + degree (float4 grid-stride)
// ---------------------------------------------------------------------------
__global__ void zero_kernel(int N) {
    size_t i = (size_t)blockIdx.x * blockDim.x + threadIdx.x;
    size_t n1 = (size_t)N * (IN_CH / 4);    // agg1 as float4
    size_t n2 = (size_t)N * (HID_CH / 4);   // agg2 as float4
    float4 z = make_float4(0.f, 0.f, 0.f, 0.f);
    if (i < n1) reinterpret_cast<float4*>(g_agg1)[i] = z;
    if (i < n2) reinterpret_cast<float4*>(g_agg2)[i] = z;
    if (i < (size_t)N) g_deg[i] = 0.f;
}

// ---------------------------------------------------------------------------
// Scatter-add: one warp per edge. Each lane loads a float4 of the source row
// and does 4 scalar atomicAdds into the destination row.
// LAYER 1: X = x (param), AGG = g_agg1, also counts degree.
// LAYER 2: X = g_h,       AGG = g_agg2.
// ---------------------------------------------------------------------------
template <int LAYER>
__global__ void scatter_kernel(const float* __restrict__ Xin,
                               const void* __restrict__ ei,
                               int E, int N) {
    constexpr int C  = (LAYER == 1) ? IN_CH : HID_CH;
    constexpr int C4 = C / 4;
    const float* __restrict__ X  = (LAYER == 1) ? Xin : g_h;
    float* __restrict__ AGG      = (LAYER == 1) ? g_agg1 : g_agg2;

    int g = blockIdx.x * blockDim.x + threadIdx.x;
    int e = g >> 5;
    int lane = g & 31;
    if (e >= E) return;

    int src, dst;
    if (g_is64) {
        src = (int)reinterpret_cast<const long long*>(ei)[e];
        dst = (int)reinterpret_cast<const long long*>(ei)[(size_t)E + e];
    } else {
        src = reinterpret_cast<const int*>(ei)[e];
        dst = reinterpret_cast<const int*>(ei)[(size_t)E + e];
    }
    // defensive: never deref a wild index (turns crashes into diagnosable errors)
    if ((unsigned)src >= (unsigned)N || (unsigned)dst >= (unsigned)N) return;

    const float4* xs = reinterpret_cast<const float4*>(X) + (size_t)src * C4;
    float* ag = AGG + (size_t)dst * C;
#pragma unroll
    for (int v = lane; v < C4; v += 32) {
        float4 val = xs[v];
        atomicAdd(&ag[v * 4 + 0], val.x);
        atomicAdd(&ag[v * 4 + 1], val.y);
        atomicAdd(&ag[v * 4 + 2], val.z);
        atomicAdd(&ag[v * 4 + 3], val.w);
    }
    if (LAYER == 1 && lane == 0) atomicAdd(&g_deg[dst], 1.0f);
}

// ---------------------------------------------------------------------------
// inv_deg[i] = 1 / max(deg[i], 1)
// ---------------------------------------------------------------------------
__global__ void invdeg_kernel(int N) {
    int i = blockIdx.x * blockDim.x + threadIdx.x;
    if (i < N) g_inv[i] = 1.0f / fmaxf(g_deg[i], 1.0f);
}

// ---------------------------------------------------------------------------
// Fused SAGE GEMM:
//   out[n][o] = act( x[n]·Wr[o] + (agg[n]*inv[n])·Wl[o] + bias[o] )
// Single virtual-K GEMM with K' = 2K:
//   A'[n][k] = k<K ? X[n][k] : AGG[n][k-K]*inv[n]
//   W'[o][k] = k<K ? Wr[o][k] : Wl[o][k-K]
// 64x64 block tile, 256 threads, 4x4 microtile per thread.
// LAYER 1: X = x (param),  AGG = g_agg1, out = g_h,  RELU, K=128, OUTC=256
// LAYER 2: X = g_h,        AGG = g_agg2, out = param, none, K=256, OUTC=128
// ---------------------------------------------------------------------------
template <int LAYER>
__global__ void __launch_bounds__(256)
gemm_fused_kernel(const float* __restrict__ Xin,
                  const float* __restrict__ Wr,
                  const float* __restrict__ Wl,
                  const float* __restrict__ bias,
                  float* __restrict__ outp,
                  int N) {
    constexpr int K    = (LAYER == 1) ? IN_CH : HID_CH;
    constexpr int OUTC = (LAYER == 1) ? HID_CH : OUT_CH;
    constexpr bool RELU = (LAYER == 1);
    const float* __restrict__ X   = (LAYER == 1) ? Xin : g_h;
    const float* __restrict__ AGG = (LAYER == 1) ? g_agg1 : g_agg2;
    float* __restrict__ out       = (LAYER == 1) ? g_h : outp;

    __shared__ float As[64][33];
    __shared__ float Bs[64][33];
    __shared__ float invs[64];

    const int tid = threadIdx.x;
    const int tx = tid & 15;       // out dimension
    const int ty = tid >> 4;       // node dimension
    const int n0 = blockIdx.x * 64;
    const int o0 = blockIdx.y * 64;

    if (tid < 64) {
        int n = n0 + tid;
        invs[tid] = (n < N) ? g_inv[n] : 0.f;
    }

    float acc[4][4] = {};

    for (int kc = 0; kc < 2 * K; kc += 32) {
        __syncthreads();
#pragma unroll
        for (int i = 0; i < 8; i++) {
            int idx = tid + i * 256;
            int r = idx >> 5;
            int c = idx & 31;
            int kg = kc + c;
            // A tile
            int n = n0 + r;
            float v = 0.f;
            if (n < N) {
                if (kg < K) v = X[(size_t)n * K + kg];
                else        v = AGG[(size_t)n * K + (kg - K)] * invs[r];
            }
            As[r][c] = v;
            // B tile (OUTC divisible by 64, always in range)
            int o = o0 + r;
            float w = (kg < K) ? Wr[(size_t)o * K + kg]
                               : Wl[(size_t)o * K + (kg - K)];
            Bs[r][c] = w;
        }
        __syncthreads();
#pragma unroll
        for (int k = 0; k < 32; k++) {
            float a[4], b[4];
#pragma unroll
            for (int i = 0; i < 4; i++) a[i] = As[ty * 4 + i][k];
#pragma unroll
            for (int j = 0; j < 4; j++) b[j] = Bs[tx * 4 + j][k];
#pragma unroll
            for (int i = 0; i < 4; i++)
#pragma unroll
                for (int j = 0; j < 4; j++)
                    acc[i][j] += a[i] * b[j];
        }
    }

    float bj[4];
#pragma unroll
    for (int j = 0; j < 4; j++) bj[j] = bias[o0 + tx * 4 + j];

#pragma unroll
    for (int i = 0; i < 4; i++) {
        int n = n0 + ty * 4 + i;
        if (n >= N) continue;
#pragma unroll
        for (int j = 0; j < 4; j++) {
            int o = o0 + tx * 4 + j;
            float r = acc[i][j] + bj[j];
            if (RELU) r = fmaxf(r, 0.f);
            out[(size_t)n * OUTC + o] = r;
        }
    }
}

// ---------------------------------------------------------------------------
// Launcher — kernel launches only; graph-capturable.
// ---------------------------------------------------------------------------
extern "C" void kernel_launch(void* const* d_in, const int* in_sizes, int n_in,
                              void* d_out, int out_size) {
    const float* x       = (const float*)d_in[0];
    const void*  ei      = d_in[1];
    const float* W1l     = (const float*)d_in[2];
    const float* b1l     = (const float*)d_in[3];
    const float* W1r     = (const float*)d_in[4];
    const float* W2l     = (const float*)d_in[5];
    const float* b2l     = (const float*)d_in[6];
    const float* W2r     = (const float*)d_in[7];
    float* out           = (float*)d_out;

    const int N = in_sizes[0] / IN_CH;
    const int E = in_sizes[1] / 2;

    // 0. detect edge_index dtype (int32 vs int64)
    detect_dtype_kernel<<<1, 128>>>((const int*)ei, E);

    // 1. zero accumulators + degree
    {
        size_t total = (size_t)N * (HID_CH / 4);  // covers all three ranges
        int blocks = (int)((total + 255) / 256);
        zero_kernel<<<blocks, 256>>>(N);
    }

    // 2. layer-1 scatter (x -> g_agg1) + degree
    {
        long threads = (long)E * 32;
        int blocks = (int)((threads + 255) / 256);
        scatter_kernel<1><<<blocks, 256>>>(x, ei, E, N);
    }

    // 3. inverse degree
    invdeg_kernel<<<(N + 255) / 256, 256>>>(N);

    // 4. layer-1 fused GEMM + ReLU -> g_h [N, 256]
    {
        dim3 grid((N + 63) / 64, HID_CH / 64);
        gemm_fused_kernel<1><<<grid, 256>>>(x, W1r, W1l, b1l, nullptr, N);
    }

    // 5. layer-2 scatter (g_h -> g_agg2)
    {
        long threads = (long)E * 32;
        int blocks = (int)((threads + 255) / 256);
        scatter_kernel<2><<<blocks, 256>>>(nullptr, ei, E, N);
    }

    // 6. layer-2 fused GEMM -> out [N, 128]
    {
        dim3 grid((N + 63) / 64, OUT_CH / 64);
        gemm_fused_kernel<2><<<grid, 256>>>(nullptr, W2r, W2l, b2l, out, N);
    }
}

// round 4
// speedup vs baseline: 3.0096x; 3.0096x over previous
#include <cuda_runtime.h>
#include <cuda_bf16.h>
#include <cstdint>

#define MAX_N 50000
#define MAX_E 800000
#define IN_CH 128
#define HID_CH 256
#define OUT_CH 128

// ---------------------------------------------------------------------------
// Device scratch (allocation-free rule)
// ---------------------------------------------------------------------------
__device__ float g_agg1[(size_t)MAX_N * IN_CH];     // mean-agg of x      [N,128]
__device__ float g_h[(size_t)MAX_N * HID_CH];       // layer-1 output     [N,256]
__device__ float g_tr[(size_t)MAX_N * HID_CH];      // [t | r] layer-2    [N,256]
__device__ int   g_cnt[MAX_N];                      // degree histogram
__device__ int   g_fill[MAX_N];                     // bucket fill cursor
__device__ int   g_rowptr[MAX_N + 1];               // CSR row pointers (by dst)
__device__ int   g_colidx[MAX_E];                   // CSR column (src) indices
__device__ int   g_is64;                            // edge_index dtype flag

// ---------------------------------------------------------------------------
// Edge dtype sniff: int64 < 2^31 has all-zero odd 32-bit words.
// ---------------------------------------------------------------------------
__global__ void detect_dtype_kernel(const int* __restrict__ ei32) {
    __shared__ int red[128];
    int t = threadIdx.x;
    red[t] = ei32[2 * t + 1];
    __syncthreads();
    for (int s = 64; s > 0; s >>= 1) {
        if (t < s) red[t] |= red[t + s];
        __syncthreads();
    }
    if (t == 0) g_is64 = (red[0] == 0) ? 1 : 0;
}

__device__ __forceinline__ void load_edge(const void* ei, int e, int E,
                                          int& src, int& dst) {
    if (g_is64) {
        src = (int)reinterpret_cast<const long long*>(ei)[e];
        dst = (int)reinterpret_cast<const long long*>(ei)[(size_t)E + e];
    } else {
        src = reinterpret_cast<const int*>(ei)[e];
        dst = reinterpret_cast<const int*>(ei)[(size_t)E + e];
    }
}

// ---------------------------------------------------------------------------
// Zero the small counters
// ---------------------------------------------------------------------------
__global__ void zero_kernel(int N) {
    int i = blockIdx.x * blockDim.x + threadIdx.x;
    if (i < N) { g_cnt[i] = 0; g_fill[i] = 0; }
}

// ---------------------------------------------------------------------------
// CSR build: histogram -> scan -> fill
// ---------------------------------------------------------------------------
__global__ void hist_kernel(const void* __restrict__ ei, int E, int N) {
    int e = blockIdx.x * blockDim.x + threadIdx.x;
    if (e >= E) return;
    int src, dst;
    load_edge(ei, e, E, src, dst);
    if ((unsigned)dst < (unsigned)N) atomicAdd(&g_cnt[dst], 1);
}

// single-block exclusive scan of g_cnt[0..N) -> g_rowptr[0..N]
__global__ void __launch_bounds__(1024) scan_kernel(int N) {
    __shared__ int sums[1024];
    int t = threadIdx.x;
    int chunk = (N + 1023) / 1024;
    int b = t * chunk;
    int e = min(b + chunk, N);
    int s = 0;
    for (int i = b; i < e; i++) s += g_cnt[i];
    sums[t] = s;
    __syncthreads();
    for (int off = 1; off < 1024; off <<= 1) {
        int v = (t >= off) ? sums[t - off] : 0;
        __syncthreads();
        sums[t] += v;
        __syncthreads();
    }
    int prefix = (t == 0) ? 0 : sums[t - 1];
    for (int i = b; i < e; i++) {
        g_rowptr[i] = prefix;
        prefix += g_cnt[i];
    }
    if (t == 1023) g_rowptr[N] = prefix;   // == E
}

__global__ void fill_kernel(const void* __restrict__ ei, int E, int N) {
    int e = blockIdx.x * blockDim.x + threadIdx.x;
    if (e >= E) return;
    int src, dst;
    load_edge(ei, e, E, src, dst);
    if ((unsigned)dst >= (unsigned)N || (unsigned)src >= (unsigned)N) return;
    int slot = g_rowptr[dst] + atomicAdd(&g_fill[dst], 1);
    g_colidx[slot] = src;
}

// ---------------------------------------------------------------------------
// Layer-1 aggregation (gather): g_agg1[n] = mean_{s in N(n)} x[s]   (128 ch)
// One warp per node, one float4 per lane.
// ---------------------------------------------------------------------------
__global__ void agg1_kernel(const float* __restrict__ x, int N) {
    int w = (blockIdx.x * blockDim.x + threadIdx.x) >> 5;
    int l = threadIdx.x & 31;
    if (w >= N) return;
    int beg = g_rowptr[w], end = g_rowptr[w + 1];
    const float4* X4 = reinterpret_cast<const float4*>(x);
    float4 acc = make_float4(0.f, 0.f, 0.f, 0.f);
    int i = beg;
    for (; i + 1 < end; i += 2) {
        int s0 = g_colidx[i], s1 = g_colidx[i + 1];
        float4 v0 = X4[(size_t)s0 * 32 + l];
        float4 v1 = X4[(size_t)s1 * 32 + l];
        acc.x += v0.x + v1.x; acc.y += v0.y + v1.y;
        acc.z += v0.z + v1.z; acc.w += v0.w + v1.w;
    }
    if (i < end) {
        int s0 = g_colidx[i];
        float4 v0 = X4[(size_t)s0 * 32 + l];
        acc.x += v0.x; acc.y += v0.y; acc.z += v0.z; acc.w += v0.w;
    }
    float inv = 1.f / fmaxf((float)(end - beg), 1.f);
    reinterpret_cast<float4*>(g_agg1)[(size_t)w * 32 + l] =
        make_float4(acc.x * inv, acc.y * inv, acc.z * inv, acc.w * inv);
}

// ---------------------------------------------------------------------------
// Layer-2 aggregation + final combine:
//   out[n][c] = mean_{s in N(n)} tr[s][c]  +  tr[n][128+c]      (c in 0..127)
// tr row = 256 floats = 64 float4; t half = first 32 float4, r half = last 32.
// ---------------------------------------------------------------------------
__global__ void agg2_kernel(float* __restrict__ out, int N) {
    int w = (blockIdx.x * blockDim.x + threadIdx.x) >> 5;
    int l = threadIdx.x & 31;
    if (w >= N) return;
    int beg = g_rowptr[w], end = g_rowptr[w + 1];
    const float4* T4 = reinterpret_cast<const float4*>(g_tr);
    float4 acc = make_float4(0.f, 0.f, 0.f, 0.f);
    int i = beg;
    for (; i + 1 < end; i += 2) {
        int s0 = g_colidx[i], s1 = g_colidx[i + 1];
        float4 v0 = T4[(size_t)s0 * 64 + l];
        float4 v1 = T4[(size_t)s1 * 64 + l];
        acc.x += v0.x + v1.x; acc.y += v0.y + v1.y;
        acc.z += v0.z + v1.z; acc.w += v0.w + v1.w;
    }
    if (i < end) {
        int s0 = g_colidx[i];
        float4 v0 = T4[(size_t)s0 * 64 + l];
        acc.x += v0.x; acc.y += v0.y; acc.z += v0.z; acc.w += v0.w;
    }
    float inv = 1.f / fmaxf((float)(end - beg), 1.f);
    float4 r = T4[(size_t)w * 64 + 32 + l];
    reinterpret_cast<float4*>(out)[(size_t)w * 32 + l] =
        make_float4(acc.x * inv + r.x, acc.y * inv + r.y,
                    acc.z * inv + r.z, acc.w * inv + r.w);
}

// ---------------------------------------------------------------------------
// GEMM, 128x128 tile, 8x8 microtile, K'=256 for both layers.
// LAYER 1: A' = [x | g_agg1] (virtual K split), W'[o][k] = k<128? W1r[o][k]
//          : W1l[o][k-128]; out = relu(A'W'^T + b1l) -> g_h.
// LAYER 2: A = g_h;          W'[o][k] = o<128 ? W2l[o][k] : W2r[o-128][k];
//          bias only on o>=128 half; out -> g_tr (no relu).
// ---------------------------------------------------------------------------
template <int LAYER>
__global__ void __launch_bounds__(256)
gemm_kernel(const float* __restrict__ Xp,
            const float* __restrict__ Wa,   // L1: W1r   L2: W2l
            const float* __restrict__ Wb,   // L1: W1l   L2: W2r
            const float* __restrict__ bias, // L1: b1l   L2: b2l
            int N) {
    constexpr int KP = 256;                 // virtual K for both layers
    __shared__ float As[8][132];
    __shared__ float Bs[8][132];

    const int tid = threadIdx.x;
    const int n0 = blockIdx.x * 128;
    const int o0 = blockIdx.y * 128;

    // loader coords: r = row within tile (0..127), c4 = k sub-offset (0 or 4)
    const int r  = tid >> 1;
    const int c4 = (tid & 1) * 4;
    // compute coords
    const int ty = tid >> 4;     // node microtile row (0..15)
    const int tx = tid & 15;     // out  microtile col (0..15)

    float acc[8][8];
#pragma unroll
    for (int i = 0; i < 8; i++)
#pragma unroll
        for (int j = 0; j < 8; j++) acc[i][j] = 0.f;

    for (int kc = 0; kc < KP; kc += 8) {
        int kg = kc + c4;
        // ---- A tile ----
        float4 av = make_float4(0.f, 0.f, 0.f, 0.f);
        int n = n0 + r;
        if (n < N) {
            if (LAYER == 1) {
                av = (kg < IN_CH)
                   ? reinterpret_cast<const float4*>(Xp)[((size_t)n * IN_CH + kg) >> 2]
                   : reinterpret_cast<const float4*>(g_agg1)[((size_t)n * IN_CH + (kg - IN_CH)) >> 2];
            } else {
                av = reinterpret_cast<const float4*>(g_h)[((size_t)n * HID_CH + kg) >> 2];
            }
        }
        // ---- B tile ----
        int o = o0 + r;   // global out row (0..255)
        float4 bv;
        if (LAYER == 1) {
            bv = (kg < IN_CH)
               ? reinterpret_cast<const float4*>(Wa)[((size_t)o * IN_CH + kg) >> 2]
               : reinterpret_cast<const float4*>(Wb)[((size_t)o * IN_CH + (kg - IN_CH)) >> 2];
        } else {
            bv = (o < OUT_CH)
               ? reinterpret_cast<const float4*>(Wa)[((size_t)o * HID_CH + kg) >> 2]
               : reinterpret_cast<const float4*>(Wb)[((size_t)(o - OUT_CH) * HID_CH + kg) >> 2];
        }
        __syncthreads();
        As[c4 + 0][r] = av.x; As[c4 + 1][r] = av.y;
        As[c4 + 2][r] = av.z; As[c4 + 3][r] = av.w;
        Bs[c4 + 0][r] = bv.x; Bs[c4 + 1][r] = bv.y;
        Bs[c4 + 2][r] = bv.z; Bs[c4 + 3][r] = bv.w;
        __syncthreads();

#pragma unroll
        for (int k = 0; k < 8; k++) {
            float a[8], b[8];
            *reinterpret_cast<float4*>(a)     = *reinterpret_cast<const float4*>(&As[k][ty * 8]);
            *reinterpret_cast<float4*>(a + 4) = *reinterpret_cast<const float4*>(&As[k][ty * 8 + 4]);
            *reinterpret_cast<float4*>(b)     = *reinterpret_cast<const float4*>(&Bs[k][tx * 8]);
            *reinterpret_cast<float4*>(b + 4) = *reinterpret_cast<const float4*>(&Bs[k][tx * 8 + 4]);
#pragma unroll
            for (int i = 0; i < 8; i++)
#pragma unroll
                for (int j = 0; j < 8; j++) acc[i][j] += a[i] * b[j];
        }
    }

    // ---- epilogue ----
    float bj[8];
#pragma unroll
    for (int j = 0; j < 8; j++) {
        int og = o0 + tx * 8 + j;
        if (LAYER == 1) bj[j] = bias[og];
        else            bj[j] = (og >= OUT_CH) ? bias[og - OUT_CH] : 0.f;
    }
    float* dst = (LAYER == 1) ? g_h : g_tr;
#pragma unroll
    for (int i = 0; i < 8; i++) {
        int n = n0 + ty * 8 + i;
        if (n >= N) continue;
#pragma unroll
        for (int j = 0; j < 8; j += 4) {
            float4 v;
            v.x = acc[i][j + 0] + bj[j + 0];
            v.y = acc[i][j + 1] + bj[j + 1];
            v.z = acc[i][j + 2] + bj[j + 2];
            v.w = acc[i][j + 3] + bj[j + 3];
            if (LAYER == 1) {
                v.x = fmaxf(v.x, 0.f); v.y = fmaxf(v.y, 0.f);
                v.z = fmaxf(v.z, 0.f); v.w = fmaxf(v.w, 0.f);
            }
            int og = o0 + tx * 8 + j;
            *reinterpret_cast<float4*>(&dst[(size_t)n * 256 + og]) = v;
        }
    }
}

// ---------------------------------------------------------------------------
// Launcher — kernel launches only; graph-capturable.
// ---------------------------------------------------------------------------
extern "C" void kernel_launch(void* const* d_in, const int* in_sizes, int n_in,
                              void* d_out, int out_size) {
    const float* x   = (const float*)d_in[0];
    const void*  ei  = d_in[1];
    const float* W1l = (const float*)d_in[2];
    const float* b1l = (const float*)d_in[3];
    const float* W1r = (const float*)d_in[4];
    const float* W2l = (const float*)d_in[5];
    const float* b2l = (const float*)d_in[6];
    const float* W2r = (const float*)d_in[7];
    float* out       = (float*)d_out;

    const int N = in_sizes[0] / IN_CH;
    const int E = in_sizes[1] / 2;

    detect_dtype_kernel<<<1, 128>>>((const int*)ei);
    zero_kernel<<<(N + 255) / 256, 256>>>(N);
    hist_kernel<<<(E + 255) / 256, 256>>>(ei, E, N);
    scan_kernel<<<1, 1024>>>(N);
    fill_kernel<<<(E + 255) / 256, 256>>>(ei, E, N);

    // layer 1: aggregate x, then fused GEMM + ReLU -> g_h
    agg1_kernel<<<(N * 32 + 255) / 256, 256>>>(x, N);
    {
        dim3 grid((N + 127) / 128, 2);
        gemm_kernel<1><<<grid, 256>>>(x, W1r, W1l, b1l, N);
    }

    // layer 2: GEMM first (tr = [h@W2l^T | h@W2r^T + b2l]), then gather+combine
    {
        dim3 grid((N + 127) / 128, 2);
        gemm_kernel<2><<<grid, 256>>>(nullptr, W2l, W2r, b2l, N);
    }
    agg2_kernel<<<(N * 32 + 255) / 256, 256>>>(out, N);
}

// round 6
// speedup vs baseline: 4.9402x; 1.6415x over previous
#include <cuda_runtime.h>
#include <cuda_bf16.h>
#include <cstdint>

#define MAX_N 50000
#define MAX_E 800000
#define IN_CH 128
#define HID_CH 256
#define OUT_CH 128

// ---------------------------------------------------------------------------
// Device scratch (allocation-free rule)
// ---------------------------------------------------------------------------
__device__ __align__(16) __nv_bfloat16 g_a1h[(size_t)MAX_N * 256];  // layer-1 A hi
__device__ __align__(16) __nv_bfloat16 g_a1l[(size_t)MAX_N * 256];  // layer-1 A lo
__device__ __align__(16) __nv_bfloat16 g_a2h[(size_t)MAX_N * 256];  // layer-2 A hi
__device__ __align__(16) __nv_bfloat16 g_a2l[(size_t)MAX_N * 256];  // layer-2 A lo
__device__ __align__(16) __nv_bfloat16 g_w1h[256 * 256], g_w1l[256 * 256];
__device__ __align__(16) __nv_bfloat16 g_w2h[256 * 256], g_w2l[256 * 256];
__device__ float g_tr[(size_t)MAX_N * 256];          // layer-2 GEMM out [t | r]
__device__ int g_cnt[MAX_N];
__device__ int g_fill[MAX_N];
__device__ int g_rowptr[MAX_N + 1];
__device__ int g_colidx[MAX_E];
__device__ int g_bsum[256], g_boff[256];
__device__ int g_is64;

// ---------------------------------------------------------------------------
// Helpers
// ---------------------------------------------------------------------------
__device__ __forceinline__ uint32_t smem_to_u32(const void* p) {
    uint32_t a;
    asm("{ .reg .u64 t; cvta.to.shared.u64 t, %1; cvt.u32.u64 %0, t; }"
        : "=r"(a) : "l"(p));
    return a;
}

__device__ __forceinline__ void ldsm_x4(uint32_t* r, uint32_t addr) {
    asm volatile("ldmatrix.sync.aligned.m8n8.x4.shared.b16 {%0,%1,%2,%3}, [%4];"
        : "=r"(r[0]), "=r"(r[1]), "=r"(r[2]), "=r"(r[3]) : "r"(addr));
}

// m16n8k16 bf16 HMMA, fp32 accumulate-in-place
__device__ __forceinline__ void mma16816(float* d, const uint32_t* a,
                                          const uint32_t* b) {
    asm volatile(
        "mma.sync.aligned.m16n8k16.row.col.f32.bf16.bf16.f32 "
        "{%0,%1,%2,%3}, {%4,%5,%6,%7}, {%8,%9}, {%0,%1,%2,%3};"
        : "+f"(d[0]), "+f"(d[1]), "+f"(d[2]), "+f"(d[3])
        : "r"(a[0]), "r"(a[1]), "r"(a[2]), "r"(a[3]), "r"(b[0]), "r"(b[1]));
}

__device__ __forceinline__ void split2(float v0, float v1,
                                       __nv_bfloat162& hp, __nv_bfloat162& lp) {
    __nv_bfloat16 h0 = __float2bfloat16(v0);
    __nv_bfloat16 h1 = __float2bfloat16(v1);
    hp.x = h0; hp.y = h1;
    lp.x = __float2bfloat16(v0 - __bfloat162float(h0));
    lp.y = __float2bfloat16(v1 - __bfloat162float(h1));
}

// ---------------------------------------------------------------------------
// Edge dtype sniff + CSR build (proven in R4/R5)
// ---------------------------------------------------------------------------
__global__ void detect_dtype_kernel(const int* __restrict__ ei32) {
    __shared__ int red[128];
    int t = threadIdx.x;
    red[t] = ei32[2 * t + 1];
    __syncthreads();
    for (int s = 64; s > 0; s >>= 1) {
        if (t < s) red[t] |= red[t + s];
        __syncthreads();
    }
    if (t == 0) g_is64 = (red[0] == 0) ? 1 : 0;
}

__device__ __forceinline__ void load_edge(const void* ei, int e, int E,
                                          int& src, int& dst) {
    if (g_is64) {
        src = (int)reinterpret_cast<const long long*>(ei)[e];
        dst = (int)reinterpret_cast<const long long*>(ei)[(size_t)E + e];
    } else {
        src = reinterpret_cast<const int*>(ei)[e];
        dst = reinterpret_cast<const int*>(ei)[(size_t)E + e];
    }
}

__global__ void zero_kernel(int N) {
    int i = blockIdx.x * blockDim.x + threadIdx.x;
    if (i < N) { g_cnt[i] = 0; g_fill[i] = 0; }
}

__global__ void hist_kernel(const void* __restrict__ ei, int E, int N) {
    int e = blockIdx.x * blockDim.x + threadIdx.x;
    if (e >= E) return;
    int src, dst;
    load_edge(ei, e, E, src, dst);
    if ((unsigned)dst < (unsigned)N) atomicAdd(&g_cnt[dst], 1);
}

// Parallel 3-pass scan
__global__ void scan_pass1(int N) {
    __shared__ int sh[256];
    int t = threadIdx.x, i = blockIdx.x * 256 + t;
    sh[t] = (i < N) ? g_cnt[i] : 0;
    __syncthreads();
    for (int s = 128; s > 0; s >>= 1) {
        if (t < s) sh[t] += sh[t + s];
        __syncthreads();
    }
    if (t == 0) g_bsum[blockIdx.x] = sh[0];
}

__global__ void scan_pass2(int NB, int N) {
    __shared__ int sh[256];
    int t = threadIdx.x;
    int v = (t < NB) ? g_bsum[t] : 0;
    sh[t] = v;
    __syncthreads();
    for (int off = 1; off < 256; off <<= 1) {
        int x = (t >= off) ? sh[t - off] : 0;
        __syncthreads();
        sh[t] += x;
        __syncthreads();
    }
    g_boff[t] = sh[t] - v;
    if (t == 255) g_rowptr[N] = sh[255];
}

__global__ void scan_pass3(int N) {
    __shared__ int sh[256];
    int t = threadIdx.x, i = blockIdx.x * 256 + t;
    int v = (i < N) ? g_cnt[i] : 0;
    sh[t] = v;
    __syncthreads();
    for (int off = 1; off < 256; off <<= 1) {
        int x = (t >= off) ? sh[t - off] : 0;
        __syncthreads();
        sh[t] += x;
        __syncthreads();
    }
    if (i < N) g_rowptr[i] = g_boff[blockIdx.x] + sh[t] - v;
}

__global__ void fill_kernel(const void* __restrict__ ei, int E, int N) {
    int e = blockIdx.x * blockDim.x + threadIdx.x;
    if (e >= E) return;
    int src, dst;
    load_edge(ei, e, E, src, dst);
    if ((unsigned)dst >= (unsigned)N || (unsigned)src >= (unsigned)N) return;
    int slot = g_rowptr[dst] + atomicAdd(&g_fill[dst], 1);
    g_colidx[slot] = src;
}

// ---------------------------------------------------------------------------
// Weight prep: [256 out, 256 k] hi/lo bf16 composite weights.
// layer1: k<128 -> W1r[o,k], else W1l[o,k-128]
// layer2: o<128 -> W2l[o,k], else W2r[o-128,k]
// ---------------------------------------------------------------------------
__global__ void conv_w_kernel(const float* __restrict__ Wa,
                              const float* __restrict__ Wb, int layer) {
    int idx = blockIdx.x * 256 + threadIdx.x;
    if (idx >= 256 * 256) return;
    int o = idx >> 8, k = idx & 255;
    float v;
    __nv_bfloat16 *H, *L;
    if (layer == 1) {
        v = (k < 128) ? Wa[o * 128 + k] : Wb[o * 128 + (k - 128)];
        H = g_w1h; L = g_w1l;
    } else {
        v = (o < 128) ? Wa[o * 256 + k] : Wb[(o - 128) * 256 + k];
        H = g_w2h; L = g_w2l;
    }
    __nv_bfloat16 hi = __float2bfloat16(v);
    H[idx] = hi;
    L[idx] = __float2bfloat16(v - __bfloat162float(hi));
}

// x -> layer-1 A cols 0..127 (split bf16)
__global__ void conv_x_kernel(const float* __restrict__ x, int N) {
    int idx = blockIdx.x * 256 + threadIdx.x;
    if (idx >= N * 64) return;
    int n = idx >> 6, k2 = (idx & 63) << 1;
    float2 v = *reinterpret_cast<const float2*>(x + (size_t)n * 128 + k2);
    __nv_bfloat162 hp, lp;
    split2(v.x, v.y, hp, lp);
    *reinterpret_cast<__nv_bfloat162*>(g_a1h + (size_t)n * 256 + k2) = hp;
    *reinterpret_cast<__nv_bfloat162*>(g_a1l + (size_t)n * 256 + k2) = lp;
}

// ---------------------------------------------------------------------------
// Layer-1 aggregation: mean of x over CSR neighbors -> split bf16 cols 128..255
// ---------------------------------------------------------------------------
__global__ void agg1_kernel(const float* __restrict__ x, int N) {
    int w = (blockIdx.x * blockDim.x + threadIdx.x) >> 5;
    int l = threadIdx.x & 31;
    if (w >= N) return;
    int beg = g_rowptr[w], end = g_rowptr[w + 1];
    const float4* X4 = reinterpret_cast<const float4*>(x);
    float4 acc = make_float4(0.f, 0.f, 0.f, 0.f);
    int i = beg;
    for (; i + 1 < end; i += 2) {
        int s0 = g_colidx[i], s1 = g_colidx[i + 1];
        float4 v0 = X4[(size_t)s0 * 32 + l];
        float4 v1 = X4[(size_t)s1 * 32 + l];
        acc.x += v0.x + v1.x; acc.y += v0.y + v1.y;
        acc.z += v0.z + v1.z; acc.w += v0.w + v1.w;
    }
    if (i < end) {
        int s0 = g_colidx[i];
        float4 v0 = X4[(size_t)s0 * 32 + l];
        acc.x += v0.x; acc.y += v0.y; acc.z += v0.z; acc.w += v0.w;
    }
    float inv = 1.f / fmaxf((float)(end - beg), 1.f);
    acc.x *= inv; acc.y *= inv; acc.z *= inv; acc.w *= inv;
    size_t base = (size_t)w * 256 + 128 + l * 4;
    __nv_bfloat162 hp0, lp0, hp1, lp1;
    split2(acc.x, acc.y, hp0, lp0);
    split2(acc.z, acc.w, hp1, lp1);
    *reinterpret_cast<__nv_bfloat162*>(g_a1h + base)     = hp0;
    *reinterpret_cast<__nv_bfloat162*>(g_a1h + base + 2) = hp1;
    *reinterpret_cast<__nv_bfloat162*>(g_a1l + base)     = lp0;
    *reinterpret_cast<__nv_bfloat162*>(g_a1l + base + 2) = lp1;
}

// ---------------------------------------------------------------------------
// Layer-2 aggregation + final combine:
//   out[n][c] = mean_{s in N(n)} tr[s][c] + tr[n][128+c]
// ---------------------------------------------------------------------------
__global__ void agg2_kernel(float* __restrict__ out, int N) {
    int w = (blockIdx.x * blockDim.x + threadIdx.x) >> 5;
    int l = threadIdx.x & 31;
    if (w >= N) return;
    int beg = g_rowptr[w], end = g_rowptr[w + 1];
    const float4* T4 = reinterpret_cast<const float4*>(g_tr);
    float4 acc = make_float4(0.f, 0.f, 0.f, 0.f);
    int i = beg;
    for (; i + 1 < end; i += 2) {
        int s0 = g_colidx[i], s1 = g_colidx[i + 1];
        float4 v0 = T4[(size_t)s0 * 64 + l];
        float4 v1 = T4[(size_t)s1 * 64 + l];
        acc.x += v0.x + v1.x; acc.y += v0.y + v1.y;
        acc.z += v0.z + v1.z; acc.w += v0.w + v1.w;
    }
    if (i < end) {
        int s0 = g_colidx[i];
        float4 v0 = T4[(size_t)s0 * 64 + l];
        acc.x += v0.x; acc.y += v0.y; acc.z += v0.z; acc.w += v0.w;
    }
    float inv = 1.f / fmaxf((float)(end - beg), 1.f);
    float4 r = T4[(size_t)w * 64 + 32 + l];
    reinterpret_cast<float4*>(out)[(size_t)w * 32 + l] =
        make_float4(acc.x * inv + r.x, acc.y * inv + r.y,
                    acc.z * inv + r.z, acc.w * inv + r.w);
}

// ---------------------------------------------------------------------------
// HMMA GEMM (mma.sync m16n8k16 bf16, fp32 accum), hi/lo split, 3 passes.
// CTA tile 128(m) x 128(n), K=256 in 8 chunks of 32. 8 warps = 2(m) x 4(n),
// warp tile 64x32. Smem rows padded to 40 bf16 for conflict-free ldmatrix.
// LAYER 1: A=g_a1*, W=g_w1*; epi relu(+b1l all cols) -> split bf16 g_a2*
// LAYER 2: A=g_a2*, W=g_w2*; epi +b2l on cols>=128    -> fp32 g_tr
// ---------------------------------------------------------------------------
#define SPAD 40

template <int LAYER>
__global__ void __launch_bounds__(256)
mma_gemm_kernel(const float* __restrict__ bias, int N) {
    __shared__ __align__(16) __nv_bfloat16 sAH[128 * SPAD];
    __shared__ __align__(16) __nv_bfloat16 sAL[128 * SPAD];
    __shared__ __align__(16) __nv_bfloat16 sBH[128 * SPAD];
    __shared__ __align__(16) __nv_bfloat16 sBL[128 * SPAD];

    const int tid  = threadIdx.x;
    const int lane = tid & 31;
    const int wid  = tid >> 5;
    const int wm   = (wid & 1) * 64;     // warp m offset
    const int wn   = (wid >> 1) * 32;    // warp n offset
    const int n0   = blockIdx.x * 128;
    const int o0   = blockIdx.y * 128;

    const __nv_bfloat16* __restrict__ AH = (LAYER == 1) ? g_a1h : g_a2h;
    const __nv_bfloat16* __restrict__ AL = (LAYER == 1) ? g_a1l : g_a2l;
    const __nv_bfloat16* __restrict__ WH = (LAYER == 1) ? g_w1h : g_w2h;
    const __nv_bfloat16* __restrict__ WL = (LAYER == 1) ? g_w1l : g_w2l;

    const uint32_t uAH = smem_to_u32(sAH);
    const uint32_t uAL = smem_to_u32(sAL);
    const uint32_t uBH = smem_to_u32(sBH);
    const uint32_t uBL = smem_to_u32(sBL);

    // loader: 2 x 16B chunks per thread per tile
    const int lrow = tid >> 2;             // 0..63 (+64)
    const int lcol = (tid & 3) * 8;        // element col within 32-k chunk

    // ldmatrix lane-invariant coords
    const int arow = wm + (lane & 15);
    const int acol = (lane >> 4) * 8;
    const int brow = wn + (lane & 7) + ((lane >> 4) << 3);
    const int bcol = ((lane >> 3) & 1) * 8;

    float acc[4][4][4];
#pragma unroll
    for (int mi = 0; mi < 4; mi++)
#pragma unroll
        for (int ni = 0; ni < 4; ni++)
#pragma unroll
            for (int q = 0; q < 4; q++) acc[mi][ni][q] = 0.f;

    for (int kc = 0; kc < 256; kc += 32) {
        uint4 vah[2], valo[2], vbh[2], vbl[2];
#pragma unroll
        for (int i = 0; i < 2; i++) {
            int row = lrow + i * 64;
            int n = n0 + row;
            if (n < N) {
                size_t ga = (size_t)n * 256 + kc + lcol;
                vah[i]  = *reinterpret_cast<const uint4*>(AH + ga);
                valo[i] = *reinterpret_cast<const uint4*>(AL + ga);
            } else {
                vah[i]  = make_uint4(0, 0, 0, 0);
                valo[i] = make_uint4(0, 0, 0, 0);
            }
            size_t gw = (size_t)(o0 + row) * 256 + kc + lcol;
            vbh[i] = *reinterpret_cast<const uint4*>(WH + gw);
            vbl[i] = *reinterpret_cast<const uint4*>(WL + gw);
        }
        __syncthreads();   // previous iteration's MMAs done reading smem
#pragma unroll
        for (int i = 0; i < 2; i++) {
            int so = (lrow + i * 64) * SPAD + lcol;
            *reinterpret_cast<uint4*>(sAH + so) = vah[i];
            *reinterpret_cast<uint4*>(sAL + so) = valo[i];
            *reinterpret_cast<uint4*>(sBH + so) = vbh[i];
            *reinterpret_cast<uint4*>(sBL + so) = vbl[i];
        }
        __syncthreads();

#pragma unroll
        for (int t = 0; t < 3; t++) {
            const uint32_t uA = (t == 2) ? uAL : uAH;
            const uint32_t uB = (t == 1) ? uBL : uBH;
#pragma unroll
            for (int ks = 0; ks < 2; ks++) {
                const int k0 = ks * 16;
                uint32_t a[4][4], b[4][2];
#pragma unroll
                for (int mi = 0; mi < 4; mi++)
                    ldsm_x4(a[mi],
                            uA + ((arow + mi * 16) * SPAD + k0 + acol) * 2);
#pragma unroll
                for (int nip = 0; nip < 2; nip++) {
                    uint32_t bb[4];
                    ldsm_x4(bb, uB + ((brow + nip * 16) * SPAD + k0 + bcol) * 2);
                    b[nip * 2][0]     = bb[0]; b[nip * 2][1]     = bb[1];
                    b[nip * 2 + 1][0] = bb[2]; b[nip * 2 + 1][1] = bb[3];
                }
#pragma unroll
                for (int mi = 0; mi < 4; mi++)
#pragma unroll
                    for (int ni = 0; ni < 4; ni++)
                        mma16816(acc[mi][ni], a[mi], b[ni]);
            }
        }
    }

    // epilogue: d0,d1 -> row l/4, cols c,c+1; d2,d3 -> row l/4+8
    const int erow = lane >> 2;
    const int ecol = (lane & 3) * 2;
#pragma unroll
    for (int mi = 0; mi < 4; mi++) {
#pragma unroll
        for (int half = 0; half < 2; half++) {
            int n = n0 + wm + mi * 16 + erow + half * 8;
            if (n >= N) continue;
#pragma unroll
            for (int ni = 0; ni < 4; ni++) {
                int col = o0 + wn + ni * 8 + ecol;
                float v0 = acc[mi][ni][half * 2 + 0];
                float v1 = acc[mi][ni][half * 2 + 1];
                if (LAYER == 1) {
                    v0 = fmaxf(v0 + bias[col],     0.f);
                    v1 = fmaxf(v1 + bias[col + 1], 0.f);
                    __nv_bfloat162 hp, lp;
                    split2(v0, v1, hp, lp);
                    size_t off = (size_t)n * 256 + col;
                    *reinterpret_cast<__nv_bfloat162*>(g_a2h + off) = hp;
                    *reinterpret_cast<__nv_bfloat162*>(g_a2l + off) = lp;
                } else {
                    if (col >= 128) {
                        v0 += bias[col - 128];
                        v1 += bias[col - 127];
                    }
                    *reinterpret_cast<float2*>(g_tr + (size_t)n * 256 + col) =
                        make_float2(v0, v1);
                }
            }
        }
    }
}

// ---------------------------------------------------------------------------
// Launcher — kernel launches only; graph-capturable.
// ---------------------------------------------------------------------------
extern "C" void kernel_launch(void* const* d_in, const int* in_sizes, int n_in,
                              void* d_out, int out_size) {
    const float* x   = (const float*)d_in[0];
    const void*  ei  = d_in[1];
    const float* W1l = (const float*)d_in[2];
    const float* b1l = (const float*)d_in[3];
    const float* W1r = (const float*)d_in[4];
    const float* W2l = (const float*)d_in[5];
    const float* b2l = (const float*)d_in[6];
    const float* W2r = (const float*)d_in[7];
    float* out       = (float*)d_out;

    const int N = in_sizes[0] / IN_CH;
    const int E = in_sizes[1] / 2;
    const int NB = (N + 255) / 256;

    // CSR build
    detect_dtype_kernel<<<1, 128>>>((const int*)ei);
    zero_kernel<<<(N + 255) / 256, 256>>>(N);
    hist_kernel<<<(E + 255) / 256, 256>>>(ei, E, N);
    scan_pass1<<<NB, 256>>>(N);
    scan_pass2<<<1, 256>>>(NB, N);
    scan_pass3<<<NB, 256>>>(N);
    fill_kernel<<<(E + 255) / 256, 256>>>(ei, E, N);

    // weight + x conversion
    conv_w_kernel<<<256, 256>>>(W1r, W1l, 1);
    conv_w_kernel<<<256, 256>>>(W2l, W2r, 2);
    conv_x_kernel<<<(N * 64 + 255) / 256, 256>>>(x, N);

    // layer 1: aggregate (split A1 cols 128..255), GEMM -> split A2
    agg1_kernel<<<(N * 32 + 255) / 256, 256>>>(x, N);
    {
        dim3 grid((N + 127) / 128, 2);
        mma_gemm_kernel<1><<<grid, 256>>>(b1l, N);
    }

    // layer 2: GEMM -> g_tr fp32, then gather + combine -> out
    {
        dim3 grid((N + 127) / 128, 2);
        mma_gemm_kernel<2><<<grid, 256>>>(b2l, N);
    }
    agg2_kernel<<<(N * 32 + 255) / 256, 256>>>(out, N);
}

// round 7
// speedup vs baseline: 5.6769x; 1.1491x over previous
#include <cuda_runtime.h>
#include <cuda_bf16.h>
#include <cstdint>

#define MAX_N 50000
#define MAX_E 800000
#define IN_CH 128
#define HID_CH 256
#define OUT_CH 128

// ---------------------------------------------------------------------------
// Device scratch (allocation-free rule)
// ---------------------------------------------------------------------------
__device__ __align__(16) __nv_bfloat16 g_a1h[(size_t)MAX_N * 256];
__device__ __align__(16) __nv_bfloat16 g_a1l[(size_t)MAX_N * 256];
__device__ __align__(16) __nv_bfloat16 g_a2h[(size_t)MAX_N * 256];
__device__ __align__(16) __nv_bfloat16 g_a2l[(size_t)MAX_N * 256];
__device__ __align__(16) __nv_bfloat16 g_w1h[256 * 256], g_w1l[256 * 256];
__device__ __align__(16) __nv_bfloat16 g_w2h[256 * 256], g_w2l[256 * 256];
__device__ float g_tr[(size_t)MAX_N * 256];
__device__ int g_cnt[MAX_N];
__device__ int g_fill[MAX_N];
__device__ int g_rowptr[MAX_N + 1];
__device__ int g_colidx[MAX_E];
__device__ int g_bsum[256], g_boff[256];
__device__ int g_is64;

// ---------------------------------------------------------------------------
// Helpers
// ---------------------------------------------------------------------------
__device__ __forceinline__ uint32_t smem_to_u32(const void* p) {
    uint32_t a;
    asm("{ .reg .u64 t; cvta.to.shared.u64 t, %1; cvt.u32.u64 %0, t; }"
        : "=r"(a) : "l"(p));
    return a;
}

__device__ __forceinline__ void ldsm_x4(uint32_t* r, uint32_t addr) {
    asm volatile("ldmatrix.sync.aligned.m8n8.x4.shared.b16 {%0,%1,%2,%3}, [%4];"
        : "=r"(r[0]), "=r"(r[1]), "=r"(r[2]), "=r"(r[3]) : "r"(addr));
}

__device__ __forceinline__ void mma16816(float* d, const uint32_t* a,
                                          const uint32_t* b) {
    asm volatile(
        "mma.sync.aligned.m16n8k16.row.col.f32.bf16.bf16.f32 "
        "{%0,%1,%2,%3}, {%4,%5,%6,%7}, {%8,%9}, {%0,%1,%2,%3};"
        : "+f"(d[0]), "+f"(d[1]), "+f"(d[2]), "+f"(d[3])
        : "r"(a[0]), "r"(a[1]), "r"(a[2]), "r"(a[3]), "r"(b[0]), "r"(b[1]));
}

__device__ __forceinline__ void cp16(uint32_t dst, const void* src, bool pred) {
    int sz = pred ? 16 : 0;
    asm volatile("cp.async.cg.shared.global [%0], [%1], 16, %2;"
        :: "r"(dst), "l"(src), "r"(sz));
}

__device__ __forceinline__ void split2(float v0, float v1,
                                       __nv_bfloat162& hp, __nv_bfloat162& lp) {
    __nv_bfloat16 h0 = __float2bfloat16(v0);
    __nv_bfloat16 h1 = __float2bfloat16(v1);
    hp.x = h0; hp.y = h1;
    lp.x = __float2bfloat16(v0 - __bfloat162float(h0));
    lp.y = __float2bfloat16(v1 - __bfloat162float(h1));
}

// ---------------------------------------------------------------------------
// Fused prep: weight split (both layers) + dtype sniff + counter zeroing.
// blocks [0,256):    W1 composite split   (65536 elems)
// blocks [256,512):  W2 composite split
// block  512:        edge dtype sniff
// blocks [513, ...): zero g_cnt/g_fill
// ---------------------------------------------------------------------------
__global__ void prep_kernel(const float* __restrict__ W1l,
                            const float* __restrict__ W1r,
                            const float* __restrict__ W2l,
                            const float* __restrict__ W2r,
                            const int* __restrict__ ei32, int N) {
    int b = blockIdx.x, t = threadIdx.x;
    if (b < 512) {
        int idx = (b & 255) * 256 + t;
        int o = idx >> 8, k = idx & 255;
        float v;
        __nv_bfloat16 *H, *L;
        if (b < 256) {   // layer1: k<128 -> W1r[o,k], else W1l[o,k-128]
            v = (k < 128) ? W1r[o * 128 + k] : W1l[o * 128 + (k - 128)];
            H = g_w1h; L = g_w1l;
        } else {         // layer2: o<128 -> W2l[o,k], else W2r[o-128,k]
            v = (o < 128) ? W2l[o * 256 + k] : W2r[(o - 128) * 256 + k];
            H = g_w2h; L = g_w2l;
        }
        __nv_bfloat16 hi = __float2bfloat16(v);
        H[idx] = hi;
        L[idx] = __float2bfloat16(v - __bfloat162float(hi));
    } else if (b == 512) {
        __shared__ int red[128];
        if (t < 128) red[t] = ei32[2 * t + 1];
        __syncthreads();
        for (int s = 64; s > 0; s >>= 1) {
            if (t < s) red[t] |= red[t + s];
            __syncthreads();
        }
        if (t == 0) g_is64 = (red[0] == 0) ? 1 : 0;
    } else {
        int i = (b - 513) * 256 + t;
        if (i < N) { g_cnt[i] = 0; g_fill[i] = 0; }
    }
}

__device__ __forceinline__ void load_edge(const void* ei, int e, int E,
                                          int& src, int& dst) {
    if (g_is64) {
        src = (int)reinterpret_cast<const long long*>(ei)[e];
        dst = (int)reinterpret_cast<const long long*>(ei)[(size_t)E + e];
    } else {
        src = reinterpret_cast<const int*>(ei)[e];
        dst = reinterpret_cast<const int*>(ei)[(size_t)E + e];
    }
}

__global__ void hist_kernel(const void* __restrict__ ei, int E, int N) {
    int e = blockIdx.x * blockDim.x + threadIdx.x;
    if (e >= E) return;
    int src, dst;
    load_edge(ei, e, E, src, dst);
    if ((unsigned)dst < (unsigned)N) atomicAdd(&g_cnt[dst], 1);
}

// Parallel 3-pass scan (proven R6)
__global__ void scan_pass1(int N) {
    __shared__ int sh[256];
    int t = threadIdx.x, i = blockIdx.x * 256 + t;
    sh[t] = (i < N) ? g_cnt[i] : 0;
    __syncthreads();
    for (int s = 128; s > 0; s >>= 1) {
        if (t < s) sh[t] += sh[t + s];
        __syncthreads();
    }
    if (t == 0) g_bsum[blockIdx.x] = sh[0];
}

__global__ void scan_pass2(int NB, int N) {
    __shared__ int sh[256];
    int t = threadIdx.x;
    int v = (t < NB) ? g_bsum[t] : 0;
    sh[t] = v;
    __syncthreads();
    for (int off = 1; off < 256; off <<= 1) {
        int x = (t >= off) ? sh[t - off] : 0;
        __syncthreads();
        sh[t] += x;
        __syncthreads();
    }
    g_boff[t] = sh[t] - v;
    if (t == 255) g_rowptr[N] = sh[255];
}

__global__ void scan_pass3(int N) {
    __shared__ int sh[256];
    int t = threadIdx.x, i = blockIdx.x * 256 + t;
    int v = (i < N) ? g_cnt[i] : 0;
    sh[t] = v;
    __syncthreads();
    for (int off = 1; off < 256; off <<= 1) {
        int x = (t >= off) ? sh[t - off] : 0;
        __syncthreads();
        sh[t] += x;
        __syncthreads();
    }
    if (i < N) g_rowptr[i] = g_boff[blockIdx.x] + sh[t] - v;
}

__global__ void fill_kernel(const void* __restrict__ ei, int E, int N) {
    int e = blockIdx.x * blockDim.x + threadIdx.x;
    if (e >= E) return;
    int src, dst;
    load_edge(ei, e, E, src, dst);
    if ((unsigned)dst >= (unsigned)N || (unsigned)src >= (unsigned)N) return;
    int slot = g_rowptr[dst] + atomicAdd(&g_fill[dst], 1);
    g_colidx[slot] = src;
}

// ---------------------------------------------------------------------------
// Layer-1 aggregation + own-row conversion (conv_x fused):
//   cols 0..127   <- split(x[n])
//   cols 128..255 <- split(mean_{s in N(n)} x[s])
// One warp per node, one float4 per lane.
// ---------------------------------------------------------------------------
__global__ void agg1_kernel(const float* __restrict__ x, int N) {
    int w = (blockIdx.x * blockDim.x + threadIdx.x) >> 5;
    int l = threadIdx.x & 31;
    if (w >= N) return;
    int beg = g_rowptr[w], end = g_rowptr[w + 1];
    const float4* X4 = reinterpret_cast<const float4*>(x);
    float4 acc = make_float4(0.f, 0.f, 0.f, 0.f);
    int i = beg;
    for (; i + 1 < end; i += 2) {
        int s0 = g_colidx[i], s1 = g_colidx[i + 1];
        float4 v0 = X4[(size_t)s0 * 32 + l];
        float4 v1 = X4[(size_t)s1 * 32 + l];
        acc.x += v0.x + v1.x; acc.y += v0.y + v1.y;
        acc.z += v0.z + v1.z; acc.w += v0.w + v1.w;
    }
    if (i < end) {
        int s0 = g_colidx[i];
        float4 v0 = X4[(size_t)s0 * 32 + l];
        acc.x += v0.x; acc.y += v0.y; acc.z += v0.z; acc.w += v0.w;
    }
    float inv = 1.f / fmaxf((float)(end - beg), 1.f);
    acc.x *= inv; acc.y *= inv; acc.z *= inv; acc.w *= inv;
    __nv_bfloat162 hp0, lp0, hp1, lp1;
    // mean -> cols 128..255
    split2(acc.x, acc.y, hp0, lp0);
    split2(acc.z, acc.w, hp1, lp1);
    size_t base = (size_t)w * 256 + 128 + l * 4;
    *reinterpret_cast<__nv_bfloat162*>(g_a1h + base)     = hp0;
    *reinterpret_cast<__nv_bfloat162*>(g_a1h + base + 2) = hp1;
    *reinterpret_cast<__nv_bfloat162*>(g_a1l + base)     = lp0;
    *reinterpret_cast<__nv_bfloat162*>(g_a1l + base + 2) = lp1;
    // own row -> cols 0..127
    float4 xr = X4[(size_t)w * 32 + l];
    split2(xr.x, xr.y, hp0, lp0);
    split2(xr.z, xr.w, hp1, lp1);
    base = (size_t)w * 256 + l * 4;
    *reinterpret_cast<__nv_bfloat162*>(g_a1h + base)     = hp0;
    *reinterpret_cast<__nv_bfloat162*>(g_a1h + base + 2) = hp1;
    *reinterpret_cast<__nv_bfloat162*>(g_a1l + base)     = lp0;
    *reinterpret_cast<__nv_bfloat162*>(g_a1l + base + 2) = lp1;
}

// ---------------------------------------------------------------------------
// Layer-2 aggregation + final combine:
//   out[n][c] = mean_{s in N(n)} tr[s][c] + tr[n][128+c]
// ---------------------------------------------------------------------------
__global__ void agg2_kernel(float* __restrict__ out, int N) {
    int w = (blockIdx.x * blockDim.x + threadIdx.x) >> 5;
    int l = threadIdx.x & 31;
    if (w >= N) return;
    int beg = g_rowptr[w], end = g_rowptr[w + 1];
    const float4* T4 = reinterpret_cast<const float4*>(g_tr);
    float4 acc = make_float4(0.f, 0.f, 0.f, 0.f);
    int i = beg;
    for (; i + 1 < end; i += 2) {
        int s0 = g_colidx[i], s1 = g_colidx[i + 1];
        float4 v0 = T4[(size_t)s0 * 64 + l];
        float4 v1 = T4[(size_t)s1 * 64 + l];
        acc.x += v0.x + v1.x; acc.y += v0.y + v1.y;
        acc.z += v0.z + v1.z; acc.w += v0.w + v1.w;
    }
    if (i < end) {
        int s0 = g_colidx[i];
        float4 v0 = T4[(size_t)s0 * 64 + l];
        acc.x += v0.x; acc.y += v0.y; acc.z += v0.z; acc.w += v0.w;
    }
    float inv = 1.f / fmaxf((float)(end - beg), 1.f);
    float4 r = T4[(size_t)w * 64 + 32 + l];
    reinterpret_cast<float4*>(out)[(size_t)w * 32 + l] =
        make_float4(acc.x * inv + r.x, acc.y * inv + r.y,
                    acc.z * inv + r.z, acc.w * inv + r.w);
}

// ---------------------------------------------------------------------------
// HMMA GEMM with cp.async double-buffering. CTA tile 128x128, K=256 in 8
// chunks of 32, hi/lo split (3 mma passes/chunk). 8 warps (2m x 4n), warp
// tile 64x32. Dynamic smem: 2 bufs x {A,B} x {hi,lo} x (128 x SPAD bf16).
// ---------------------------------------------------------------------------
#define SPAD 40
#define TILE_B (128 * SPAD * 2)       // 10240 bytes per (matrix, half)
#define GEMM_SMEM (8 * TILE_B)        // 81920

template <int LAYER>
__global__ void __launch_bounds__(256)
mma_gemm_kernel(const float* __restrict__ bias, int N) {
    extern __shared__ char dsmem[];
    const uint32_t sbase = smem_to_u32(dsmem);

    const int tid  = threadIdx.x;
    const int lane = tid & 31;
    const int wid  = tid >> 5;
    const int wm   = (wid & 1) * 64;
    const int wn   = (wid >> 1) * 32;
    const int n0   = blockIdx.x * 128;
    const int o0   = blockIdx.y * 128;

    const __nv_bfloat16* __restrict__ AH = (LAYER == 1) ? g_a1h : g_a2h;
    const __nv_bfloat16* __restrict__ AL = (LAYER == 1) ? g_a1l : g_a2l;
    const __nv_bfloat16* __restrict__ WH = (LAYER == 1) ? g_w1h : g_w2h;
    const __nv_bfloat16* __restrict__ WL = (LAYER == 1) ? g_w1l : g_w2l;

    // tile(buf, mat, half): mat 0=A 1=B, half 0=hi 1=lo
    #define TILE_AT(buf, mat, half) \
        (sbase + (uint32_t)(((buf) * 4 + (mat) * 2 + (half)) * TILE_B))

    const int lrow = tid >> 2;
    const int lcol = (tid & 3) * 8;

    const int arow = wm + (lane & 15);
    const int acol = (lane >> 4) * 8;
    const int brow = wn + (lane & 7) + ((lane >> 4) << 3);
    const int bcol = ((lane >> 3) & 1) * 8;

    float acc[4][4][4];
#pragma unroll
    for (int mi = 0; mi < 4; mi++)
#pragma unroll
        for (int ni = 0; ni < 4; ni++)
#pragma unroll
            for (int q = 0; q < 4; q++) acc[mi][ni][q] = 0.f;

    // chunk loader via cp.async
    auto load_chunk = [&](int kc, int buf) {
#pragma unroll
        for (int i = 0; i < 2; i++) {
            int row = lrow + i * 64;
            int n = n0 + row;
            bool ok = n < N;
            size_t ga = (size_t)(ok ? n : 0) * 256 + kc + lcol;
            size_t gw = (size_t)(o0 + row) * 256 + kc + lcol;
            uint32_t so = (uint32_t)((row * SPAD + lcol) * 2);
            cp16(TILE_AT(buf, 0, 0) + so, AH + ga, ok);
            cp16(TILE_AT(buf, 0, 1) + so, AL + ga, ok);
            cp16(TILE_AT(buf, 1, 0) + so, WH + gw, true);
            cp16(TILE_AT(buf, 1, 1) + so, WL + gw, true);
        }
        asm volatile("cp.async.commit_group;");
    };

    load_chunk(0, 0);

    for (int c = 0; c < 8; c++) {
        const int cur = c & 1;
        if (c < 7) {
            load_chunk((c + 1) * 32, 1 - cur);
            asm volatile("cp.async.wait_group 1;");
        } else {
            asm volatile("cp.async.wait_group 0;");
        }
        __syncthreads();

#pragma unroll
        for (int t = 0; t < 3; t++) {
            const uint32_t uA = TILE_AT(cur, 0, (t == 2) ? 1 : 0);
            const uint32_t uB = TILE_AT(cur, 1, (t == 1) ? 1 : 0);
#pragma unroll
            for (int ks = 0; ks < 2; ks++) {
                const int k0 = ks * 16;
                uint32_t a[4][4], b[4][2];
#pragma unroll
                for (int mi = 0; mi < 4; mi++)
                    ldsm_x4(a[mi],
                            uA + ((arow + mi * 16) * SPAD + k0 + acol) * 2);
#pragma unroll
                for (int nip = 0; nip < 2; nip++) {
                    uint32_t bb[4];
                    ldsm_x4(bb, uB + ((brow + nip * 16) * SPAD + k0 + bcol) * 2);
                    b[nip * 2][0]     = bb[0]; b[nip * 2][1]     = bb[1];
                    b[nip * 2 + 1][0] = bb[2]; b[nip * 2 + 1][1] = bb[3];
                }
#pragma unroll
                for (int mi = 0; mi < 4; mi++)
#pragma unroll
                    for (int ni = 0; ni < 4; ni++)
                        mma16816(acc[mi][ni], a[mi], b[ni]);
            }
        }
        __syncthreads();
    }

    // epilogue
    const int erow = lane >> 2;
    const int ecol = (lane & 3) * 2;
#pragma unroll
    for (int mi = 0; mi < 4; mi++) {
#pragma unroll
        for (int half = 0; half < 2; half++) {
            int n = n0 + wm + mi * 16 + erow + half * 8;
            if (n >= N) continue;
#pragma unroll
            for (int ni = 0; ni < 4; ni++) {
                int col = o0 + wn + ni * 8 + ecol;
                float v0 = acc[mi][ni][half * 2 + 0];
                float v1 = acc[mi][ni][half * 2 + 1];
                if (LAYER == 1) {
                    v0 = fmaxf(v0 + bias[col],     0.f);
                    v1 = fmaxf(v1 + bias[col + 1], 0.f);
                    __nv_bfloat162 hp, lp;
                    split2(v0, v1, hp, lp);
                    size_t off = (size_t)n * 256 + col;
                    *reinterpret_cast<__nv_bfloat162*>(g_a2h + off) = hp;
                    *reinterpret_cast<__nv_bfloat162*>(g_a2l + off) = lp;
                } else {
                    if (col >= 128) {
                        v0 += bias[col - 128];
                        v1 += bias[col - 127];
                    }
                    *reinterpret_cast<float2*>(g_tr + (size_t)n * 256 + col) =
                        make_float2(v0, v1);
                }
            }
        }
    }
    #undef TILE_AT
}

// ---------------------------------------------------------------------------
// Launcher — kernel launches only; graph-capturable.
// ---------------------------------------------------------------------------
extern "C" void kernel_launch(void* const* d_in, const int* in_sizes, int n_in,
                              void* d_out, int out_size) {
    const float* x   = (const float*)d_in[0];
    const void*  ei  = d_in[1];
    const float* W1l = (const float*)d_in[2];
    const float* b1l = (const float*)d_in[3];
    const float* W1r = (const float*)d_in[4];
    const float* W2l = (const float*)d_in[5];
    const float* b2l = (const float*)d_in[6];
    const float* W2r = (const float*)d_in[7];
    float* out       = (float*)d_out;

    const int N = in_sizes[0] / IN_CH;
    const int E = in_sizes[1] / 2;
    const int NB = (N + 255) / 256;

    static bool attr_done = false;
    if (!attr_done) {
        cudaFuncSetAttribute(mma_gemm_kernel<1>,
                             cudaFuncAttributeMaxDynamicSharedMemorySize, GEMM_SMEM);
        cudaFuncSetAttribute(mma_gemm_kernel<2>,
                             cudaFuncAttributeMaxDynamicSharedMemorySize, GEMM_SMEM);
        attr_done = true;
    }

    // prep: weight split + dtype sniff + counter zero (one fused launch)
    prep_kernel<<<513 + NB, 256>>>(W1l, W1r, W2l, W2r, (const int*)ei, N);

    // CSR build
    hist_kernel<<<(E + 255) / 256, 256>>>(ei, E, N);
    scan_pass1<<<NB, 256>>>(N);
    scan_pass2<<<1, 256>>>(NB, N);
    scan_pass3<<<NB, 256>>>(N);
    fill_kernel<<<(E + 255) / 256, 256>>>(ei, E, N);

    // layer 1: aggregate + own-row convert, GEMM -> split A2
    agg1_kernel<<<(N * 32 + 255) / 256, 256>>>(x, N);
    {
        dim3 grid((N + 127) / 128, 2);
        mma_gemm_kernel<1><<<grid, 256, GEMM_SMEM>>>(b1l, N);
    }

    // layer 2: GEMM -> g_tr fp32, then gather + combine -> out
    {
        dim3 grid((N + 127) / 128, 2);
        mma_gemm_kernel<2><<<grid, 256, GEMM_SMEM>>>(b2l, N);
    }
    agg2_kernel<<<(N * 32 + 255) / 256, 256>>>(out, N);
}

// round 8
// speedup vs baseline: 5.7046x; 1.0049x over previous
#include <cuda_runtime.h>
#include <cuda_bf16.h>
#include <cstdint>

#define MAX_N 50000
#define MAX_E 800000
#define IN_CH 128
#define HID_CH 256
#define OUT_CH 128

// ---------------------------------------------------------------------------
// Device scratch (allocation-free rule)
// ---------------------------------------------------------------------------
__device__ __align__(16) __nv_bfloat16 g_a1h[(size_t)MAX_N * 256];
__device__ __align__(16) __nv_bfloat16 g_a1l[(size_t)MAX_N * 256];
__device__ __align__(16) __nv_bfloat16 g_a2h[(size_t)MAX_N * 256];
__device__ __align__(16) __nv_bfloat16 g_a2l[(size_t)MAX_N * 256];
__device__ __align__(16) __nv_bfloat16 g_w1h[256 * 256], g_w1l[256 * 256];
__device__ __align__(16) __nv_bfloat16 g_w2h[256 * 256], g_w2l[256 * 256];
__device__ float g_tr[(size_t)MAX_N * 256];
__device__ int g_cnt[MAX_N];
__device__ int g_fill[MAX_N];
__device__ int g_rowptr[MAX_N + 1];
__device__ int g_colidx[MAX_E];
__device__ int g_bsum[256];
__device__ int g_is64;

// ---------------------------------------------------------------------------
// Helpers
// ---------------------------------------------------------------------------
__device__ __forceinline__ uint32_t smem_to_u32(const void* p) {
    uint32_t a;
    asm("{ .reg .u64 t; cvta.to.shared.u64 t, %1; cvt.u32.u64 %0, t; }"
        : "=r"(a) : "l"(p));
    return a;
}

__device__ __forceinline__ void ldsm_x4(uint32_t* r, uint32_t addr) {
    asm volatile("ldmatrix.sync.aligned.m8n8.x4.shared.b16 {%0,%1,%2,%3}, [%4];"
        : "=r"(r[0]), "=r"(r[1]), "=r"(r[2]), "=r"(r[3]) : "r"(addr));
}

__device__ __forceinline__ void mma16816(float* d, const uint32_t* a,
                                          const uint32_t* b) {
    asm volatile(
        "mma.sync.aligned.m16n8k16.row.col.f32.bf16.bf16.f32 "
        "{%0,%1,%2,%3}, {%4,%5,%6,%7}, {%8,%9}, {%0,%1,%2,%3};"
        : "+f"(d[0]), "+f"(d[1]), "+f"(d[2]), "+f"(d[3])
        : "r"(a[0]), "r"(a[1]), "r"(a[2]), "r"(a[3]), "r"(b[0]), "r"(b[1]));
}

__device__ __forceinline__ void cp16(uint32_t dst, const void* src, bool pred) {
    int sz = pred ? 16 : 0;
    asm volatile("cp.async.cg.shared.global [%0], [%1], 16, %2;"
        :: "r"(dst), "l"(src), "r"(sz));
}

__device__ __forceinline__ void split2(float v0, float v1,
                                       __nv_bfloat162& hp, __nv_bfloat162& lp) {
    __nv_bfloat16 h0 = __float2bfloat16(v0);
    __nv_bfloat16 h1 = __float2bfloat16(v1);
    hp.x = h0; hp.y = h1;
    lp.x = __float2bfloat16(v0 - __bfloat162float(h0));
    lp.y = __float2bfloat16(v1 - __bfloat162float(h1));
}

__device__ __forceinline__ void load_edge(const void* ei, int e, int E,
                                          int& src, int& dst) {
    if (g_is64) {
        src = (int)reinterpret_cast<const long long*>(ei)[e];
        dst = (int)reinterpret_cast<const long long*>(ei)[(size_t)E + e];
    } else {
        src = reinterpret_cast<const int*>(ei)[e];
        dst = reinterpret_cast<const int*>(ei)[(size_t)E + e];
    }
}

// ---------------------------------------------------------------------------
// Kernel 0: zero counters + edge dtype sniff (block 0)
// ---------------------------------------------------------------------------
__global__ void zero_sniff_kernel(const int* __restrict__ ei32, int N) {
    __shared__ int red[128];
    int b = blockIdx.x, t = threadIdx.x;
    int i = b * 256 + t;
    if (i < N) { g_cnt[i] = 0; g_fill[i] = 0; }
    if (b == 0) {
        if (t < 128) red[t] = ei32[2 * t + 1];
        __syncthreads();
        for (int s = 64; s > 0; s >>= 1) {
            if (t < s && t < 128) red[t] |= red[t + s];
            __syncthreads();
        }
        if (t == 0) g_is64 = (red[0] == 0) ? 1 : 0;
    }
}

// ---------------------------------------------------------------------------
// Kernel 1: histogram (blocks [0,EB)) + weight hi/lo split (blocks [EB,EB+512))
// co-scheduled so weight prep hides behind the edge pass.
// ---------------------------------------------------------------------------
__global__ void hist_prep_kernel(const void* __restrict__ ei, int E, int N, int EB,
                                 const float* __restrict__ W1l,
                                 const float* __restrict__ W1r,
                                 const float* __restrict__ W2l,
                                 const float* __restrict__ W2r) {
    int b = blockIdx.x, t = threadIdx.x;
    if (b < EB) {
        int e = b * 256 + t;
        if (e >= E) return;
        int src, dst;
        load_edge(ei, e, E, src, dst);
        if ((unsigned)dst < (unsigned)N) atomicAdd(&g_cnt[dst], 1);
    } else {
        int wb = b - EB;                   // 0..511
        int idx = (wb & 255) * 256 + t;
        int o = idx >> 8, k = idx & 255;
        float v;
        __nv_bfloat16 *H, *L;
        if (wb < 256) {   // layer1: k<128 -> W1r[o,k], else W1l[o,k-128]
            v = (k < 128) ? W1r[o * 128 + k] : W1l[o * 128 + (k - 128)];
            H = g_w1h; L = g_w1l;
        } else {          // layer2: o<128 -> W2l[o,k], else W2r[o-128,k]
            v = (o < 128) ? W2l[o * 256 + k] : W2r[(o - 128) * 256 + k];
            H = g_w2h; L = g_w2l;
        }
        __nv_bfloat16 hi = __float2bfloat16(v);
        H[idx] = hi;
        L[idx] = __float2bfloat16(v - __bfloat162float(hi));
    }
}

// ---------------------------------------------------------------------------
// Scan: pass1 (block sums), pass23 fused (per-block base re-derivation + local
// exclusive scan). NB <= 256 guaranteed (N <= 50000 -> NB <= 196).
// ---------------------------------------------------------------------------
__global__ void scan_pass1(int N) {
    __shared__ int sh[256];
    int t = threadIdx.x, i = blockIdx.x * 256 + t;
    sh[t] = (i < N) ? g_cnt[i] : 0;
    __syncthreads();
    for (int s = 128; s > 0; s >>= 1) {
        if (t < s) sh[t] += sh[t + s];
        __syncthreads();
    }
    if (t == 0) g_bsum[blockIdx.x] = sh[0];
}

__global__ void scan_pass23(int NB, int N) {
    __shared__ int sh[256];
    __shared__ int base_sh;
    int t = threadIdx.x, bid = blockIdx.x;
    // base = sum of block sums before this block
    sh[t] = (t < bid) ? g_bsum[t] : 0;
    __syncthreads();
    for (int s = 128; s > 0; s >>= 1) {
        if (t < s) sh[t] += sh[t + s];
        __syncthreads();
    }
    if (t == 0) base_sh = sh[0];
    __syncthreads();
    int base = base_sh;
    // block-local inclusive scan of counts
    int i = bid * 256 + t;
    int c = (i < N) ? g_cnt[i] : 0;
    __syncthreads();
    sh[t] = c;
    __syncthreads();
    for (int off = 1; off < 256; off <<= 1) {
        int x2 = (t >= off) ? sh[t - off] : 0;
        __syncthreads();
        sh[t] += x2;
        __syncthreads();
    }
    if (i < N) g_rowptr[i] = base + sh[t] - c;   // exclusive
    if (bid == NB - 1 && t == 255) g_rowptr[N] = base + sh[255];
}

__global__ void fill_kernel(const void* __restrict__ ei, int E, int N) {
    int e = blockIdx.x * blockDim.x + threadIdx.x;
    if (e >= E) return;
    int src, dst;
    load_edge(ei, e, E, src, dst);
    if ((unsigned)dst >= (unsigned)N || (unsigned)src >= (unsigned)N) return;
    int slot = g_rowptr[dst] + atomicAdd(&g_fill[dst], 1);
    g_colidx[slot] = src;
}

// ---------------------------------------------------------------------------
// Layer-1 aggregation + own-row conversion:
//   cols 0..127   <- split(x[n]);  cols 128..255 <- split(mean_{s} x[s])
// One warp per node, one float4 per lane.
// ---------------------------------------------------------------------------
__global__ void agg1_kernel(const float* __restrict__ x, int N) {
    int w = (blockIdx.x * blockDim.x + threadIdx.x) >> 5;
    int l = threadIdx.x & 31;
    if (w >= N) return;
    int beg = g_rowptr[w], end = g_rowptr[w + 1];
    const float4* X4 = reinterpret_cast<const float4*>(x);
    float4 acc = make_float4(0.f, 0.f, 0.f, 0.f);
    int i = beg;
    for (; i + 1 < end; i += 2) {
        int s0 = g_colidx[i], s1 = g_colidx[i + 1];
        float4 v0 = X4[(size_t)s0 * 32 + l];
        float4 v1 = X4[(size_t)s1 * 32 + l];
        acc.x += v0.x + v1.x; acc.y += v0.y + v1.y;
        acc.z += v0.z + v1.z; acc.w += v0.w + v1.w;
    }
    if (i < end) {
        int s0 = g_colidx[i];
        float4 v0 = X4[(size_t)s0 * 32 + l];
        acc.x += v0.x; acc.y += v0.y; acc.z += v0.z; acc.w += v0.w;
    }
    float inv = 1.f / fmaxf((float)(end - beg), 1.f);
    acc.x *= inv; acc.y *= inv; acc.z *= inv; acc.w *= inv;
    __nv_bfloat162 hp0, lp0, hp1, lp1;
    split2(acc.x, acc.y, hp0, lp0);
    split2(acc.z, acc.w, hp1, lp1);
    size_t base = (size_t)w * 256 + 128 + l * 4;
    *reinterpret_cast<__nv_bfloat162*>(g_a1h + base)     = hp0;
    *reinterpret_cast<__nv_bfloat162*>(g_a1h + base + 2) = hp1;
    *reinterpret_cast<__nv_bfloat162*>(g_a1l + base)     = lp0;
    *reinterpret_cast<__nv_bfloat162*>(g_a1l + base + 2) = lp1;
    float4 xr = X4[(size_t)w * 32 + l];
    split2(xr.x, xr.y, hp0, lp0);
    split2(xr.z, xr.w, hp1, lp1);
    base = (size_t)w * 256 + l * 4;
    *reinterpret_cast<__nv_bfloat162*>(g_a1h + base)     = hp0;
    *reinterpret_cast<__nv_bfloat162*>(g_a1h + base + 2) = hp1;
    *reinterpret_cast<__nv_bfloat162*>(g_a1l + base)     = lp0;
    *reinterpret_cast<__nv_bfloat162*>(g_a1l + base + 2) = lp1;
}

// ---------------------------------------------------------------------------
// Layer-2 aggregation + final combine:
//   out[n][c] = mean_{s in N(n)} tr[s][c] + tr[n][128+c]
// ---------------------------------------------------------------------------
__global__ void agg2_kernel(float* __restrict__ out, int N) {
    int w = (blockIdx.x * blockDim.x + threadIdx.x) >> 5;
    int l = threadIdx.x & 31;
    if (w >= N) return;
    int beg = g_rowptr[w], end = g_rowptr[w + 1];
    const float4* T4 = reinterpret_cast<const float4*>(g_tr);
    float4 acc = make_float4(0.f, 0.f, 0.f, 0.f);
    int i = beg;
    for (; i + 1 < end; i += 2) {
        int s0 = g_colidx[i], s1 = g_colidx[i + 1];
        float4 v0 = T4[(size_t)s0 * 64 + l];
        float4 v1 = T4[(size_t)s1 * 64 + l];
        acc.x += v0.x + v1.x; acc.y += v0.y + v1.y;
        acc.z += v0.z + v1.z; acc.w += v0.w + v1.w;
    }
    if (i < end) {
        int s0 = g_colidx[i];
        float4 v0 = T4[(size_t)s0 * 64 + l];
        acc.x += v0.x; acc.y += v0.y; acc.z += v0.z; acc.w += v0.w;
    }
    float inv = 1.f / fmaxf((float)(end - beg), 1.f);
    float4 r = T4[(size_t)w * 64 + 32 + l];
    reinterpret_cast<float4*>(out)[(size_t)w * 32 + l] =
        make_float4(acc.x * inv + r.x, acc.y * inv + r.y,
                    acc.z * inv + r.z, acc.w * inv + r.w);
}

// ---------------------------------------------------------------------------
// HMMA GEMM with cp.async double-buffering (proven R7). CTA tile 128x128,
// K=256 in 8 chunks of 32, hi/lo split (3 mma passes/chunk). 8 warps (2m x 4n).
// ---------------------------------------------------------------------------
#define SPAD 40
#define TILE_B (128 * SPAD * 2)
#define GEMM_SMEM (8 * TILE_B)

template <int LAYER>
__global__ void __launch_bounds__(256)
mma_gemm_kernel(const float* __restrict__ bias, int N) {
    extern __shared__ char dsmem[];
    const uint32_t sbase = smem_to_u32(dsmem);

    const int tid  = threadIdx.x;
    const int lane = tid & 31;
    const int wid  = tid >> 5;
    const int wm   = (wid & 1) * 64;
    const int wn   = (wid >> 1) * 32;
    const int n0   = blockIdx.x * 128;
    const int o0   = blockIdx.y * 128;

    const __nv_bfloat16* __restrict__ AH = (LAYER == 1) ? g_a1h : g_a2h;
    const __nv_bfloat16* __restrict__ AL = (LAYER == 1) ? g_a1l : g_a2l;
    const __nv_bfloat16* __restrict__ WH = (LAYER == 1) ? g_w1h : g_w2h;
    const __nv_bfloat16* __restrict__ WL = (LAYER == 1) ? g_w1l : g_w2l;

    #define TILE_AT(buf, mat, half) \
        (sbase + (uint32_t)(((buf) * 4 + (mat) * 2 + (half)) * TILE_B))

    const int lrow = tid >> 2;
    const int lcol = (tid & 3) * 8;

    const int arow = wm + (lane & 15);
    const int acol = (lane >> 4) * 8;
    const int brow = wn + (lane & 7) + ((lane >> 4) << 3);
    const int bcol = ((lane >> 3) & 1) * 8;

    float acc[4][4][4];
#pragma unroll
    for (int mi = 0; mi < 4; mi++)
#pragma unroll
        for (int ni = 0; ni < 4; ni++)
#pragma unroll
            for (int q = 0; q < 4; q++) acc[mi][ni][q] = 0.f;

    auto load_chunk = [&](int kc, int buf) {
#pragma unroll
        for (int i = 0; i < 2; i++) {
            int row = lrow + i * 64;
            int n = n0 + row;
            bool ok = n < N;
            size_t ga = (size_t)(ok ? n : 0) * 256 + kc + lcol;
            size_t gw = (size_t)(o0 + row) * 256 + kc + lcol;
            uint32_t so = (uint32_t)((row * SPAD + lcol) * 2);
            cp16(TILE_AT(buf, 0, 0) + so, AH + ga, ok);
            cp16(TILE_AT(buf, 0, 1) + so, AL + ga, ok);
            cp16(TILE_AT(buf, 1, 0) + so, WH + gw, true);
            cp16(TILE_AT(buf, 1, 1) + so, WL + gw, true);
        }
        asm volatile("cp.async.commit_group;");
    };

    load_chunk(0, 0);

    for (int c = 0; c < 8; c++) {
        const int cur = c & 1;
        if (c < 7) {
            load_chunk((c + 1) * 32, 1 - cur);
            asm volatile("cp.async.wait_group 1;");
        } else {
            asm volatile("cp.async.wait_group 0;");
        }
        __syncthreads();

#pragma unroll
        for (int t = 0; t < 3; t++) {
            const uint32_t uA = TILE_AT(cur, 0, (t == 2) ? 1 : 0);
            const uint32_t uB = TILE_AT(cur, 1, (t == 1) ? 1 : 0);
#pragma unroll
            for (int ks = 0; ks < 2; ks++) {
                const int k0 = ks * 16;
                uint32_t a[4][4], b[4][2];
#pragma unroll
                for (int mi = 0; mi < 4; mi++)
                    ldsm_x4(a[mi],
                            uA + ((arow + mi * 16) * SPAD + k0 + acol) * 2);
#pragma unroll
                for (int nip = 0; nip < 2; nip++) {
                    uint32_t bb[4];
                    ldsm_x4(bb, uB + ((brow + nip * 16) * SPAD + k0 + bcol) * 2);
                    b[nip * 2][0]     = bb[0]; b[nip * 2][1]     = bb[1];
                    b[nip * 2 + 1][0] = bb[2]; b[nip * 2 + 1][1] = bb[3];
                }
#pragma unroll
                for (int mi = 0; mi < 4; mi++)
#pragma unroll
                    for (int ni = 0; ni < 4; ni++)
                        mma16816(acc[mi][ni], a[mi], b[ni]);
            }
        }
        __syncthreads();
    }

    const int erow = lane >> 2;
    const int ecol = (lane & 3) * 2;
#pragma unroll
    for (int mi = 0; mi < 4; mi++) {
#pragma unroll
        for (int half = 0; half < 2; half++) {
            int n = n0 + wm + mi * 16 + erow + half * 8;
            if (n >= N) continue;
#pragma unroll
            for (int ni = 0; ni < 4; ni++) {
                int col = o0 + wn + ni * 8 + ecol;
                float v0 = acc[mi][ni][half * 2 + 0];
                float v1 = acc[mi][ni][half * 2 + 1];
                if (LAYER == 1) {
                    v0 = fmaxf(v0 + bias[col],     0.f);
                    v1 = fmaxf(v1 + bias[col + 1], 0.f);
                    __nv_bfloat162 hp, lp;
                    split2(v0, v1, hp, lp);
                    size_t off = (size_t)n * 256 + col;
                    *reinterpret_cast<__nv_bfloat162*>(g_a2h + off) = hp;
                    *reinterpret_cast<__nv_bfloat162*>(g_a2l + off) = lp;
                } else {
                    if (col >= 128) {
                        v0 += bias[col - 128];
                        v1 += bias[col - 127];
                    }
                    *reinterpret_cast<float2*>(g_tr + (size_t)n * 256 + col) =
                        make_float2(v0, v1);
                }
            }
        }
    }
    #undef TILE_AT
}

// ---------------------------------------------------------------------------
// Launcher — kernel launches only; graph-capturable; no static state.
// ---------------------------------------------------------------------------
extern "C" void kernel_launch(void* const* d_in, const int* in_sizes, int n_in,
                              void* d_out, int out_size) {
    const float* x   = (const float*)d_in[0];
    const void*  ei  = d_in[1];
    const float* W1l = (const float*)d_in[2];
    const float* b1l = (const float*)d_in[3];
    const float* W1r = (const float*)d_in[4];
    const float* W2l = (const float*)d_in[5];
    const float* b2l = (const float*)d_in[6];
    const float* W2r = (const float*)d_in[7];
    float* out       = (float*)d_out;

    const int N  = in_sizes[0] / IN_CH;
    const int E  = in_sizes[1] / 2;
    const int NB = (N + 255) / 256;
    const int EB = (E + 255) / 256;

    cudaFuncSetAttribute(mma_gemm_kernel<1>,
                         cudaFuncAttributeMaxDynamicSharedMemorySize, GEMM_SMEM);
    cudaFuncSetAttribute(mma_gemm_kernel<2>,
                         cudaFuncAttributeMaxDynamicSharedMemorySize, GEMM_SMEM);

    // 0: zero counters + dtype sniff
    zero_sniff_kernel<<<NB, 256>>>((const int*)ei, N);
    // 1: histogram + weight split (co-scheduled)
    hist_prep_kernel<<<EB + 512, 256>>>(ei, E, N, EB, W1l, W1r, W2l, W2r);
    // 2,3: scan
    scan_pass1<<<NB, 256>>>(N);
    scan_pass23<<<NB, 256>>>(NB, N);
    // 4: CSR fill
    fill_kernel<<<EB, 256>>>(ei, E, N);
    // 5: layer-1 aggregation + own-row convert
    agg1_kernel<<<(N * 32 + 255) / 256, 256>>>(x, N);
    // 6: layer-1 GEMM (relu, split bf16 out)
    {
        dim3 grid((N + 127) / 128, 2);
        mma_gemm_kernel<1><<<grid, 256, GEMM_SMEM>>>(b1l, N);
    }
    // 7: layer-2 GEMM (fp32 out)
    {
        dim3 grid((N + 127) / 128, 2);
        mma_gemm_kernel<2><<<grid, 256, GEMM_SMEM>>>(b2l, N);
    }
    // 8: layer-2 aggregation + combine
    agg2_kernel<<<(N * 32 + 255) / 256, 256>>>(out, N);
}

// round 9
// speedup vs baseline: 7.4706x; 1.3096x over previous
#include <cuda_runtime.h>
#include <cuda_bf16.h>
#include <cuda_fp16.h>
#include <cstdint>

#define MAX_N 50000
#define MAX_E 800000
#define IN_CH 128
#define HID_CH 256
#define OUT_CH 128

// ---------------------------------------------------------------------------
// Device scratch (allocation-free rule)
// ---------------------------------------------------------------------------
__device__ __align__(16) __half g_a1h[(size_t)MAX_N * 256];   // layer-1 A hi (fp16)
__device__ __align__(16) __half g_a1l[(size_t)MAX_N * 256];   // layer-1 A lo (fp16)
__device__ __align__(16) __half g_a2h[(size_t)MAX_N * 256];
__device__ __align__(16) __half g_a2l[(size_t)MAX_N * 256];
__device__ __align__(16) __half g_w1[256 * 256];              // composite W, fp16
__device__ __align__(16) __half g_w2[256 * 256];
__device__ float g_tr[(size_t)MAX_N * 256];
__device__ int g_cnt[MAX_N];
__device__ int g_fill[MAX_N];
__device__ int g_rowptr[MAX_N + 1];
__device__ int g_colidx[MAX_E];
__device__ int g_bsum[256];
__device__ int g_is64;

// ---------------------------------------------------------------------------
// Helpers
// ---------------------------------------------------------------------------
__device__ __forceinline__ uint32_t smem_to_u32(const void* p) {
    uint32_t a;
    asm("{ .reg .u64 t; cvta.to.shared.u64 t, %1; cvt.u32.u64 %0, t; }"
        : "=r"(a) : "l"(p));
    return a;
}

__device__ __forceinline__ void ldsm_x4(uint32_t* r, uint32_t addr) {
    asm volatile("ldmatrix.sync.aligned.m8n8.x4.shared.b16 {%0,%1,%2,%3}, [%4];"
        : "=r"(r[0]), "=r"(r[1]), "=r"(r[2]), "=r"(r[3]) : "r"(addr));
}

// m16n8k16 fp16 HMMA, fp32 accumulate-in-place
__device__ __forceinline__ void mma16816(float* d, const uint32_t* a,
                                          const uint32_t* b) {
    asm volatile(
        "mma.sync.aligned.m16n8k16.row.col.f32.f16.f16.f32 "
        "{%0,%1,%2,%3}, {%4,%5,%6,%7}, {%8,%9}, {%0,%1,%2,%3};"
        : "+f"(d[0]), "+f"(d[1]), "+f"(d[2]), "+f"(d[3])
        : "r"(a[0]), "r"(a[1]), "r"(a[2]), "r"(a[3]), "r"(b[0]), "r"(b[1]));
}

__device__ __forceinline__ void cp16(uint32_t dst, const void* src, bool pred) {
    int sz = pred ? 16 : 0;
    asm volatile("cp.async.cg.shared.global [%0], [%1], 16, %2;"
        :: "r"(dst), "l"(src), "r"(sz));
}

// fp16 hi/lo split of two fp32 values
__device__ __forceinline__ void split2h(float v0, float v1,
                                        __half2& hp, __half2& lp) {
    __half h0 = __float2half_rn(v0);
    __half h1 = __float2half_rn(v1);
    hp = __halves2half2(h0, h1);
    lp = __halves2half2(__float2half_rn(v0 - __half2float(h0)),
                        __float2half_rn(v1 - __half2float(h1)));
}

__device__ __forceinline__ void load_edge(const void* ei, int e, int E,
                                          int& src, int& dst) {
    if (g_is64) {
        src = (int)reinterpret_cast<const long long*>(ei)[e];
        dst = (int)reinterpret_cast<const long long*>(ei)[(size_t)E + e];
    } else {
        src = reinterpret_cast<const int*>(ei)[e];
        dst = reinterpret_cast<const int*>(ei)[(size_t)E + e];
    }
}

// ---------------------------------------------------------------------------
// Kernel 0: zero counters + edge dtype sniff (block 0)
// ---------------------------------------------------------------------------
__global__ void zero_sniff_kernel(const int* __restrict__ ei32, int N) {
    __shared__ int red[128];
    int b = blockIdx.x, t = threadIdx.x;
    int i = b * 256 + t;
    if (i < N) { g_cnt[i] = 0; g_fill[i] = 0; }
    if (b == 0) {
        if (t < 128) red[t] = ei32[2 * t + 1];
        __syncthreads();
        for (int s = 64; s > 0; s >>= 1) {
            if (t < s && t < 128) red[t] |= red[t + s];
            __syncthreads();
        }
        if (t == 0) g_is64 = (red[0] == 0) ? 1 : 0;
    }
}

// ---------------------------------------------------------------------------
// Kernel 1: histogram (blocks [0,EB)) + fp16 weight prep (blocks [EB,EB+512))
// layer1 composite row o: k<128 -> W1r[o,k], else W1l[o,k-128]
// layer2 composite row o: o<128 -> W2l[o,k], else W2r[o-128,k]
// ---------------------------------------------------------------------------
__global__ void hist_prep_kernel(const void* __restrict__ ei, int E, int N, int EB,
                                 const float* __restrict__ W1l,
                                 const float* __restrict__ W1r,
                                 const float* __restrict__ W2l,
                                 const float* __restrict__ W2r) {
    int b = blockIdx.x, t = threadIdx.x;
    if (b < EB) {
        int e = b * 256 + t;
        if (e >= E) return;
        int src, dst;
        load_edge(ei, e, E, src, dst);
        if ((unsigned)dst < (unsigned)N) atomicAdd(&g_cnt[dst], 1);
    } else {
        int wb = b - EB;                   // 0..511
        int idx = (wb & 255) * 256 + t;
        int o = idx >> 8, k = idx & 255;
        if (wb < 256) {
            float v = (k < 128) ? W1r[o * 128 + k] : W1l[o * 128 + (k - 128)];
            g_w1[idx] = __float2half_rn(v);
        } else {
            float v = (o < 128) ? W2l[o * 256 + k] : W2r[(o - 128) * 256 + k];
            g_w2[idx] = __float2half_rn(v);
        }
    }
}

// ---------------------------------------------------------------------------
// Scan: pass1 (block sums) + fused pass23
// ---------------------------------------------------------------------------
__global__ void scan_pass1(int N) {
    __shared__ int sh[256];
    int t = threadIdx.x, i = blockIdx.x * 256 + t;
    sh[t] = (i < N) ? g_cnt[i] : 0;
    __syncthreads();
    for (int s = 128; s > 0; s >>= 1) {
        if (t < s) sh[t] += sh[t + s];
        __syncthreads();
    }
    if (t == 0) g_bsum[blockIdx.x] = sh[0];
}

__global__ void scan_pass23(int NB, int N) {
    __shared__ int sh[256];
    __shared__ int base_sh;
    int t = threadIdx.x, bid = blockIdx.x;
    sh[t] = (t < bid) ? g_bsum[t] : 0;
    __syncthreads();
    for (int s = 128; s > 0; s >>= 1) {
        if (t < s) sh[t] += sh[t + s];
        __syncthreads();
    }
    if (t == 0) base_sh = sh[0];
    __syncthreads();
    int base = base_sh;
    int i = bid * 256 + t;
    int c = (i < N) ? g_cnt[i] : 0;
    __syncthreads();
    sh[t] = c;
    __syncthreads();
    for (int off = 1; off < 256; off <<= 1) {
        int x2 = (t >= off) ? sh[t - off] : 0;
        __syncthreads();
        sh[t] += x2;
        __syncthreads();
    }
    if (i < N) g_rowptr[i] = base + sh[t] - c;
    if (bid == NB - 1 && t == 255) g_rowptr[N] = base + sh[255];
}

__global__ void fill_kernel(const void* __restrict__ ei, int E, int N) {
    int e = blockIdx.x * blockDim.x + threadIdx.x;
    if (e >= E) return;
    int src, dst;
    load_edge(ei, e, E, src, dst);
    if ((unsigned)dst >= (unsigned)N || (unsigned)src >= (unsigned)N) return;
    int slot = g_rowptr[dst] + atomicAdd(&g_fill[dst], 1);
    g_colidx[slot] = src;
}

// ---------------------------------------------------------------------------
// Layer-1 aggregation + own-row conversion (fp16 hi/lo):
//   cols 0..127   <- split(x[n]);  cols 128..255 <- split(mean_{s} x[s])
// ---------------------------------------------------------------------------
__global__ void agg1_kernel(const float* __restrict__ x, int N) {
    int w = (blockIdx.x * blockDim.x + threadIdx.x) >> 5;
    int l = threadIdx.x & 31;
    if (w >= N) return;
    int beg = g_rowptr[w], end = g_rowptr[w + 1];
    const float4* X4 = reinterpret_cast<const float4*>(x);
    float4 acc = make_float4(0.f, 0.f, 0.f, 0.f);
    int i = beg;
    for (; i + 1 < end; i += 2) {
        int s0 = g_colidx[i], s1 = g_colidx[i + 1];
        float4 v0 = X4[(size_t)s0 * 32 + l];
        float4 v1 = X4[(size_t)s1 * 32 + l];
        acc.x += v0.x + v1.x; acc.y += v0.y + v1.y;
        acc.z += v0.z + v1.z; acc.w += v0.w + v1.w;
    }
    if (i < end) {
        int s0 = g_colidx[i];
        float4 v0 = X4[(size_t)s0 * 32 + l];
        acc.x += v0.x; acc.y += v0.y; acc.z += v0.z; acc.w += v0.w;
    }
    float inv = 1.f / fmaxf((float)(end - beg), 1.f);
    acc.x *= inv; acc.y *= inv; acc.z *= inv; acc.w *= inv;
    __half2 hp0, lp0, hp1, lp1;
    split2h(acc.x, acc.y, hp0, lp0);
    split2h(acc.z, acc.w, hp1, lp1);
    size_t base = (size_t)w * 256 + 128 + l * 4;
    *reinterpret_cast<__half2*>(g_a1h + base)     = hp0;
    *reinterpret_cast<__half2*>(g_a1h + base + 2) = hp1;
    *reinterpret_cast<__half2*>(g_a1l + base)     = lp0;
    *reinterpret_cast<__half2*>(g_a1l + base + 2) = lp1;
    float4 xr = X4[(size_t)w * 32 + l];
    split2h(xr.x, xr.y, hp0, lp0);
    split2h(xr.z, xr.w, hp1, lp1);
    base = (size_t)w * 256 + l * 4;
    *reinterpret_cast<__half2*>(g_a1h + base)     = hp0;
    *reinterpret_cast<__half2*>(g_a1h + base + 2) = hp1;
    *reinterpret_cast<__half2*>(g_a1l + base)     = lp0;
    *reinterpret_cast<__half2*>(g_a1l + base + 2) = lp1;
}

// ---------------------------------------------------------------------------
// Layer-2 aggregation + final combine:
//   out[n][c] = mean_{s in N(n)} tr[s][c] + tr[n][128+c]
// ---------------------------------------------------------------------------
__global__ void agg2_kernel(float* __restrict__ out, int N) {
    int w = (blockIdx.x * blockDim.x + threadIdx.x) >> 5;
    int l = threadIdx.x & 31;
    if (w >= N) return;
    int beg = g_rowptr[w], end = g_rowptr[w + 1];
    const float4* T4 = reinterpret_cast<const float4*>(g_tr);
    float4 acc = make_float4(0.f, 0.f, 0.f, 0.f);
    int i = beg;
    for (; i + 1 < end; i += 2) {
        int s0 = g_colidx[i], s1 = g_colidx[i + 1];
        float4 v0 = T4[(size_t)s0 * 64 + l];
        float4 v1 = T4[(size_t)s1 * 64 + l];
        acc.x += v0.x + v1.x; acc.y += v0.y + v1.y;
        acc.z += v0.z + v1.z; acc.w += v0.w + v1.w;
    }
    if (i < end) {
        int s0 = g_colidx[i];
        float4 v0 = T4[(size_t)s0 * 64 + l];
        acc.x += v0.x; acc.y += v0.y; acc.z += v0.z; acc.w += v0.w;
    }
    float inv = 1.f / fmaxf((float)(end - beg), 1.f);
    float4 r = T4[(size_t)w * 64 + 32 + l];
    reinterpret_cast<float4*>(out)[(size_t)w * 32 + l] =
        make_float4(acc.x * inv + r.x, acc.y * inv + r.y,
                    acc.z * inv + r.z, acc.w * inv + r.w);
}

// ---------------------------------------------------------------------------
// HMMA GEMM, fp16, A hi/lo split (2 passes: AhB + AlB), B single fp16.
// CTA tile 128x128, K=256 in 8 chunks of 32, cp.async double-buffered.
// 8 warps (2m x 4n), warp tile 64x32. Tiles per buf: Ah, Al, B.
// LAYER 1: A=g_a1*, W=g_w1; epi relu(+b1l all cols) -> fp16 split g_a2*
// LAYER 2: A=g_a2*, W=g_w2; epi +b2l on cols>=128   -> fp32 g_tr
// ---------------------------------------------------------------------------
#define SPAD 40
#define TILE_B (128 * SPAD * 2)     // 10240 bytes
#define GEMM_SMEM (6 * TILE_B)      // 61440

template <int LAYER>
__global__ void __launch_bounds__(256)
mma_gemm_kernel(const float* __restrict__ bias, int N) {
    extern __shared__ char dsmem[];
    const uint32_t sbase = smem_to_u32(dsmem);

    const int tid  = threadIdx.x;
    const int lane = tid & 31;
    const int wid  = tid >> 5;
    const int wm   = (wid & 1) * 64;
    const int wn   = (wid >> 1) * 32;
    const int n0   = blockIdx.x * 128;
    const int o0   = blockIdx.y * 128;

    const __half* __restrict__ AH = (LAYER == 1) ? g_a1h : g_a2h;
    const __half* __restrict__ AL = (LAYER == 1) ? g_a1l : g_a2l;
    const __half* __restrict__ W  = (LAYER == 1) ? g_w1 : g_w2;

    // tile slots: 0=Ah, 1=Al, 2=B
    #define TILE_AT(buf, slot) (sbase + (uint32_t)(((buf) * 3 + (slot)) * TILE_B))

    const int lrow = tid >> 2;
    const int lcol = (tid & 3) * 8;

    const int arow = wm + (lane & 15);
    const int acol = (lane >> 4) * 8;
    const int brow = wn + (lane & 7) + ((lane >> 4) << 3);
    const int bcol = ((lane >> 3) & 1) * 8;

    float acc[4][4][4];
#pragma unroll
    for (int mi = 0; mi < 4; mi++)
#pragma unroll
        for (int ni = 0; ni < 4; ni++)
#pragma unroll
            for (int q = 0; q < 4; q++) acc[mi][ni][q] = 0.f;

    auto load_chunk = [&](int kc, int buf) {
#pragma unroll
        for (int i = 0; i < 2; i++) {
            int row = lrow + i * 64;
            int n = n0 + row;
            bool ok = n < N;
            size_t ga = (size_t)(ok ? n : 0) * 256 + kc + lcol;
            size_t gw = (size_t)(o0 + row) * 256 + kc + lcol;
            uint32_t so = (uint32_t)((row * SPAD + lcol) * 2);
            cp16(TILE_AT(buf, 0) + so, AH + ga, ok);
            cp16(TILE_AT(buf, 1) + so, AL + ga, ok);
            cp16(TILE_AT(buf, 2) + so, W + gw, true);
        }
        asm volatile("cp.async.commit_group;");
    };

    load_chunk(0, 0);

    for (int c = 0; c < 8; c++) {
        const int cur = c & 1;
        if (c < 7) {
            load_chunk((c + 1) * 32, 1 - cur);
            asm volatile("cp.async.wait_group 1;");
        } else {
            asm volatile("cp.async.wait_group 0;");
        }
        __syncthreads();

#pragma unroll
        for (int t = 0; t < 2; t++) {
            const uint32_t uA = TILE_AT(cur, t);       // 0=Ah, 1=Al
            const uint32_t uB = TILE_AT(cur, 2);
#pragma unroll
            for (int ks = 0; ks < 2; ks++) {
                const int k0 = ks * 16;
                uint32_t a[4][4], b[4][2];
#pragma unroll
                for (int mi = 0; mi < 4; mi++)
                    ldsm_x4(a[mi],
                            uA + ((arow + mi * 16) * SPAD + k0 + acol) * 2);
#pragma unroll
                for (int nip = 0; nip < 2; nip++) {
                    uint32_t bb[4];
                    ldsm_x4(bb, uB + ((brow + nip * 16) * SPAD + k0 + bcol) * 2);
                    b[nip * 2][0]     = bb[0]; b[nip * 2][1]     = bb[1];
                    b[nip * 2 + 1][0] = bb[2]; b[nip * 2 + 1][1] = bb[3];
                }
#pragma unroll
                for (int mi = 0; mi < 4; mi++)
#pragma unroll
                    for (int ni = 0; ni < 4; ni++)
                        mma16816(acc[mi][ni], a[mi], b[ni]);
            }
        }
        __syncthreads();
    }

    const int erow = lane >> 2;
    const int ecol = (lane & 3) * 2;
#pragma unroll
    for (int mi = 0; mi < 4; mi++) {
#pragma unroll
        for (int half = 0; half < 2; half++) {
            int n = n0 + wm + mi * 16 + erow + half * 8;
            if (n >= N) continue;
#pragma unroll
            for (int ni = 0; ni < 4; ni++) {
                int col = o0 + wn + ni * 8 + ecol;
                float v0 = acc[mi][ni][half * 2 + 0];
                float v1 = acc[mi][ni][half * 2 + 1];
                if (LAYER == 1) {
                    v0 = fmaxf(v0 + bias[col],     0.f);
                    v1 = fmaxf(v1 + bias[col + 1], 0.f);
                    __half2 hp, lp;
                    split2h(v0, v1, hp, lp);
                    size_t off = (size_t)n * 256 + col;
                    *reinterpret_cast<__half2*>(g_a2h + off) = hp;
                    *reinterpret_cast<__half2*>(g_a2l + off) = lp;
                } else {
                    if (col >= 128) {
                        v0 += bias[col - 128];
                        v1 += bias[col - 127];
                    }
                    *reinterpret_cast<float2*>(g_tr + (size_t)n * 256 + col) =
                        make_float2(v0, v1);
                }
            }
        }
    }
    #undef TILE_AT
}

// ---------------------------------------------------------------------------
// Launcher — kernel launches only; graph-capturable; no static state.
// ---------------------------------------------------------------------------
extern "C" void kernel_launch(void* const* d_in, const int* in_sizes, int n_in,
                              void* d_out, int out_size) {
    const float* x   = (const float*)d_in[0];
    const void*  ei  = d_in[1];
    const float* W1l = (const float*)d_in[2];
    const float* b1l = (const float*)d_in[3];
    const float* W1r = (const float*)d_in[4];
    const float* W2l = (const float*)d_in[5];
    const float* b2l = (const float*)d_in[6];
    const float* W2r = (const float*)d_in[7];
    float* out       = (float*)d_out;

    const int N  = in_sizes[0] / IN_CH;
    const int E  = in_sizes[1] / 2;
    const int NB = (N + 255) / 256;
    const int EB = (E + 255) / 256;

    cudaFuncSetAttribute(mma_gemm_kernel<1>,
                         cudaFuncAttributeMaxDynamicSharedMemorySize, GEMM_SMEM);
    cudaFuncSetAttribute(mma_gemm_kernel<2>,
                         cudaFuncAttributeMaxDynamicSharedMemorySize, GEMM_SMEM);

    zero_sniff_kernel<<<NB, 256>>>((const int*)ei, N);
    hist_prep_kernel<<<EB + 512, 256>>>(ei, E, N, EB, W1l, W1r, W2l, W2r);
    scan_pass1<<<NB, 256>>>(N);
    scan_pass23<<<NB, 256>>>(NB, N);
    fill_kernel<<<EB, 256>>>(ei, E, N);
    agg1_kernel<<<(N * 32 + 255) / 256, 256>>>(x, N);
    {
        dim3 grid((N + 127) / 128, 2);
        mma_gemm_kernel<1><<<grid, 256, GEMM_SMEM>>>(b1l, N);
    }
    {
        dim3 grid((N + 127) / 128, 2);
        mma_gemm_kernel<2><<<grid, 256, GEMM_SMEM>>>(b2l, N);
    }
    agg2_kernel<<<(N * 32 + 255) / 256, 256>>>(out, N);
}

// round 10
// speedup vs baseline: 7.6888x; 1.0292x over previous
#include <cuda_runtime.h>
#include <cuda_bf16.h>
#include <cuda_fp16.h>
#include <cstdint>

#define MAX_N 50000
#define MAX_E 800000
#define IN_CH 128
#define HID_CH 256
#define OUT_CH 128

// ---------------------------------------------------------------------------
// Device scratch (allocation-free rule)
// ---------------------------------------------------------------------------
__device__ __align__(16) __half g_a1h[(size_t)MAX_N * 256];   // layer-1 A hi
__device__ __align__(16) __half g_a1l[(size_t)MAX_N * 256];   // layer-1 A lo
__device__ __align__(16) __half g_a2h[(size_t)MAX_N * 256];
__device__ __align__(16) __half g_a2l[(size_t)MAX_N * 256];
__device__ __align__(16) __half g_w1[256 * 256];              // composite W fp16
__device__ __align__(16) __half g_w2[256 * 256];
__device__ __align__(16) __half g_x16[(size_t)MAX_N * 128];   // x, fp16 hi (gather copy)
__device__ __align__(16) __half g_t16[(size_t)MAX_N * 128];   // layer-2 t half, fp16
__device__ float g_r[(size_t)MAX_N * 128];                    // layer-2 r half, fp32
__device__ int g_cnt[MAX_N];
__device__ int g_fill[MAX_N];
__device__ int g_rowptr[MAX_N + 1];
__device__ int g_colidx[MAX_E];
__device__ int g_bsum[256];
__device__ int g_is64;

// ---------------------------------------------------------------------------
// Helpers
// ---------------------------------------------------------------------------
__device__ __forceinline__ uint32_t smem_to_u32(const void* p) {
    uint32_t a;
    asm("{ .reg .u64 t; cvta.to.shared.u64 t, %1; cvt.u32.u64 %0, t; }"
        : "=r"(a) : "l"(p));
    return a;
}

__device__ __forceinline__ void ldsm_x4(uint32_t* r, uint32_t addr) {
    asm volatile("ldmatrix.sync.aligned.m8n8.x4.shared.b16 {%0,%1,%2,%3}, [%4];"
        : "=r"(r[0]), "=r"(r[1]), "=r"(r[2]), "=r"(r[3]) : "r"(addr));
}

__device__ __forceinline__ void mma16816(float* d, const uint32_t* a,
                                          const uint32_t* b) {
    asm volatile(
        "mma.sync.aligned.m16n8k16.row.col.f32.f16.f16.f32 "
        "{%0,%1,%2,%3}, {%4,%5,%6,%7}, {%8,%9}, {%0,%1,%2,%3};"
        : "+f"(d[0]), "+f"(d[1]), "+f"(d[2]), "+f"(d[3])
        : "r"(a[0]), "r"(a[1]), "r"(a[2]), "r"(a[3]), "r"(b[0]), "r"(b[1]));
}

__device__ __forceinline__ void cp16(uint32_t dst, const void* src, bool pred) {
    int sz = pred ? 16 : 0;
    asm volatile("cp.async.cg.shared.global [%0], [%1], 16, %2;"
        :: "r"(dst), "l"(src), "r"(sz));
}

__device__ __forceinline__ void split2h(float v0, float v1,
                                        __half2& hp, __half2& lp) {
    __half h0 = __float2half_rn(v0);
    __half h1 = __float2half_rn(v1);
    hp = __halves2half2(h0, h1);
    lp = __halves2half2(__float2half_rn(v0 - __half2float(h0)),
                        __float2half_rn(v1 - __half2float(h1)));
}

__device__ __forceinline__ void load_edge(const void* ei, int e, int E,
                                          int& src, int& dst) {
    if (g_is64) {
        src = (int)reinterpret_cast<const long long*>(ei)[e];
        dst = (int)reinterpret_cast<const long long*>(ei)[(size_t)E + e];
    } else {
        src = reinterpret_cast<const int*>(ei)[e];
        dst = reinterpret_cast<const int*>(ei)[(size_t)E + e];
    }
}

// ---------------------------------------------------------------------------
// Kernel 0: zero counters + edge dtype sniff (block 0)
// ---------------------------------------------------------------------------
__global__ void zero_sniff_kernel(const int* __restrict__ ei32, int N) {
    __shared__ int red[128];
    int b = blockIdx.x, t = threadIdx.x;
    int i = b * 256 + t;
    if (i < N) { g_cnt[i] = 0; g_fill[i] = 0; }
    if (b == 0) {
        if (t < 128) red[t] = ei32[2 * t + 1];
        __syncthreads();
        for (int s = 64; s > 0; s >>= 1) {
            if (t < s && t < 128) red[t] |= red[t + s];
            __syncthreads();
        }
        if (t == 0) g_is64 = (red[0] == 0) ? 1 : 0;
    }
}

// ---------------------------------------------------------------------------
// Kernel 1: histogram (blocks [0,EB)) + fp16 weight prep (blocks [EB,EB+512))
//           + x -> fp16 gather copy (blocks [EB+512, EB+512+XB))
// ---------------------------------------------------------------------------
__global__ void hist_prep_kernel(const void* __restrict__ ei, int E, int N, int EB,
                                 const float* __restrict__ W1l,
                                 const float* __restrict__ W1r,
                                 const float* __restrict__ W2l,
                                 const float* __restrict__ W2r,
                                 const float* __restrict__ x) {
    int b = blockIdx.x, t = threadIdx.x;
    if (b < EB) {
        int e = b * 256 + t;
        if (e >= E) return;
        int src, dst;
        load_edge(ei, e, E, src, dst);
        if ((unsigned)dst < (unsigned)N) atomicAdd(&g_cnt[dst], 1);
    } else if (b < EB + 512) {
        int wb = b - EB;
        int idx = (wb & 255) * 256 + t;
        int o = idx >> 8, k = idx & 255;
        if (wb < 256) {
            float v = (k < 128) ? W1r[o * 128 + k] : W1l[o * 128 + (k - 128)];
            g_w1[idx] = __float2half_rn(v);
        } else {
            float v = (o < 128) ? W2l[o * 256 + k] : W2r[(o - 128) * 256 + k];
            g_w2[idx] = __float2half_rn(v);
        }
    } else {
        // x conversion: each thread converts one float2 -> half2
        int idx = (b - EB - 512) * 256 + t;          // over N*64 float2s
        if (idx >= N * 64) return;
        float2 v = reinterpret_cast<const float2*>(x)[idx];
        reinterpret_cast<__half2*>(g_x16)[idx] = __float22half2_rn(v);
    }
}

// ---------------------------------------------------------------------------
// Scan: pass1 (block sums) + fused pass23
// ---------------------------------------------------------------------------
__global__ void scan_pass1(int N) {
    __shared__ int sh[256];
    int t = threadIdx.x, i = blockIdx.x * 256 + t;
    sh[t] = (i < N) ? g_cnt[i] : 0;
    __syncthreads();
    for (int s = 128; s > 0; s >>= 1) {
        if (t < s) sh[t] += sh[t + s];
        __syncthreads();
    }
    if (t == 0) g_bsum[blockIdx.x] = sh[0];
}

__global__ void scan_pass23(int NB, int N) {
    __shared__ int sh[256];
    __shared__ int base_sh;
    int t = threadIdx.x, bid = blockIdx.x;
    sh[t] = (t < bid) ? g_bsum[t] : 0;
    __syncthreads();
    for (int s = 128; s > 0; s >>= 1) {
        if (t < s) sh[t] += sh[t + s];
        __syncthreads();
    }
    if (t == 0) base_sh = sh[0];
    __syncthreads();
    int base = base_sh;
    int i = bid * 256 + t;
    int c = (i < N) ? g_cnt[i] : 0;
    __syncthreads();
    sh[t] = c;
    __syncthreads();
    for (int off = 1; off < 256; off <<= 1) {
        int x2 = (t >= off) ? sh[t - off] : 0;
        __syncthreads();
        sh[t] += x2;
        __syncthreads();
    }
    if (i < N) g_rowptr[i] = base + sh[t] - c;
    if (bid == NB - 1 && t == 255) g_rowptr[N] = base + sh[255];
}

__global__ void fill_kernel(const void* __restrict__ ei, int E, int N) {
    int e = blockIdx.x * blockDim.x + threadIdx.x;
    if (e >= E) return;
    int src, dst;
    load_edge(ei, e, E, src, dst);
    if ((unsigned)dst >= (unsigned)N || (unsigned)src >= (unsigned)N) return;
    int slot = g_rowptr[dst] + atomicAdd(&g_fill[dst], 1);
    g_colidx[slot] = src;
}

// ---------------------------------------------------------------------------
// Layer-1 aggregation (fp16 gathers from g_x16) + own-row conversion:
//   cols 0..127   <- split(x[n])  (fp32 source, sequential)
//   cols 128..255 <- split(mean_{s} x16[s])
// One warp per node; lane covers 4 channels (uint2 = 4 halves).
// ---------------------------------------------------------------------------
__global__ void agg1_kernel(const float* __restrict__ x, int N) {
    int w = (blockIdx.x * blockDim.x + threadIdx.x) >> 5;
    int l = threadIdx.x & 31;
    if (w >= N) return;
    int beg = g_rowptr[w], end = g_rowptr[w + 1];
    const uint2* X2 = reinterpret_cast<const uint2*>(g_x16);   // 4 halves per uint2
    float2 a0 = make_float2(0.f, 0.f), a1 = make_float2(0.f, 0.f);
    for (int i = beg; i < end; i++) {
        int s0 = g_colidx[i];
        uint2 v = X2[(size_t)s0 * 32 + l];
        float2 f0 = __half22float2(*reinterpret_cast<__half2*>(&v.x));
        float2 f1 = __half22float2(*reinterpret_cast<__half2*>(&v.y));
        a0.x += f0.x; a0.y += f0.y; a1.x += f1.x; a1.y += f1.y;
    }
    float inv = 1.f / fmaxf((float)(end - beg), 1.f);
    a0.x *= inv; a0.y *= inv; a1.x *= inv; a1.y *= inv;
    __half2 hp0, lp0, hp1, lp1;
    split2h(a0.x, a0.y, hp0, lp0);
    split2h(a1.x, a1.y, hp1, lp1);
    size_t base = (size_t)w * 256 + 128 + l * 4;
    *reinterpret_cast<__half2*>(g_a1h + base)     = hp0;
    *reinterpret_cast<__half2*>(g_a1h + base + 2) = hp1;
    *reinterpret_cast<__half2*>(g_a1l + base)     = lp0;
    *reinterpret_cast<__half2*>(g_a1l + base + 2) = lp1;
    // own row from fp32 x (full precision)
    float4 xr = reinterpret_cast<const float4*>(x)[(size_t)w * 32 + l];
    split2h(xr.x, xr.y, hp0, lp0);
    split2h(xr.z, xr.w, hp1, lp1);
    base = (size_t)w * 256 + l * 4;
    *reinterpret_cast<__half2*>(g_a1h + base)     = hp0;
    *reinterpret_cast<__half2*>(g_a1h + base + 2) = hp1;
    *reinterpret_cast<__half2*>(g_a1l + base)     = lp0;
    *reinterpret_cast<__half2*>(g_a1l + base + 2) = lp1;
}

// ---------------------------------------------------------------------------
// Layer-2 aggregation (fp16 gathers from g_t16) + combine with fp32 r:
//   out[n][c] = mean_{s in N(n)} t16[s][c] + r[n][c]
// ---------------------------------------------------------------------------
__global__ void agg2_kernel(float* __restrict__ out, int N) {
    int w = (blockIdx.x * blockDim.x + threadIdx.x) >> 5;
    int l = threadIdx.x & 31;
    if (w >= N) return;
    int beg = g_rowptr[w], end = g_rowptr[w + 1];
    const uint2* T2 = reinterpret_cast<const uint2*>(g_t16);
    float2 a0 = make_float2(0.f, 0.f), a1 = make_float2(0.f, 0.f);
    for (int i = beg; i < end; i++) {
        int s0 = g_colidx[i];
        uint2 v = T2[(size_t)s0 * 32 + l];
        float2 f0 = __half22float2(*reinterpret_cast<__half2*>(&v.x));
        float2 f1 = __half22float2(*reinterpret_cast<__half2*>(&v.y));
        a0.x += f0.x; a0.y += f0.y; a1.x += f1.x; a1.y += f1.y;
    }
    float inv = 1.f / fmaxf((float)(end - beg), 1.f);
    float4 r = reinterpret_cast<const float4*>(g_r)[(size_t)w * 32 + l];
    reinterpret_cast<float4*>(out)[(size_t)w * 32 + l] =
        make_float4(a0.x * inv + r.x, a0.y * inv + r.y,
                    a1.x * inv + r.z, a1.y * inv + r.w);
}

// ---------------------------------------------------------------------------
// HMMA GEMM, fp16, A hi/lo split (2 passes), B single fp16 (proven R9).
// LAYER 1: epi relu(+b1l) -> fp16 split g_a2*
// LAYER 2: epi cols<128 -> fp16 g_t16; cols>=128 -> fp32 g_r (+b2l)
// ---------------------------------------------------------------------------
#define SPAD 40
#define TILE_B (128 * SPAD * 2)
#define GEMM_SMEM (6 * TILE_B)

template <int LAYER>
__global__ void __launch_bounds__(256)
mma_gemm_kernel(const float* __restrict__ bias, int N) {
    extern __shared__ char dsmem[];
    const uint32_t sbase = smem_to_u32(dsmem);

    const int tid  = threadIdx.x;
    const int lane = tid & 31;
    const int wid  = tid >> 5;
    const int wm   = (wid & 1) * 64;
    const int wn   = (wid >> 1) * 32;
    const int n0   = blockIdx.x * 128;
    const int o0   = blockIdx.y * 128;

    const __half* __restrict__ AH = (LAYER == 1) ? g_a1h : g_a2h;
    const __half* __restrict__ AL = (LAYER == 1) ? g_a1l : g_a2l;
    const __half* __restrict__ W  = (LAYER == 1) ? g_w1 : g_w2;

    #define TILE_AT(buf, slot) (sbase + (uint32_t)(((buf) * 3 + (slot)) * TILE_B))

    const int lrow = tid >> 2;
    const int lcol = (tid & 3) * 8;

    const int arow = wm + (lane & 15);
    const int acol = (lane >> 4) * 8;
    const int brow = wn + (lane & 7) + ((lane >> 4) << 3);
    const int bcol = ((lane >> 3) & 1) * 8;

    float acc[4][4][4];
#pragma unroll
    for (int mi = 0; mi < 4; mi++)
#pragma unroll
        for (int ni = 0; ni < 4; ni++)
#pragma unroll
            for (int q = 0; q < 4; q++) acc[mi][ni][q] = 0.f;

    auto load_chunk = [&](int kc, int buf) {
#pragma unroll
        for (int i = 0; i < 2; i++) {
            int row = lrow + i * 64;
            int n = n0 + row;
            bool ok = n < N;
            size_t ga = (size_t)(ok ? n : 0) * 256 + kc + lcol;
            size_t gw = (size_t)(o0 + row) * 256 + kc + lcol;
            uint32_t so = (uint32_t)((row * SPAD + lcol) * 2);
            cp16(TILE_AT(buf, 0) + so, AH + ga, ok);
            cp16(TILE_AT(buf, 1) + so, AL + ga, ok);
            cp16(TILE_AT(buf, 2) + so, W + gw, true);
        }
        asm volatile("cp.async.commit_group;");
    };

    load_chunk(0, 0);

    for (int c = 0; c < 8; c++) {
        const int cur = c & 1;
        if (c < 7) {
            load_chunk((c + 1) * 32, 1 - cur);
            asm volatile("cp.async.wait_group 1;");
        } else {
            asm volatile("cp.async.wait_group 0;");
        }
        __syncthreads();

#pragma unroll
        for (int t = 0; t < 2; t++) {
            const uint32_t uA = TILE_AT(cur, t);
            const uint32_t uB = TILE_AT(cur, 2);
#pragma unroll
            for (int ks = 0; ks < 2; ks++) {
                const int k0 = ks * 16;
                uint32_t a[4][4], b[4][2];
#pragma unroll
                for (int mi = 0; mi < 4; mi++)
                    ldsm_x4(a[mi],
                            uA + ((arow + mi * 16) * SPAD + k0 + acol) * 2);
#pragma unroll
                for (int nip = 0; nip < 2; nip++) {
                    uint32_t bb[4];
                    ldsm_x4(bb, uB + ((brow + nip * 16) * SPAD + k0 + bcol) * 2);
                    b[nip * 2][0]     = bb[0]; b[nip * 2][1]     = bb[1];
                    b[nip * 2 + 1][0] = bb[2]; b[nip * 2 + 1][1] = bb[3];
                }
#pragma unroll
                for (int mi = 0; mi < 4; mi++)
#pragma unroll
                    for (int ni = 0; ni < 4; ni++)
                        mma16816(acc[mi][ni], a[mi], b[ni]);
            }
        }
        __syncthreads();
    }

    const int erow = lane >> 2;
    const int ecol = (lane & 3) * 2;
#pragma unroll
    for (int mi = 0; mi < 4; mi++) {
#pragma unroll
        for (int half = 0; half < 2; half++) {
            int n = n0 + wm + mi * 16 + erow + half * 8;
            if (n >= N) continue;
#pragma unroll
            for (int ni = 0; ni < 4; ni++) {
                int col = o0 + wn + ni * 8 + ecol;
                float v0 = acc[mi][ni][half * 2 + 0];
                float v1 = acc[mi][ni][half * 2 + 1];
                if (LAYER == 1) {
                    v0 = fmaxf(v0 + bias[col],     0.f);
                    v1 = fmaxf(v1 + bias[col + 1], 0.f);
                    __half2 hp, lp;
                    split2h(v0, v1, hp, lp);
                    size_t off = (size_t)n * 256 + col;
                    *reinterpret_cast<__half2*>(g_a2h + off) = hp;
                    *reinterpret_cast<__half2*>(g_a2l + off) = lp;
                } else {
                    if (col < 128) {
                        // t half -> fp16 (gathered + mean-attenuated downstream)
                        *reinterpret_cast<__half2*>(g_t16 + (size_t)n * 128 + col) =
                            __halves2half2(__float2half_rn(v0), __float2half_rn(v1));
                    } else {
                        // r half -> fp32, + bias
                        v0 += bias[col - 128];
                        v1 += bias[col - 127];
                        *reinterpret_cast<float2*>(g_r + (size_t)n * 128 + (col - 128)) =
                            make_float2(v0, v1);
                    }
                }
            }
        }
    }
    #undef TILE_AT
}

// ---------------------------------------------------------------------------
// Launcher — kernel launches only; graph-capturable; no static state.
// ---------------------------------------------------------------------------
extern "C" void kernel_launch(void* const* d_in, const int* in_sizes, int n_in,
                              void* d_out, int out_size) {
    const float* x   = (const float*)d_in[0];
    const void*  ei  = d_in[1];
    const float* W1l = (const float*)d_in[2];
    const float* b1l = (const float*)d_in[3];
    const float* W1r = (const float*)d_in[4];
    const float* W2l = (const float*)d_in[5];
    const float* b2l = (const float*)d_in[6];
    const float* W2r = (const float*)d_in[7];
    float* out       = (float*)d_out;

    const int N  = in_sizes[0] / IN_CH;
    const int E  = in_sizes[1] / 2;
    const int NB = (N + 255) / 256;
    const int EB = (E + 255) / 256;
    const int XB = (N * 64 + 255) / 256;    // x-conversion blocks

    cudaFuncSetAttribute(mma_gemm_kernel<1>,
                         cudaFuncAttributeMaxDynamicSharedMemorySize, GEMM_SMEM);
    cudaFuncSetAttribute(mma_gemm_kernel<2>,
                         cudaFuncAttributeMaxDynamicSharedMemorySize, GEMM_SMEM);

    zero_sniff_kernel<<<NB, 256>>>((const int*)ei, N);
    hist_prep_kernel<<<EB + 512 + XB, 256>>>(ei, E, N, EB, W1l, W1r, W2l, W2r, x);
    scan_pass1<<<NB, 256>>>(N);
    scan_pass23<<<NB, 256>>>(NB, N);
    fill_kernel<<<EB, 256>>>(ei, E, N);
    agg1_kernel<<<(N * 32 + 255) / 256, 256>>>(x, N);
    {
        dim3 grid((N + 127) / 128, 2);
        mma_gemm_kernel<1><<<grid, 256, GEMM_SMEM>>>(b1l, N);
    }
    {
        dim3 grid((N + 127) / 128, 2);
        mma_gemm_kernel<2><<<grid, 256, GEMM_SMEM>>>(b2l, N);
    }
    agg2_kernel<<<(N * 32 + 255) / 256, 256>>>(out, N);
}

// round 11
// speedup vs baseline: 7.7601x; 1.0093x over previous
#include <cuda_runtime.h>
#include <cuda_bf16.h>
#include <cuda_fp16.h>
#include <cstdint>

#define MAX_N 50000
#define MAX_E 800000
#define IN_CH 128
#define HID_CH 256
#define OUT_CH 128

// ---------------------------------------------------------------------------
// Device scratch (allocation-free rule)
// ---------------------------------------------------------------------------
__device__ __align__(16) __half g_a1h[(size_t)MAX_N * 256];   // layer-1 A hi
__device__ __align__(16) __half g_a1l[(size_t)MAX_N * 256];   // layer-1 A lo
__device__ __align__(16) __half g_a2h[(size_t)MAX_N * 256];
__device__ __align__(16) __half g_a2l[(size_t)MAX_N * 256];
__device__ __align__(16) __half g_w1[256 * 256];              // composite W fp16
__device__ __align__(16) __half g_w2[256 * 256];
__device__ __align__(16) __half g_x16[(size_t)MAX_N * 128];   // x, fp16 (gather copy)
__device__ __align__(16) __half g_t16[(size_t)MAX_N * 128];   // layer-2 t half, fp16
__device__ float g_r[(size_t)MAX_N * 128];                    // layer-2 r half, fp32
__device__ int g_cnt[MAX_N];
__device__ int g_fill[MAX_N];
__device__ int g_rowptr[MAX_N + 1];
__device__ int g_colidx[MAX_E];
__device__ int g_bsum[256];
__device__ int g_is64;

// ---------------------------------------------------------------------------
// Helpers
// ---------------------------------------------------------------------------
__device__ __forceinline__ uint32_t smem_to_u32(const void* p) {
    uint32_t a;
    asm("{ .reg .u64 t; cvta.to.shared.u64 t, %1; cvt.u32.u64 %0, t; }"
        : "=r"(a) : "l"(p));
    return a;
}

__device__ __forceinline__ void ldsm_x4(uint32_t* r, uint32_t addr) {
    asm volatile("ldmatrix.sync.aligned.m8n8.x4.shared.b16 {%0,%1,%2,%3}, [%4];"
        : "=r"(r[0]), "=r"(r[1]), "=r"(r[2]), "=r"(r[3]) : "r"(addr));
}

__device__ __forceinline__ void mma16816(float* d, const uint32_t* a,
                                          const uint32_t* b) {
    asm volatile(
        "mma.sync.aligned.m16n8k16.row.col.f32.f16.f16.f32 "
        "{%0,%1,%2,%3}, {%4,%5,%6,%7}, {%8,%9}, {%0,%1,%2,%3};"
        : "+f"(d[0]), "+f"(d[1]), "+f"(d[2]), "+f"(d[3])
        : "r"(a[0]), "r"(a[1]), "r"(a[2]), "r"(a[3]), "r"(b[0]), "r"(b[1]));
}

__device__ __forceinline__ void cp16(uint32_t dst, const void* src, bool pred) {
    int sz = pred ? 16 : 0;
    asm volatile("cp.async.cg.shared.global [%0], [%1], 16, %2;"
        :: "r"(dst), "l"(src), "r"(sz));
}

__device__ __forceinline__ void split2h(float v0, float v1,
                                        __half2& hp, __half2& lp) {
    __half h0 = __float2half_rn(v0);
    __half h1 = __float2half_rn(v1);
    hp = __halves2half2(h0, h1);
    lp = __halves2half2(__float2half_rn(v0 - __half2float(h0)),
                        __float2half_rn(v1 - __half2float(h1)));
}

__device__ __forceinline__ void load_edge(const void* ei, int e, int E,
                                          int& src, int& dst) {
    if (g_is64) {
        src = (int)reinterpret_cast<const long long*>(ei)[e];
        dst = (int)reinterpret_cast<const long long*>(ei)[(size_t)E + e];
    } else {
        src = reinterpret_cast<const int*>(ei)[e];
        dst = reinterpret_cast<const int*>(ei)[(size_t)E + e];
    }
}

// ---------------------------------------------------------------------------
// Kernel 0: zero counters + edge dtype sniff (block 0)
// ---------------------------------------------------------------------------
__global__ void zero_sniff_kernel(const int* __restrict__ ei32, int N) {
    __shared__ int red[128];
    int b = blockIdx.x, t = threadIdx.x;
    int i = b * 256 + t;
    if (i < N) { g_cnt[i] = 0; g_fill[i] = 0; }
    if (b == 0) {
        if (t < 128) red[t] = ei32[2 * t + 1];
        __syncthreads();
        for (int s = 64; s > 0; s >>= 1) {
            if (t < s && t < 128) red[t] |= red[t + s];
            __syncthreads();
        }
        if (t == 0) g_is64 = (red[0] == 0) ? 1 : 0;
    }
}

// ---------------------------------------------------------------------------
// Kernel 1: histogram + fp16 weight prep + x->fp16 copy (co-scheduled)
// ---------------------------------------------------------------------------
__global__ void hist_prep_kernel(const void* __restrict__ ei, int E, int N, int EB,
                                 const float* __restrict__ W1l,
                                 const float* __restrict__ W1r,
                                 const float* __restrict__ W2l,
                                 const float* __restrict__ W2r,
                                 const float* __restrict__ x) {
    int b = blockIdx.x, t = threadIdx.x;
    if (b < EB) {
        int e = b * 256 + t;
        if (e >= E) return;
        int src, dst;
        load_edge(ei, e, E, src, dst);
        if ((unsigned)dst < (unsigned)N) atomicAdd(&g_cnt[dst], 1);
    } else if (b < EB + 512) {
        int wb = b - EB;
        int idx = (wb & 255) * 256 + t;
        int o = idx >> 8, k = idx & 255;
        if (wb < 256) {
            float v = (k < 128) ? W1r[o * 128 + k] : W1l[o * 128 + (k - 128)];
            g_w1[idx] = __float2half_rn(v);
        } else {
            float v = (o < 128) ? W2l[o * 256 + k] : W2r[(o - 128) * 256 + k];
            g_w2[idx] = __float2half_rn(v);
        }
    } else {
        int idx = (b - EB - 512) * 256 + t;          // over N*64 float2s
        if (idx >= N * 64) return;
        float2 v = reinterpret_cast<const float2*>(x)[idx];
        reinterpret_cast<__half2*>(g_x16)[idx] = __float22half2_rn(v);
    }
}

// ---------------------------------------------------------------------------
// Scan: pass1 (block sums) + fused pass23
// ---------------------------------------------------------------------------
__global__ void scan_pass1(int N) {
    __shared__ int sh[256];
    int t = threadIdx.x, i = blockIdx.x * 256 + t;
    sh[t] = (i < N) ? g_cnt[i] : 0;
    __syncthreads();
    for (int s = 128; s > 0; s >>= 1) {
        if (t < s) sh[t] += sh[t + s];
        __syncthreads();
    }
    if (t == 0) g_bsum[blockIdx.x] = sh[0];
}

__global__ void scan_pass23(int NB, int N) {
    __shared__ int sh[256];
    __shared__ int base_sh;
    int t = threadIdx.x, bid = blockIdx.x;
    sh[t] = (t < bid) ? g_bsum[t] : 0;
    __syncthreads();
    for (int s = 128; s > 0; s >>= 1) {
        if (t < s) sh[t] += sh[t + s];
        __syncthreads();
    }
    if (t == 0) base_sh = sh[0];
    __syncthreads();
    int base = base_sh;
    int i = bid * 256 + t;
    int c = (i < N) ? g_cnt[i] : 0;
    __syncthreads();
    sh[t] = c;
    __syncthreads();
    for (int off = 1; off < 256; off <<= 1) {
        int x2 = (t >= off) ? sh[t - off] : 0;
        __syncthreads();
        sh[t] += x2;
        __syncthreads();
    }
    if (i < N) g_rowptr[i] = base + sh[t] - c;
    if (bid == NB - 1 && t == 255) g_rowptr[N] = base + sh[255];
}

__global__ void fill_kernel(const void* __restrict__ ei, int E, int N) {
    int e = blockIdx.x * blockDim.x + threadIdx.x;
    if (e >= E) return;
    int src, dst;
    load_edge(ei, e, E, src, dst);
    if ((unsigned)dst >= (unsigned)N || (unsigned)src >= (unsigned)N) return;
    int slot = g_rowptr[dst] + atomicAdd(&g_fill[dst], 1);
    g_colidx[slot] = src;
}

// ---------------------------------------------------------------------------
// Layer-1 aggregation, unroll-8 (MLP restore — R10 post-mortem):
//   cols 0..127   <- split(x[n]) ;  cols 128..255 <- split(mean_{s} x16[s])
// One warp per node; lane covers 4 channels (uint2 = 4 halves).
// ---------------------------------------------------------------------------
__global__ void agg1_kernel(const float* __restrict__ x, int N) {
    int w = (blockIdx.x * blockDim.x + threadIdx.x) >> 5;
    int l = threadIdx.x & 31;
    if (w >= N) return;
    int beg = g_rowptr[w], end = g_rowptr[w + 1];
    const uint2* X2 = reinterpret_cast<const uint2*>(g_x16);
    float2 a0 = make_float2(0.f, 0.f), a1 = make_float2(0.f, 0.f);
    int i = beg;
    for (; i + 7 < end; i += 8) {
        int s[8];
#pragma unroll
        for (int u = 0; u < 8; u++) s[u] = g_colidx[i + u];
        uint2 v[8];
#pragma unroll
        for (int u = 0; u < 8; u++) v[u] = X2[(size_t)s[u] * 32 + l];
#pragma unroll
        for (int u = 0; u < 8; u++) {
            float2 f0 = __half22float2(*reinterpret_cast<__half2*>(&v[u].x));
            float2 f1 = __half22float2(*reinterpret_cast<__half2*>(&v[u].y));
            a0.x += f0.x; a0.y += f0.y; a1.x += f1.x; a1.y += f1.y;
        }
    }
    for (; i < end; i++) {
        uint2 v = X2[(size_t)g_colidx[i] * 32 + l];
        float2 f0 = __half22float2(*reinterpret_cast<__half2*>(&v.x));
        float2 f1 = __half22float2(*reinterpret_cast<__half2*>(&v.y));
        a0.x += f0.x; a0.y += f0.y; a1.x += f1.x; a1.y += f1.y;
    }
    float inv = 1.f / fmaxf((float)(end - beg), 1.f);
    a0.x *= inv; a0.y *= inv; a1.x *= inv; a1.y *= inv;
    __half2 hp0, lp0, hp1, lp1;
    split2h(a0.x, a0.y, hp0, lp0);
    split2h(a1.x, a1.y, hp1, lp1);
    size_t base = (size_t)w * 256 + 128 + l * 4;
    *reinterpret_cast<__half2*>(g_a1h + base)     = hp0;
    *reinterpret_cast<__half2*>(g_a1h + base + 2) = hp1;
    *reinterpret_cast<__half2*>(g_a1l + base)     = lp0;
    *reinterpret_cast<__half2*>(g_a1l + base + 2) = lp1;
    float4 xr = reinterpret_cast<const float4*>(x)[(size_t)w * 32 + l];
    split2h(xr.x, xr.y, hp0, lp0);
    split2h(xr.z, xr.w, hp1, lp1);
    base = (size_t)w * 256 + l * 4;
    *reinterpret_cast<__half2*>(g_a1h + base)     = hp0;
    *reinterpret_cast<__half2*>(g_a1h + base + 2) = hp1;
    *reinterpret_cast<__half2*>(g_a1l + base)     = lp0;
    *reinterpret_cast<__half2*>(g_a1l + base + 2) = lp1;
}

// ---------------------------------------------------------------------------
// Layer-2 aggregation, unroll-8:
//   out[n][c] = mean_{s in N(n)} t16[s][c] + r[n][c]
// ---------------------------------------------------------------------------
__global__ void agg2_kernel(float* __restrict__ out, int N) {
    int w = (blockIdx.x * blockDim.x + threadIdx.x) >> 5;
    int l = threadIdx.x & 31;
    if (w >= N) return;
    int beg = g_rowptr[w], end = g_rowptr[w + 1];
    const uint2* T2 = reinterpret_cast<const uint2*>(g_t16);
    float2 a0 = make_float2(0.f, 0.f), a1 = make_float2(0.f, 0.f);
    int i = beg;
    for (; i + 7 < end; i += 8) {
        int s[8];
#pragma unroll
        for (int u = 0; u < 8; u++) s[u] = g_colidx[i + u];
        uint2 v[8];
#pragma unroll
        for (int u = 0; u < 8; u++) v[u] = T2[(size_t)s[u] * 32 + l];
#pragma unroll
        for (int u = 0; u < 8; u++) {
            float2 f0 = __half22float2(*reinterpret_cast<__half2*>(&v[u].x));
            float2 f1 = __half22float2(*reinterpret_cast<__half2*>(&v[u].y));
            a0.x += f0.x; a0.y += f0.y; a1.x += f1.x; a1.y += f1.y;
        }
    }
    for (; i < end; i++) {
        uint2 v = T2[(size_t)g_colidx[i] * 32 + l];
        float2 f0 = __half22float2(*reinterpret_cast<__half2*>(&v.x));
        float2 f1 = __half22float2(*reinterpret_cast<__half2*>(&v.y));
        a0.x += f0.x; a0.y += f0.y; a1.x += f1.x; a1.y += f1.y;
    }
    float inv = 1.f / fmaxf((float)(end - beg), 1.f);
    float4 r = reinterpret_cast<const float4*>(g_r)[(size_t)w * 32 + l];
    reinterpret_cast<float4*>(out)[(size_t)w * 32 + l] =
        make_float4(a0.x * inv + r.x, a0.y * inv + r.y,
                    a1.x * inv + r.z, a1.y * inv + r.w);
}

// ---------------------------------------------------------------------------
// HMMA GEMM, fp16, A hi/lo split (2 passes), B single fp16 (proven R9/R10).
// LAYER 1: epi relu(+b1l) -> fp16 split g_a2*
// LAYER 2: epi cols<128 -> fp16 g_t16; cols>=128 -> fp32 g_r (+b2l)
// ---------------------------------------------------------------------------
#define SPAD 40
#define TILE_B (128 * SPAD * 2)
#define GEMM_SMEM (6 * TILE_B)

template <int LAYER>
__global__ void __launch_bounds__(256)
mma_gemm_kernel(const float* __restrict__ bias, int N) {
    extern __shared__ char dsmem[];
    const uint32_t sbase = smem_to_u32(dsmem);

    const int tid  = threadIdx.x;
    const int lane = tid & 31;
    const int wid  = tid >> 5;
    const int wm   = (wid & 1) * 64;
    const int wn   = (wid >> 1) * 32;
    const int n0   = blockIdx.x * 128;
    const int o0   = blockIdx.y * 128;

    const __half* __restrict__ AH = (LAYER == 1) ? g_a1h : g_a2h;
    const __half* __restrict__ AL = (LAYER == 1) ? g_a1l : g_a2l;
    const __half* __restrict__ W  = (LAYER == 1) ? g_w1 : g_w2;

    #define TILE_AT(buf, slot) (sbase + (uint32_t)(((buf) * 3 + (slot)) * TILE_B))

    const int lrow = tid >> 2;
    const int lcol = (tid & 3) * 8;

    const int arow = wm + (lane & 15);
    const int acol = (lane >> 4) * 8;
    const int brow = wn + (lane & 7) + ((lane >> 4) << 3);
    const int bcol = ((lane >> 3) & 1) * 8;

    float acc[4][4][4];
#pragma unroll
    for (int mi = 0; mi < 4; mi++)
#pragma unroll
        for (int ni = 0; ni < 4; ni++)
#pragma unroll
            for (int q = 0; q < 4; q++) acc[mi][ni][q] = 0.f;

    auto load_chunk = [&](int kc, int buf) {
#pragma unroll
        for (int i = 0; i < 2; i++) {
            int row = lrow + i * 64;
            int n = n0 + row;
            bool ok = n < N;
            size_t ga = (size_t)(ok ? n : 0) * 256 + kc + lcol;
            size_t gw = (size_t)(o0 + row) * 256 + kc + lcol;
            uint32_t so = (uint32_t)((row * SPAD + lcol) * 2);
            cp16(TILE_AT(buf, 0) + so, AH + ga, ok);
            cp16(TILE_AT(buf, 1) + so, AL + ga, ok);
            cp16(TILE_AT(buf, 2) + so, W + gw, true);
        }
        asm volatile("cp.async.commit_group;");
    };

    load_chunk(0, 0);

    for (int c = 0; c < 8; c++) {
        const int cur = c & 1;
        if (c < 7) {
            load_chunk((c + 1) * 32, 1 - cur);
            asm volatile("cp.async.wait_group 1;");
        } else {
            asm volatile("cp.async.wait_group 0;");
        }
        __syncthreads();

#pragma unroll
        for (int t = 0; t < 2; t++) {
            const uint32_t uA = TILE_AT(cur, t);
            const uint32_t uB = TILE_AT(cur, 2);
#pragma unroll
            for (int ks = 0; ks < 2; ks++) {
                const int k0 = ks * 16;
                uint32_t a[4][4], b[4][2];
#pragma unroll
                for (int mi = 0; mi < 4; mi++)
                    ldsm_x4(a[mi],
                            uA + ((arow + mi * 16) * SPAD + k0 + acol) * 2);
#pragma unroll
                for (int nip = 0; nip < 2; nip++) {
                    uint32_t bb[4];
                    ldsm_x4(bb, uB + ((brow + nip * 16) * SPAD + k0 + bcol) * 2);
                    b[nip * 2][0]     = bb[0]; b[nip * 2][1]     = bb[1];
                    b[nip * 2 + 1][0] = bb[2]; b[nip * 2 + 1][1] = bb[3];
                }
#pragma unroll
                for (int mi = 0; mi < 4; mi++)
#pragma unroll
                    for (int ni = 0; ni < 4; ni++)
                        mma16816(acc[mi][ni], a[mi], b[ni]);
            }
        }
        __syncthreads();
    }

    const int erow = lane >> 2;
    const int ecol = (lane & 3) * 2;
#pragma unroll
    for (int mi = 0; mi < 4; mi++) {
#pragma unroll
        for (int half = 0; half < 2; half++) {
            int n = n0 + wm + mi * 16 + erow + half * 8;
            if (n >= N) continue;
#pragma unroll
            for (int ni = 0; ni < 4; ni++) {
                int col = o0 + wn + ni * 8 + ecol;
                float v0 = acc[mi][ni][half * 2 + 0];
                float v1 = acc[mi][ni][half * 2 + 1];
                if (LAYER == 1) {
                    v0 = fmaxf(v0 + bias[col],     0.f);
                    v1 = fmaxf(v1 + bias[col + 1], 0.f);
                    __half2 hp, lp;
                    split2h(v0, v1, hp, lp);
                    size_t off = (size_t)n * 256 + col;
                    *reinterpret_cast<__half2*>(g_a2h + off) = hp;
                    *reinterpret_cast<__half2*>(g_a2l + off) = lp;
                } else {
                    if (col < 128) {
                        *reinterpret_cast<__half2*>(g_t16 + (size_t)n * 128 + col) =
                            __halves2half2(__float2half_rn(v0), __float2half_rn(v1));
                    } else {
                        v0 += bias[col - 128];
                        v1 += bias[col - 127];
                        *reinterpret_cast<float2*>(g_r + (size_t)n * 128 + (col - 128)) =
                            make_float2(v0, v1);
                    }
                }
            }
        }
    }
    #undef TILE_AT
}

// ---------------------------------------------------------------------------
// Launcher — kernel launches only; graph-capturable; no static state.
// ---------------------------------------------------------------------------
extern "C" void kernel_launch(void* const* d_in, const int* in_sizes, int n_in,
                              void* d_out, int out_size) {
    const float* x   = (const float*)d_in[0];
    const void*  ei  = d_in[1];
    const float* W1l = (const float*)d_in[2];
    const float* b1l = (const float*)d_in[3];
    const float* W1r = (const float*)d_in[4];
    const float* W2l = (const float*)d_in[5];
    const float* b2l = (const float*)d_in[6];
    const float* W2r = (const float*)d_in[7];
    float* out       = (float*)d_out;

    const int N  = in_sizes[0] / IN_CH;
    const int E  = in_sizes[1] / 2;
    const int NB = (N + 255) / 256;
    const int EB = (E + 255) / 256;
    const int XB = (N * 64 + 255) / 256;

    cudaFuncSetAttribute(mma_gemm_kernel<1>,
                         cudaFuncAttributeMaxDynamicSharedMemorySize, GEMM_SMEM);
    cudaFuncSetAttribute(mma_gemm_kernel<2>,
                         cudaFuncAttributeMaxDynamicSharedMemorySize, GEMM_SMEM);

    zero_sniff_kernel<<<NB, 256>>>((const int*)ei, N);
    hist_prep_kernel<<<EB + 512 + XB, 256>>>(ei, E, N, EB, W1l, W1r, W2l, W2r, x);
    scan_pass1<<<NB, 256>>>(N);
    scan_pass23<<<NB, 256>>>(NB, N);
    fill_kernel<<<EB, 256>>>(ei, E, N);
    agg1_kernel<<<(N * 32 + 255) / 256, 256>>>(x, N);
    {
        dim3 grid((N + 127) / 128, 2);
        mma_gemm_kernel<1><<<grid, 256, GEMM_SMEM>>>(b1l, N);
    }
    {
        dim3 grid((N + 127) / 128, 2);
        mma_gemm_kernel<2><<<grid, 256, GEMM_SMEM>>>(b2l, N);
    }
    agg2_kernel<<<(N * 32 + 255) / 256, 256>>>(out, N);
}

// round 12
// speedup vs baseline: 9.8930x; 1.2749x over previous
#include <cuda_runtime.h>
#include <cuda_bf16.h>
#include <cuda_fp16.h>
#include <cstdint>

#define MAX_N 50000
#define MAX_E 800000
#define IN_CH 128
#define HID_CH 256
#define OUT_CH 128

// ---------------------------------------------------------------------------
// Device scratch (allocation-free rule)
// ---------------------------------------------------------------------------
__device__ __align__(16) __half g_a1[(size_t)MAX_N * 256];    // layer-1 A, fp16
__device__ __align__(16) __half g_a2[(size_t)MAX_N * 256];    // layer-2 A, fp16
__device__ __align__(16) __half g_w1[256 * 256];              // composite W fp16
__device__ __align__(16) __half g_w2[256 * 256];
__device__ __align__(16) __half g_x16[(size_t)MAX_N * 128];   // x, fp16 (gather copy)
__device__ __align__(16) __half g_t16[(size_t)MAX_N * 128];   // layer-2 t half, fp16
__device__ float g_r[(size_t)MAX_N * 128];                    // layer-2 r half, fp32
__device__ int g_cnt[MAX_N];
__device__ int g_fill[MAX_N];
__device__ int g_rowptr[MAX_N + 1];
__device__ int g_colidx[MAX_E];
__device__ int g_bsum[256];
__device__ int g_is64;

// ---------------------------------------------------------------------------
// Helpers
// ---------------------------------------------------------------------------
__device__ __forceinline__ uint32_t smem_to_u32(const void* p) {
    uint32_t a;
    asm("{ .reg .u64 t; cvta.to.shared.u64 t, %1; cvt.u32.u64 %0, t; }"
        : "=r"(a) : "l"(p));
    return a;
}

__device__ __forceinline__ void ldsm_x4(uint32_t* r, uint32_t addr) {
    asm volatile("ldmatrix.sync.aligned.m8n8.x4.shared.b16 {%0,%1,%2,%3}, [%4];"
        : "=r"(r[0]), "=r"(r[1]), "=r"(r[2]), "=r"(r[3]) : "r"(addr));
}

__device__ __forceinline__ void mma16816(float* d, const uint32_t* a,
                                          const uint32_t* b) {
    asm volatile(
        "mma.sync.aligned.m16n8k16.row.col.f32.f16.f16.f32 "
        "{%0,%1,%2,%3}, {%4,%5,%6,%7}, {%8,%9}, {%0,%1,%2,%3};"
        : "+f"(d[0]), "+f"(d[1]), "+f"(d[2]), "+f"(d[3])
        : "r"(a[0]), "r"(a[1]), "r"(a[2]), "r"(a[3]), "r"(b[0]), "r"(b[1]));
}

__device__ __forceinline__ void cp16(uint32_t dst, const void* src, bool pred) {
    int sz = pred ? 16 : 0;
    asm volatile("cp.async.cg.shared.global [%0], [%1], 16, %2;"
        :: "r"(dst), "l"(src), "r"(sz));
}

__device__ __forceinline__ void load_edge(const void* ei, int e, int E,
                                          int& src, int& dst) {
    if (g_is64) {
        src = (int)reinterpret_cast<const long long*>(ei)[e];
        dst = (int)reinterpret_cast<const long long*>(ei)[(size_t)E + e];
    } else {
        src = reinterpret_cast<const int*>(ei)[e];
        dst = reinterpret_cast<const int*>(ei)[(size_t)E + e];
    }
}

// ---------------------------------------------------------------------------
// Kernel 0: zero counters + edge dtype sniff (block 0)
// ---------------------------------------------------------------------------
__global__ void zero_sniff_kernel(const int* __restrict__ ei32, int N) {
    __shared__ int red[128];
    int b = blockIdx.x, t = threadIdx.x;
    int i = b * 256 + t;
    if (i < N) { g_cnt[i] = 0; g_fill[i] = 0; }
    if (b == 0) {
        if (t < 128) red[t] = ei32[2 * t + 1];
        __syncthreads();
        for (int s = 64; s > 0; s >>= 1) {
            if (t < s && t < 128) red[t] |= red[t + s];
            __syncthreads();
        }
        if (t == 0) g_is64 = (red[0] == 0) ? 1 : 0;
    }
}

// ---------------------------------------------------------------------------
// Kernel 1: histogram + fp16 weight prep + x->fp16 copy (co-scheduled)
// ---------------------------------------------------------------------------
__global__ void hist_prep_kernel(const void* __restrict__ ei, int E, int N, int EB,
                                 const float* __restrict__ W1l,
                                 const float* __restrict__ W1r,
                                 const float* __restrict__ W2l,
                                 const float* __restrict__ W2r,
                                 const float* __restrict__ x) {
    int b = blockIdx.x, t = threadIdx.x;
    if (b < EB) {
        int e = b * 256 + t;
        if (e >= E) return;
        int src, dst;
        load_edge(ei, e, E, src, dst);
        if ((unsigned)dst < (unsigned)N) atomicAdd(&g_cnt[dst], 1);
    } else if (b < EB + 512) {
        int wb = b - EB;
        int idx = (wb & 255) * 256 + t;
        int o = idx >> 8, k = idx & 255;
        if (wb < 256) {
            float v = (k < 128) ? W1r[o * 128 + k] : W1l[o * 128 + (k - 128)];
            g_w1[idx] = __float2half_rn(v);
        } else {
            float v = (o < 128) ? W2l[o * 256 + k] : W2r[(o - 128) * 256 + k];
            g_w2[idx] = __float2half_rn(v);
        }
    } else {
        int idx = (b - EB - 512) * 256 + t;          // over N*64 float2s
        if (idx >= N * 64) return;
        float2 v = reinterpret_cast<const float2*>(x)[idx];
        reinterpret_cast<__half2*>(g_x16)[idx] = __float22half2_rn(v);
    }
}

// ---------------------------------------------------------------------------
// Scan: pass1 (block sums) + fused pass23
// ---------------------------------------------------------------------------
__global__ void scan_pass1(int N) {
    __shared__ int sh[256];
    int t = threadIdx.x, i = blockIdx.x * 256 + t;
    sh[t] = (i < N) ? g_cnt[i] : 0;
    __syncthreads();
    for (int s = 128; s > 0; s >>= 1) {
        if (t < s) sh[t] += sh[t + s];
        __syncthreads();
    }
    if (t == 0) g_bsum[blockIdx.x] = sh[0];
}

__global__ void scan_pass23(int NB, int N) {
    __shared__ int sh[256];
    __shared__ int base_sh;
    int t = threadIdx.x, bid = blockIdx.x;
    sh[t] = (t < bid) ? g_bsum[t] : 0;
    __syncthreads();
    for (int s = 128; s > 0; s >>= 1) {
        if (t < s) sh[t] += sh[t + s];
        __syncthreads();
    }
    if (t == 0) base_sh = sh[0];
    __syncthreads();
    int base = base_sh;
    int i = bid * 256 + t;
    int c = (i < N) ? g_cnt[i] : 0;
    __syncthreads();
    sh[t] = c;
    __syncthreads();
    for (int off = 1; off < 256; off <<= 1) {
        int x2 = (t >= off) ? sh[t - off] : 0;
        __syncthreads();
        sh[t] += x2;
        __syncthreads();
    }
    if (i < N) g_rowptr[i] = base + sh[t] - c;
    if (bid == NB - 1 && t == 255) g_rowptr[N] = base + sh[255];
}

__global__ void fill_kernel(const void* __restrict__ ei, int E, int N) {
    int e = blockIdx.x * blockDim.x + threadIdx.x;
    if (e >= E) return;
    int src, dst;
    load_edge(ei, e, E, src, dst);
    if ((unsigned)dst >= (unsigned)N || (unsigned)src >= (unsigned)N) return;
    int slot = g_rowptr[dst] + atomicAdd(&g_fill[dst], 1);
    g_colidx[slot] = src;
}

// ---------------------------------------------------------------------------
// Layer-1 aggregation (unroll-8) -> single fp16 A:
//   cols 0..127 <- fp16(x[n]);  cols 128..255 <- fp16(mean_{s} x16[s])
// ---------------------------------------------------------------------------
__global__ void agg1_kernel(const float* __restrict__ x, int N) {
    int w = (blockIdx.x * blockDim.x + threadIdx.x) >> 5;
    int l = threadIdx.x & 31;
    if (w >= N) return;
    int beg = g_rowptr[w], end = g_rowptr[w + 1];
    const uint2* X2 = reinterpret_cast<const uint2*>(g_x16);
    float2 a0 = make_float2(0.f, 0.f), a1 = make_float2(0.f, 0.f);
    int i = beg;
    for (; i + 7 < end; i += 8) {
        int s[8];
#pragma unroll
        for (int u = 0; u < 8; u++) s[u] = g_colidx[i + u];
        uint2 v[8];
#pragma unroll
        for (int u = 0; u < 8; u++) v[u] = X2[(size_t)s[u] * 32 + l];
#pragma unroll
        for (int u = 0; u < 8; u++) {
            float2 f0 = __half22float2(*reinterpret_cast<__half2*>(&v[u].x));
            float2 f1 = __half22float2(*reinterpret_cast<__half2*>(&v[u].y));
            a0.x += f0.x; a0.y += f0.y; a1.x += f1.x; a1.y += f1.y;
        }
    }
    for (; i < end; i++) {
        uint2 v = X2[(size_t)g_colidx[i] * 32 + l];
        float2 f0 = __half22float2(*reinterpret_cast<__half2*>(&v.x));
        float2 f1 = __half22float2(*reinterpret_cast<__half2*>(&v.y));
        a0.x += f0.x; a0.y += f0.y; a1.x += f1.x; a1.y += f1.y;
    }
    float inv = 1.f / fmaxf((float)(end - beg), 1.f);
    size_t base = (size_t)w * 256 + 128 + l * 4;
    *reinterpret_cast<__half2*>(g_a1 + base) =
        __halves2half2(__float2half_rn(a0.x * inv), __float2half_rn(a0.y * inv));
    *reinterpret_cast<__half2*>(g_a1 + base + 2) =
        __halves2half2(__float2half_rn(a1.x * inv), __float2half_rn(a1.y * inv));
    float4 xr = reinterpret_cast<const float4*>(x)[(size_t)w * 32 + l];
    base = (size_t)w * 256 + l * 4;
    *reinterpret_cast<__half2*>(g_a1 + base) =
        __halves2half2(__float2half_rn(xr.x), __float2half_rn(xr.y));
    *reinterpret_cast<__half2*>(g_a1 + base + 2) =
        __halves2half2(__float2half_rn(xr.z), __float2half_rn(xr.w));
}

// ---------------------------------------------------------------------------
// Layer-2 aggregation (unroll-8):
//   out[n][c] = mean_{s in N(n)} t16[s][c] + r[n][c]
// ---------------------------------------------------------------------------
__global__ void agg2_kernel(float* __restrict__ out, int N) {
    int w = (blockIdx.x * blockDim.x + threadIdx.x) >> 5;
    int l = threadIdx.x & 31;
    if (w >= N) return;
    int beg = g_rowptr[w], end = g_rowptr[w + 1];
    const uint2* T2 = reinterpret_cast<const uint2*>(g_t16);
    float2 a0 = make_float2(0.f, 0.f), a1 = make_float2(0.f, 0.f);
    int i = beg;
    for (; i + 7 < end; i += 8) {
        int s[8];
#pragma unroll
        for (int u = 0; u < 8; u++) s[u] = g_colidx[i + u];
        uint2 v[8];
#pragma unroll
        for (int u = 0; u < 8; u++) v[u] = T2[(size_t)s[u] * 32 + l];
#pragma unroll
        for (int u = 0; u < 8; u++) {
            float2 f0 = __half22float2(*reinterpret_cast<__half2*>(&v[u].x));
            float2 f1 = __half22float2(*reinterpret_cast<__half2*>(&v[u].y));
            a0.x += f0.x; a0.y += f0.y; a1.x += f1.x; a1.y += f1.y;
        }
    }
    for (; i < end; i++) {
        uint2 v = T2[(size_t)g_colidx[i] * 32 + l];
        float2 f0 = __half22float2(*reinterpret_cast<__half2*>(&v.x));
        float2 f1 = __half22float2(*reinterpret_cast<__half2*>(&v.y));
        a0.x += f0.x; a0.y += f0.y; a1.x += f1.x; a1.y += f1.y;
    }
    float inv = 1.f / fmaxf((float)(end - beg), 1.f);
    float4 r = reinterpret_cast<const float4*>(g_r)[(size_t)w * 32 + l];
    reinterpret_cast<float4*>(out)[(size_t)w * 32 + l] =
        make_float4(a0.x * inv + r.x, a0.y * inv + r.y,
                    a1.x * inv + r.z, a1.y * inv + r.w);
}

// ---------------------------------------------------------------------------
// HMMA GEMM, plain fp16 x fp16 (single pass — R12: dropped A-lo compensation).
// CTA tile 128x128, K=256 in 8 chunks of 32, cp.async double-buffered.
// grid = (o_tiles=2, n_tiles): o varies fastest -> A tile shared in L2.
// LAYER 1: epi relu(+b1l) -> fp16 g_a2
// LAYER 2: epi cols<128 -> fp16 g_t16; cols>=128 -> fp32 g_r (+b2l)
// ---------------------------------------------------------------------------
#define SPAD 40
#define TILE_B (128 * SPAD * 2)
#define GEMM_SMEM (4 * TILE_B)      // 2 bufs x {A,B}

template <int LAYER>
__global__ void __launch_bounds__(256)
mma_gemm_kernel(const float* __restrict__ bias, int N) {
    extern __shared__ char dsmem[];
    const uint32_t sbase = smem_to_u32(dsmem);

    const int tid  = threadIdx.x;
    const int lane = tid & 31;
    const int wid  = tid >> 5;
    const int wm   = (wid & 1) * 64;
    const int wn   = (wid >> 1) * 32;
    const int n0   = blockIdx.y * 128;       // node tile
    const int o0   = blockIdx.x * 128;       // out tile (fastest-varying)

    const __half* __restrict__ A = (LAYER == 1) ? g_a1 : g_a2;
    const __half* __restrict__ W = (LAYER == 1) ? g_w1 : g_w2;

    #define TILE_AT(buf, slot) (sbase + (uint32_t)(((buf) * 2 + (slot)) * TILE_B))

    const int lrow = tid >> 2;
    const int lcol = (tid & 3) * 8;

    const int arow = wm + (lane & 15);
    const int acol = (lane >> 4) * 8;
    const int brow = wn + (lane & 7) + ((lane >> 4) << 3);
    const int bcol = ((lane >> 3) & 1) * 8;

    float acc[4][4][4];
#pragma unroll
    for (int mi = 0; mi < 4; mi++)
#pragma unroll
        for (int ni = 0; ni < 4; ni++)
#pragma unroll
            for (int q = 0; q < 4; q++) acc[mi][ni][q] = 0.f;

    auto load_chunk = [&](int kc, int buf) {
#pragma unroll
        for (int i = 0; i < 2; i++) {
            int row = lrow + i * 64;
            int n = n0 + row;
            bool ok = n < N;
            size_t ga = (size_t)(ok ? n : 0) * 256 + kc + lcol;
            size_t gw = (size_t)(o0 + row) * 256 + kc + lcol;
            uint32_t so = (uint32_t)((row * SPAD + lcol) * 2);
            cp16(TILE_AT(buf, 0) + so, A + ga, ok);
            cp16(TILE_AT(buf, 1) + so, W + gw, true);
        }
        asm volatile("cp.async.commit_group;");
    };

    load_chunk(0, 0);

    for (int c = 0; c < 8; c++) {
        const int cur = c & 1;
        if (c < 7) {
            load_chunk((c + 1) * 32, 1 - cur);
            asm volatile("cp.async.wait_group 1;");
        } else {
            asm volatile("cp.async.wait_group 0;");
        }
        __syncthreads();

        const uint32_t uA = TILE_AT(cur, 0);
        const uint32_t uB = TILE_AT(cur, 1);
#pragma unroll
        for (int ks = 0; ks < 2; ks++) {
            const int k0 = ks * 16;
            uint32_t a[4][4], b[4][2];
#pragma unroll
            for (int mi = 0; mi < 4; mi++)
                ldsm_x4(a[mi], uA + ((arow + mi * 16) * SPAD + k0 + acol) * 2);
#pragma unroll
            for (int nip = 0; nip < 2; nip++) {
                uint32_t bb[4];
                ldsm_x4(bb, uB + ((brow + nip * 16) * SPAD + k0 + bcol) * 2);
                b[nip * 2][0]     = bb[0]; b[nip * 2][1]     = bb[1];
                b[nip * 2 + 1][0] = bb[2]; b[nip * 2 + 1][1] = bb[3];
            }
#pragma unroll
            for (int mi = 0; mi < 4; mi++)
#pragma unroll
                for (int ni = 0; ni < 4; ni++)
                    mma16816(acc[mi][ni], a[mi], b[ni]);
        }
        __syncthreads();
    }

    const int erow = lane >> 2;
    const int ecol = (lane & 3) * 2;
#pragma unroll
    for (int mi = 0; mi < 4; mi++) {
#pragma unroll
        for (int half = 0; half < 2; half++) {
            int n = n0 + wm + mi * 16 + erow + half * 8;
            if (n >= N) continue;
#pragma unroll
            for (int ni = 0; ni < 4; ni++) {
                int col = o0 + wn + ni * 8 + ecol;
                float v0 = acc[mi][ni][half * 2 + 0];
                float v1 = acc[mi][ni][half * 2 + 1];
                if (LAYER == 1) {
                    v0 = fmaxf(v0 + bias[col],     0.f);
                    v1 = fmaxf(v1 + bias[col + 1], 0.f);
                    *reinterpret_cast<__half2*>(g_a2 + (size_t)n * 256 + col) =
                        __halves2half2(__float2half_rn(v0), __float2half_rn(v1));
                } else {
                    if (col < 128) {
                        *reinterpret_cast<__half2*>(g_t16 + (size_t)n * 128 + col) =
                            __halves2half2(__float2half_rn(v0), __float2half_rn(v1));
                    } else {
                        v0 += bias[col - 128];
                        v1 += bias[col - 127];
                        *reinterpret_cast<float2*>(g_r + (size_t)n * 128 + (col - 128)) =
                            make_float2(v0, v1);
                    }
                }
            }
        }
    }
    #undef TILE_AT
}

// ---------------------------------------------------------------------------
// Launcher — kernel launches only; graph-capturable; no static state.
// ---------------------------------------------------------------------------
extern "C" void kernel_launch(void* const* d_in, const int* in_sizes, int n_in,
                              void* d_out, int out_size) {
    const float* x   = (const float*)d_in[0];
    const void*  ei  = d_in[1];
    const float* W1l = (const float*)d_in[2];
    const float* b1l = (const float*)d_in[3];
    const float* W1r = (const float*)d_in[4];
    const float* W2l = (const float*)d_in[5];
    const float* b2l = (const float*)d_in[6];
    const float* W2r = (const float*)d_in[7];
    float* out       = (float*)d_out;

    const int N  = in_sizes[0] / IN_CH;
    const int E  = in_sizes[1] / 2;
    const int NB = (N + 255) / 256;
    const int EB = (E + 255) / 256;
    const int XB = (N * 64 + 255) / 256;

    cudaFuncSetAttribute(mma_gemm_kernel<1>,
                         cudaFuncAttributeMaxDynamicSharedMemorySize, GEMM_SMEM);
    cudaFuncSetAttribute(mma_gemm_kernel<2>,
                         cudaFuncAttributeMaxDynamicSharedMemorySize, GEMM_SMEM);

    zero_sniff_kernel<<<NB, 256>>>((const int*)ei, N);
    hist_prep_kernel<<<EB + 512 + XB, 256>>>(ei, E, N, EB, W1l, W1r, W2l, W2r, x);
    scan_pass1<<<NB, 256>>>(N);
    scan_pass23<<<NB, 256>>>(NB, N);
    fill_kernel<<<EB, 256>>>(ei, E, N);
    agg1_kernel<<<(N * 32 + 255) / 256, 256>>>(x, N);
    {
        dim3 grid(2, (N + 127) / 128);
        mma_gemm_kernel<1><<<grid, 256, GEMM_SMEM>>>(b1l, N);
    }
    {
        dim3 grid(2, (N + 127) / 128);
        mma_gemm_kernel<2><<<grid, 256, GEMM_SMEM>>>(b2l, N);
    }
    agg2_kernel<<<(N * 32 + 255) / 256, 256>>>(out, N);
}

// round 13
// speedup vs baseline: 10.4535x; 1.0567x over previous
#include <cuda_runtime.h>
#include <cuda_bf16.h>
#include <cuda_fp16.h>
#include <cstdint>

#define MAX_N 50000
#define MAX_E 800000
#define IN_CH 128
#define HID_CH 256
#define OUT_CH 128
#define DMAX 128

// ---------------------------------------------------------------------------
// Device scratch (allocation-free rule). Zero-initialized at module load;
// g_fill is restored to zero by agg2 every call (deterministic invariant).
// ---------------------------------------------------------------------------
__device__ __align__(16) __half g_a1[(size_t)MAX_N * 256];    // layer-1 A, fp16
__device__ __align__(16) __half g_a2[(size_t)MAX_N * 256];    // layer-2 A, fp16
__device__ __align__(16) __half g_w1[256 * 256];              // composite W fp16
__device__ __align__(16) __half g_w2[256 * 256];
__device__ __align__(16) __half g_x16[(size_t)MAX_N * 128];   // x, fp16 (gather copy)
__device__ __align__(16) __half g_t16[(size_t)MAX_N * 128];   // layer-2 t half, fp16
__device__ float g_r[(size_t)MAX_N * 128];                    // layer-2 r half, fp32
__device__ int g_fill[MAX_N];                                 // degree counters
__device__ int g_colpad[(size_t)MAX_N * DMAX];                // padded CSR

// ---------------------------------------------------------------------------
// Helpers
// ---------------------------------------------------------------------------
__device__ __forceinline__ uint32_t smem_to_u32(const void* p) {
    uint32_t a;
    asm("{ .reg .u64 t; cvta.to.shared.u64 t, %1; cvt.u32.u64 %0, t; }"
        : "=r"(a) : "l"(p));
    return a;
}

__device__ __forceinline__ void ldsm_x4(uint32_t* r, uint32_t addr) {
    asm volatile("ldmatrix.sync.aligned.m8n8.x4.shared.b16 {%0,%1,%2,%3}, [%4];"
        : "=r"(r[0]), "=r"(r[1]), "=r"(r[2]), "=r"(r[3]) : "r"(addr));
}

__device__ __forceinline__ void mma16816(float* d, const uint32_t* a,
                                          const uint32_t* b) {
    asm volatile(
        "mma.sync.aligned.m16n8k16.row.col.f32.f16.f16.f32 "
        "{%0,%1,%2,%3}, {%4,%5,%6,%7}, {%8,%9}, {%0,%1,%2,%3};"
        : "+f"(d[0]), "+f"(d[1]), "+f"(d[2]), "+f"(d[3])
        : "r"(a[0]), "r"(a[1]), "r"(a[2]), "r"(a[3]), "r"(b[0]), "r"(b[1]));
}

__device__ __forceinline__ void cp16(uint32_t dst, const void* src, bool pred) {
    int sz = pred ? 16 : 0;
    asm volatile("cp.async.cg.shared.global [%0], [%1], 16, %2;"
        :: "r"(dst), "l"(src), "r"(sz));
}

// ---------------------------------------------------------------------------
// Kernel 1 (single edge pass): padded-CSR fill with per-block dtype self-sniff
//   blocks [0,EB):          edge fill (slot = atomicAdd(fill[dst]))
//   blocks [EB,EB+512):     fp16 weight prep
//   blocks [EB+512,+XB):    x -> fp16 gather copy
// ---------------------------------------------------------------------------
__global__ void fill_prep_kernel(const void* __restrict__ ei, int E, int N, int EB,
                                 const float* __restrict__ W1l,
                                 const float* __restrict__ W1r,
                                 const float* __restrict__ W2l,
                                 const float* __restrict__ W2r,
                                 const float* __restrict__ x) {
    int b = blockIdx.x, t = threadIdx.x;
    if (b < EB) {
        // per-block dtype sniff: OR of first 256 odd 32-bit words == 0 => int64
        __shared__ int red[256];
        red[t] = reinterpret_cast<const int*>(ei)[2 * t + 1];
        __syncthreads();
        for (int s = 128; s > 0; s >>= 1) {
            if (t < s) red[t] |= red[t + s];
            __syncthreads();
        }
        bool is64 = (red[0] == 0);
        int e = b * 256 + t;
        if (e >= E) return;
        int src, dst;
        if (is64) {
            src = (int)reinterpret_cast<const long long*>(ei)[e];
            dst = (int)reinterpret_cast<const long long*>(ei)[(size_t)E + e];
        } else {
            src = reinterpret_cast<const int*>(ei)[e];
            dst = reinterpret_cast<const int*>(ei)[(size_t)E + e];
        }
        if ((unsigned)src >= (unsigned)N || (unsigned)dst >= (unsigned)N) return;
        int slot = atomicAdd(&g_fill[dst], 1);
        if (slot < DMAX)
            g_colpad[(size_t)dst * DMAX + slot] = src;
    } else if (b < EB + 512) {
        int wb = b - EB;
        int idx = (wb & 255) * 256 + t;
        int o = idx >> 8, k = idx & 255;
        if (wb < 256) {   // layer1: k<128 -> W1r[o,k], else W1l[o,k-128]
            float v = (k < 128) ? W1r[o * 128 + k] : W1l[o * 128 + (k - 128)];
            g_w1[idx] = __float2half_rn(v);
        } else {          // layer2: o<128 -> W2l[o,k], else W2r[o-128,k]
            float v = (o < 128) ? W2l[o * 256 + k] : W2r[(o - 128) * 256 + k];
            g_w2[idx] = __float2half_rn(v);
        }
    } else {
        int idx = (b - EB - 512) * 256 + t;          // over N*64 float2s
        if (idx >= N * 64) return;
        float2 v = reinterpret_cast<const float2*>(x)[idx];
        reinterpret_cast<__half2*>(g_x16)[idx] = __float22half2_rn(v);
    }
}

// ---------------------------------------------------------------------------
// Layer-1 aggregation (padded CSR, unroll-8) -> single fp16 A:
//   cols 0..127 <- fp16(x[n]);  cols 128..255 <- fp16(mean_{s} x16[s])
// ---------------------------------------------------------------------------
__global__ void agg1_kernel(const float* __restrict__ x, int N) {
    int w = (blockIdx.x * blockDim.x + threadIdx.x) >> 5;
    int l = threadIdx.x & 31;
    if (w >= N) return;
    int deg = g_fill[w];
    int end = min(deg, DMAX);
    const int* col = g_colpad + (size_t)w * DMAX;
    const uint2* X2 = reinterpret_cast<const uint2*>(g_x16);
    float2 a0 = make_float2(0.f, 0.f), a1 = make_float2(0.f, 0.f);
    int i = 0;
    for (; i + 7 < end; i += 8) {
        int s[8];
#pragma unroll
        for (int u = 0; u < 8; u++) s[u] = col[i + u];
        uint2 v[8];
#pragma unroll
        for (int u = 0; u < 8; u++) v[u] = X2[(size_t)s[u] * 32 + l];
#pragma unroll
        for (int u = 0; u < 8; u++) {
            float2 f0 = __half22float2(*reinterpret_cast<__half2*>(&v[u].x));
            float2 f1 = __half22float2(*reinterpret_cast<__half2*>(&v[u].y));
            a0.x += f0.x; a0.y += f0.y; a1.x += f1.x; a1.y += f1.y;
        }
    }
    for (; i < end; i++) {
        uint2 v = X2[(size_t)col[i] * 32 + l];
        float2 f0 = __half22float2(*reinterpret_cast<__half2*>(&v.x));
        float2 f1 = __half22float2(*reinterpret_cast<__half2*>(&v.y));
        a0.x += f0.x; a0.y += f0.y; a1.x += f1.x; a1.y += f1.y;
    }
    float inv = 1.f / fmaxf((float)deg, 1.f);
    size_t base = (size_t)w * 256 + 128 + l * 4;
    *reinterpret_cast<__half2*>(g_a1 + base) =
        __halves2half2(__float2half_rn(a0.x * inv), __float2half_rn(a0.y * inv));
    *reinterpret_cast<__half2*>(g_a1 + base + 2) =
        __halves2half2(__float2half_rn(a1.x * inv), __float2half_rn(a1.y * inv));
    float4 xr = reinterpret_cast<const float4*>(x)[(size_t)w * 32 + l];
    base = (size_t)w * 256 + l * 4;
    *reinterpret_cast<__half2*>(g_a1 + base) =
        __halves2half2(__float2half_rn(xr.x), __float2half_rn(xr.y));
    *reinterpret_cast<__half2*>(g_a1 + base + 2) =
        __halves2half2(__float2half_rn(xr.z), __float2half_rn(xr.w));
}

// ---------------------------------------------------------------------------
// Layer-2 aggregation (padded CSR, unroll-8) + combine; restores g_fill to 0
// so every kernel_launch call starts from zeroed counters (deterministic).
//   out[n][c] = mean_{s in N(n)} t16[s][c] + r[n][c]
// ---------------------------------------------------------------------------
__global__ void agg2_kernel(float* __restrict__ out, int N) {
    int w = (blockIdx.x * blockDim.x + threadIdx.x) >> 5;
    int l = threadIdx.x & 31;
    if (w >= N) return;
    int deg = g_fill[w];
    int end = min(deg, DMAX);
    const int* col = g_colpad + (size_t)w * DMAX;
    const uint2* T2 = reinterpret_cast<const uint2*>(g_t16);
    float2 a0 = make_float2(0.f, 0.f), a1 = make_float2(0.f, 0.f);
    int i = 0;
    for (; i + 7 < end; i += 8) {
        int s[8];
#pragma unroll
        for (int u = 0; u < 8; u++) s[u] = col[i + u];
        uint2 v[8];
#pragma unroll
        for (int u = 0; u < 8; u++) v[u] = T2[(size_t)s[u] * 32 + l];
#pragma unroll
        for (int u = 0; u < 8; u++) {
            float2 f0 = __half22float2(*reinterpret_cast<__half2*>(&v[u].x));
            float2 f1 = __half22float2(*reinterpret_cast<__half2*>(&v[u].y));
            a0.x += f0.x; a0.y += f0.y; a1.x += f1.x; a1.y += f1.y;
        }
    }
    for (; i < end; i++) {
        uint2 v = T2[(size_t)col[i] * 32 + l];
        float2 f0 = __half22float2(*reinterpret_cast<__half2*>(&v.x));
        float2 f1 = __half22float2(*reinterpret_cast<__half2*>(&v.y));
        a0.x += f0.x; a0.y += f0.y; a1.x += f1.x; a1.y += f1.y;
    }
    float inv = 1.f / fmaxf((float)deg, 1.f);
    float4 r = reinterpret_cast<const float4*>(g_r)[(size_t)w * 32 + l];
    reinterpret_cast<float4*>(out)[(size_t)w * 32 + l] =
        make_float4(a0.x * inv + r.x, a0.y * inv + r.y,
                    a1.x * inv + r.z, a1.y * inv + r.w);
    __syncwarp();
    if (l == 0) g_fill[w] = 0;     // restore zero-counter invariant
}

// ---------------------------------------------------------------------------
// HMMA GEMM, plain fp16 x fp16 single pass (proven R12).
// CTA tile 128x128, K=256 in 8 chunks of 32, cp.async double-buffered.
// grid = (o_tiles=2, n_tiles); o varies fastest.
// LAYER 1: epi relu(+b1l) -> fp16 g_a2
// LAYER 2: epi cols<128 -> fp16 g_t16; cols>=128 -> fp32 g_r (+b2l)
// ---------------------------------------------------------------------------
#define SPAD 40
#define TILE_B (128 * SPAD * 2)
#define GEMM_SMEM (4 * TILE_B)

template <int LAYER>
__global__ void __launch_bounds__(256)
mma_gemm_kernel(const float* __restrict__ bias, int N) {
    extern __shared__ char dsmem[];
    const uint32_t sbase = smem_to_u32(dsmem);

    const int tid  = threadIdx.x;
    const int lane = tid & 31;
    const int wid  = tid >> 5;
    const int wm   = (wid & 1) * 64;
    const int wn   = (wid >> 1) * 32;
    const int n0   = blockIdx.y * 128;
    const int o0   = blockIdx.x * 128;

    const __half* __restrict__ A = (LAYER == 1) ? g_a1 : g_a2;
    const __half* __restrict__ W = (LAYER == 1) ? g_w1 : g_w2;

    #define TILE_AT(buf, slot) (sbase + (uint32_t)(((buf) * 2 + (slot)) * TILE_B))

    const int lrow = tid >> 2;
    const int lcol = (tid & 3) * 8;

    const int arow = wm + (lane & 15);
    const int acol = (lane >> 4) * 8;
    const int brow = wn + (lane & 7) + ((lane >> 4) << 3);
    const int bcol = ((lane >> 3) & 1) * 8;

    float acc[4][4][4];
#pragma unroll
    for (int mi = 0; mi < 4; mi++)
#pragma unroll
        for (int ni = 0; ni < 4; ni++)
#pragma unroll
            for (int q = 0; q < 4; q++) acc[mi][ni][q] = 0.f;

    auto load_chunk = [&](int kc, int buf) {
#pragma unroll
        for (int i = 0; i < 2; i++) {
            int row = lrow + i * 64;
            int n = n0 + row;
            bool ok = n < N;
            size_t ga = (size_t)(ok ? n : 0) * 256 + kc + lcol;
            size_t gw = (size_t)(o0 + row) * 256 + kc + lcol;
            uint32_t so = (uint32_t)((row * SPAD + lcol) * 2);
            cp16(TILE_AT(buf, 0) + so, A + ga, ok);
            cp16(TILE_AT(buf, 1) + so, W + gw, true);
        }
        asm volatile("cp.async.commit_group;");
    };

    load_chunk(0, 0);

    for (int c = 0; c < 8; c++) {
        const int cur = c & 1;
        if (c < 7) {
            load_chunk((c + 1) * 32, 1 - cur);
            asm volatile("cp.async.wait_group 1;");
        } else {
            asm volatile("cp.async.wait_group 0;");
        }
        __syncthreads();

        const uint32_t uA = TILE_AT(cur, 0);
        const uint32_t uB = TILE_AT(cur, 1);
#pragma unroll
        for (int ks = 0; ks < 2; ks++) {
            const int k0 = ks * 16;
            uint32_t a[4][4], b[4][2];
#pragma unroll
            for (int mi = 0; mi < 4; mi++)
                ldsm_x4(a[mi], uA + ((arow + mi * 16) * SPAD + k0 + acol) * 2);
#pragma unroll
            for (int nip = 0; nip < 2; nip++) {
                uint32_t bb[4];
                ldsm_x4(bb, uB + ((brow + nip * 16) * SPAD + k0 + bcol) * 2);
                b[nip * 2][0]     = bb[0]; b[nip * 2][1]     = bb[1];
                b[nip * 2 + 1][0] = bb[2]; b[nip * 2 + 1][1] = bb[3];
            }
#pragma unroll
            for (int mi = 0; mi < 4; mi++)
#pragma unroll
                for (int ni = 0; ni < 4; ni++)
                    mma16816(acc[mi][ni], a[mi], b[ni]);
        }
        __syncthreads();
    }

    const int erow = lane >> 2;
    const int ecol = (lane & 3) * 2;
#pragma unroll
    for (int mi = 0; mi < 4; mi++) {
#pragma unroll
        for (int half = 0; half < 2; half++) {
            int n = n0 + wm + mi * 16 + erow + half * 8;
            if (n >= N) continue;
#pragma unroll
            for (int ni = 0; ni < 4; ni++) {
                int col = o0 + wn + ni * 8 + ecol;
                float v0 = acc[mi][ni][half * 2 + 0];
                float v1 = acc[mi][ni][half * 2 + 1];
                if (LAYER == 1) {
                    v0 = fmaxf(v0 + bias[col],     0.f);
                    v1 = fmaxf(v1 + bias[col + 1], 0.f);
                    *reinterpret_cast<__half2*>(g_a2 + (size_t)n * 256 + col) =
                        __halves2half2(__float2half_rn(v0), __float2half_rn(v1));
                } else {
                    if (col < 128) {
                        *reinterpret_cast<__half2*>(g_t16 + (size_t)n * 128 + col) =
                            __halves2half2(__float2half_rn(v0), __float2half_rn(v1));
                    } else {
                        v0 += bias[col - 128];
                        v1 += bias[col - 127];
                        *reinterpret_cast<float2*>(g_r + (size_t)n * 128 + (col - 128)) =
                            make_float2(v0, v1);
                    }
                }
            }
        }
    }
    #undef TILE_AT
}

// ---------------------------------------------------------------------------
// Launcher — 5 kernel launches; graph-capturable; no static state.
// ---------------------------------------------------------------------------
extern "C" void kernel_launch(void* const* d_in, const int* in_sizes, int n_in,
                              void* d_out, int out_size) {
    const float* x   = (const float*)d_in[0];
    const void*  ei  = d_in[1];
    const float* W1l = (const float*)d_in[2];
    const float* b1l = (const float*)d_in[3];
    const float* W1r = (const float*)d_in[4];
    const float* W2l = (const float*)d_in[5];
    const float* b2l = (const float*)d_in[6];
    const float* W2r = (const float*)d_in[7];
    float* out       = (float*)d_out;

    const int N  = in_sizes[0] / IN_CH;
    const int E  = in_sizes[1] / 2;
    const int EB = (E + 255) / 256;
    const int XB = (N * 64 + 255) / 256;

    cudaFuncSetAttribute(mma_gemm_kernel<1>,
                         cudaFuncAttributeMaxDynamicSharedMemorySize, GEMM_SMEM);
    cudaFuncSetAttribute(mma_gemm_kernel<2>,
                         cudaFuncAttributeMaxDynamicSharedMemorySize, GEMM_SMEM);

    // 1: padded-CSR fill + weight split + x fp16 copy (one co-scheduled pass)
    fill_prep_kernel<<<EB + 512 + XB, 256>>>(ei, E, N, EB, W1l, W1r, W2l, W2r, x);
    // 2: layer-1 aggregation
    agg1_kernel<<<(N * 32 + 255) / 256, 256>>>(x, N);
    // 3,4: GEMMs
    {
        dim3 grid(2, (N + 127) / 128);
        mma_gemm_kernel<1><<<grid, 256, GEMM_SMEM>>>(b1l, N);
        mma_gemm_kernel<2><<<grid, 256, GEMM_SMEM>>>(b2l, N);
    }
    // 5: layer-2 aggregation + combine (+ counter restore)
    agg2_kernel<<<(N * 32 + 255) / 256, 256>>>(out, N);
}

// round 14
// speedup vs baseline: 11.0709x; 1.0591x over previous
#include <cuda_runtime.h>
#include <cuda_bf16.h>
#include <cuda_fp16.h>
#include <cstdint>

#define MAX_N 50000
#define MAX_E 800000
#define IN_CH 128
#define HID_CH 256
#define OUT_CH 128
#define DMAX 128

// ---------------------------------------------------------------------------
// Device scratch (allocation-free rule). Zero-initialized at module load;
// g_fill is restored to zero by agg2 every call (deterministic invariant).
// ---------------------------------------------------------------------------
__device__ __align__(16) __half g_a1[(size_t)MAX_N * 256];    // layer-1 A, fp16
__device__ __align__(16) __half g_a2[(size_t)MAX_N * 256];    // layer-2 A, fp16
__device__ __align__(16) __half g_w1[256 * 256];              // composite W fp16
__device__ __align__(16) __half g_w2[256 * 256];
__device__ __align__(16) __half g_x16[(size_t)MAX_N * 128];   // x, fp16 (gather copy)
__device__ __align__(16) __half g_t16[(size_t)MAX_N * 128];   // layer-2 t half, fp16
__device__ float g_r[(size_t)MAX_N * 128];                    // layer-2 r half, fp32
__device__ int g_fill[MAX_N];                                 // degree counters
__device__ int g_colpad[(size_t)MAX_N * DMAX];                // padded CSR

// ---------------------------------------------------------------------------
// Helpers
// ---------------------------------------------------------------------------
__device__ __forceinline__ uint32_t smem_to_u32(const void* p) {
    uint32_t a;
    asm("{ .reg .u64 t; cvta.to.shared.u64 t, %1; cvt.u32.u64 %0, t; }"
        : "=r"(a) : "l"(p));
    return a;
}

__device__ __forceinline__ void ldsm_x4(uint32_t* r, uint32_t addr) {
    asm volatile("ldmatrix.sync.aligned.m8n8.x4.shared.b16 {%0,%1,%2,%3}, [%4];"
        : "=r"(r[0]), "=r"(r[1]), "=r"(r[2]), "=r"(r[3]) : "r"(addr));
}

__device__ __forceinline__ void mma16816(float* d, const uint32_t* a,
                                          const uint32_t* b) {
    asm volatile(
        "mma.sync.aligned.m16n8k16.row.col.f32.f16.f16.f32 "
        "{%0,%1,%2,%3}, {%4,%5,%6,%7}, {%8,%9}, {%0,%1,%2,%3};"
        : "+f"(d[0]), "+f"(d[1]), "+f"(d[2]), "+f"(d[3])
        : "r"(a[0]), "r"(a[1]), "r"(a[2]), "r"(a[3]), "r"(b[0]), "r"(b[1]));
}

__device__ __forceinline__ void cp16(uint32_t dst, const void* src, bool pred) {
    int sz = pred ? 16 : 0;
    asm volatile("cp.async.cg.shared.global [%0], [%1], 16, %2;"
        :: "r"(dst), "l"(src), "r"(sz));
}

// ---------------------------------------------------------------------------
// Kernel 1 (single edge pass): padded-CSR fill with per-block dtype self-sniff
//   blocks [0,EB):          edge fill (slot = atomicAdd(fill[dst]))
//   blocks [EB,EB+512):     fp16 weight prep
//   blocks [EB+512,+XB):    x -> fp16 gather copy
// ---------------------------------------------------------------------------
__global__ void fill_prep_kernel(const void* __restrict__ ei, int E, int N, int EB,
                                 const float* __restrict__ W1l,
                                 const float* __restrict__ W1r,
                                 const float* __restrict__ W2l,
                                 const float* __restrict__ W2r,
                                 const float* __restrict__ x) {
    int b = blockIdx.x, t = threadIdx.x;
    if (b < EB) {
        __shared__ int red[256];
        red[t] = reinterpret_cast<const int*>(ei)[2 * t + 1];
        __syncthreads();
        for (int s = 128; s > 0; s >>= 1) {
            if (t < s) red[t] |= red[t + s];
            __syncthreads();
        }
        bool is64 = (red[0] == 0);
        int e = b * 256 + t;
        if (e >= E) return;
        int src, dst;
        if (is64) {
            src = (int)reinterpret_cast<const long long*>(ei)[e];
            dst = (int)reinterpret_cast<const long long*>(ei)[(size_t)E + e];
        } else {
            src = reinterpret_cast<const int*>(ei)[e];
            dst = reinterpret_cast<const int*>(ei)[(size_t)E + e];
        }
        if ((unsigned)src >= (unsigned)N || (unsigned)dst >= (unsigned)N) return;
        int slot = atomicAdd(&g_fill[dst], 1);
        if (slot < DMAX)
            g_colpad[(size_t)dst * DMAX + slot] = src;
    } else if (b < EB + 512) {
        int wb = b - EB;
        int idx = (wb & 255) * 256 + t;
        int o = idx >> 8, k = idx & 255;
        if (wb < 256) {
            float v = (k < 128) ? W1r[o * 128 + k] : W1l[o * 128 + (k - 128)];
            g_w1[idx] = __float2half_rn(v);
        } else {
            float v = (o < 128) ? W2l[o * 256 + k] : W2r[(o - 128) * 256 + k];
            g_w2[idx] = __float2half_rn(v);
        }
    } else {
        int idx = (b - EB - 512) * 256 + t;
        if (idx >= N * 64) return;
        float2 v = reinterpret_cast<const float2*>(x)[idx];
        reinterpret_cast<__half2*>(g_x16)[idx] = __float22half2_rn(v);
    }
}

// ---------------------------------------------------------------------------
// Layer-1 aggregation (padded CSR, unroll-8) -> single fp16 A:
//   cols 0..127 <- fp16(x[n]);  cols 128..255 <- fp16(mean_{s} x16[s])
// ---------------------------------------------------------------------------
__global__ void agg1_kernel(const float* __restrict__ x, int N) {
    int w = (blockIdx.x * blockDim.x + threadIdx.x) >> 5;
    int l = threadIdx.x & 31;
    if (w >= N) return;
    int deg = g_fill[w];
    int end = min(deg, DMAX);
    const int* col = g_colpad + (size_t)w * DMAX;
    const uint2* X2 = reinterpret_cast<const uint2*>(g_x16);
    float2 a0 = make_float2(0.f, 0.f), a1 = make_float2(0.f, 0.f);
    int i = 0;
    for (; i + 7 < end; i += 8) {
        int s[8];
#pragma unroll
        for (int u = 0; u < 8; u++) s[u] = col[i + u];
        uint2 v[8];
#pragma unroll
        for (int u = 0; u < 8; u++) v[u] = X2[(size_t)s[u] * 32 + l];
#pragma unroll
        for (int u = 0; u < 8; u++) {
            float2 f0 = __half22float2(*reinterpret_cast<__half2*>(&v[u].x));
            float2 f1 = __half22float2(*reinterpret_cast<__half2*>(&v[u].y));
            a0.x += f0.x; a0.y += f0.y; a1.x += f1.x; a1.y += f1.y;
        }
    }
    for (; i < end; i++) {
        uint2 v = X2[(size_t)col[i] * 32 + l];
        float2 f0 = __half22float2(*reinterpret_cast<__half2*>(&v.x));
        float2 f1 = __half22float2(*reinterpret_cast<__half2*>(&v.y));
        a0.x += f0.x; a0.y += f0.y; a1.x += f1.x; a1.y += f1.y;
    }
    float inv = 1.f / fmaxf((float)deg, 1.f);
    size_t base = (size_t)w * 256 + 128 + l * 4;
    *reinterpret_cast<__half2*>(g_a1 + base) =
        __halves2half2(__float2half_rn(a0.x * inv), __float2half_rn(a0.y * inv));
    *reinterpret_cast<__half2*>(g_a1 + base + 2) =
        __halves2half2(__float2half_rn(a1.x * inv), __float2half_rn(a1.y * inv));
    float4 xr = reinterpret_cast<const float4*>(x)[(size_t)w * 32 + l];
    base = (size_t)w * 256 + l * 4;
    *reinterpret_cast<__half2*>(g_a1 + base) =
        __halves2half2(__float2half_rn(xr.x), __float2half_rn(xr.y));
    *reinterpret_cast<__half2*>(g_a1 + base + 2) =
        __halves2half2(__float2half_rn(xr.z), __float2half_rn(xr.w));
}

// ---------------------------------------------------------------------------
// Layer-2 aggregation (padded CSR, unroll-8) + combine; restores g_fill to 0.
//   out[n][c] = mean_{s in N(n)} t16[s][c] + r[n][c]
// ---------------------------------------------------------------------------
__global__ void agg2_kernel(float* __restrict__ out, int N) {
    int w = (blockIdx.x * blockDim.x + threadIdx.x) >> 5;
    int l = threadIdx.x & 31;
    if (w >= N) return;
    int deg = g_fill[w];
    int end = min(deg, DMAX);
    const int* col = g_colpad + (size_t)w * DMAX;
    const uint2* T2 = reinterpret_cast<const uint2*>(g_t16);
    float2 a0 = make_float2(0.f, 0.f), a1 = make_float2(0.f, 0.f);
    int i = 0;
    for (; i + 7 < end; i += 8) {
        int s[8];
#pragma unroll
        for (int u = 0; u < 8; u++) s[u] = col[i + u];
        uint2 v[8];
#pragma unroll
        for (int u = 0; u < 8; u++) v[u] = T2[(size_t)s[u] * 32 + l];
#pragma unroll
        for (int u = 0; u < 8; u++) {
            float2 f0 = __half22float2(*reinterpret_cast<__half2*>(&v[u].x));
            float2 f1 = __half22float2(*reinterpret_cast<__half2*>(&v[u].y));
            a0.x += f0.x; a0.y += f0.y; a1.x += f1.x; a1.y += f1.y;
        }
    }
    for (; i < end; i++) {
        uint2 v = T2[(size_t)col[i] * 32 + l];
        float2 f0 = __half22float2(*reinterpret_cast<__half2*>(&v.x));
        float2 f1 = __half22float2(*reinterpret_cast<__half2*>(&v.y));
        a0.x += f0.x; a0.y += f0.y; a1.x += f1.x; a1.y += f1.y;
    }
    float inv = 1.f / fmaxf((float)deg, 1.f);
    float4 r = reinterpret_cast<const float4*>(g_r)[(size_t)w * 32 + l];
    reinterpret_cast<float4*>(out)[(size_t)w * 32 + l] =
        make_float4(a0.x * inv + r.x, a0.y * inv + r.y,
                    a1.x * inv + r.z, a1.y * inv + r.w);
    __syncwarp();
    if (l == 0) g_fill[w] = 0;
}

// ---------------------------------------------------------------------------
// HMMA GEMM, fp16 single pass. R14: K-chunk 64 (4 chunks), halving sync count
// (ncu R13: issue=22%, all pipes <45% -> barrier-latency-bound).
// CTA tile 128x128, 8 warps (2m x 4n), cp.async double-buffered.
// Smem rows: 72 halves (144B stride -> conflict-free ldmatrix phases).
// LAYER 1: epi relu(+b1l) -> fp16 g_a2
// LAYER 2: epi cols<128 -> fp16 g_t16; cols>=128 -> fp32 g_r (+b2l)
// ---------------------------------------------------------------------------
#define SPADK 72
#define TILE_B (128 * SPADK * 2)      // 18432 bytes
#define GEMM_SMEM (4 * TILE_B)        // 73728

template <int LAYER>
__global__ void __launch_bounds__(256)
mma_gemm_kernel(const float* __restrict__ bias, int N) {
    extern __shared__ char dsmem[];
    const uint32_t sbase = smem_to_u32(dsmem);

    const int tid  = threadIdx.x;
    const int lane = tid & 31;
    const int wid  = tid >> 5;
    const int wm   = (wid & 1) * 64;
    const int wn   = (wid >> 1) * 32;
    const int n0   = blockIdx.y * 128;
    const int o0   = blockIdx.x * 128;

    const __half* __restrict__ A = (LAYER == 1) ? g_a1 : g_a2;
    const __half* __restrict__ W = (LAYER == 1) ? g_w1 : g_w2;

    #define TILE_AT(buf, slot) (sbase + (uint32_t)(((buf) * 2 + (slot)) * TILE_B))

    // loader: 8 segments of 8 halves (16B) per 64-half row; 32 rows per pass
    const int seg  = tid & 7;
    const int row0 = tid >> 3;        // 0..31

    const int arow = wm + (lane & 15);
    const int acol = (lane >> 4) * 8;
    const int brow = wn + (lane & 7) + ((lane >> 4) << 3);
    const int bcol = ((lane >> 3) & 1) * 8;

    float acc[4][4][4];
#pragma unroll
    for (int mi = 0; mi < 4; mi++)
#pragma unroll
        for (int ni = 0; ni < 4; ni++)
#pragma unroll
            for (int q = 0; q < 4; q++) acc[mi][ni][q] = 0.f;

    auto load_chunk = [&](int kc, int buf) {
#pragma unroll
        for (int i = 0; i < 4; i++) {
            int row = row0 + i * 32;
            int n = n0 + row;
            bool ok = n < N;
            size_t ga = (size_t)(ok ? n : 0) * 256 + kc + seg * 8;
            size_t gw = (size_t)(o0 + row) * 256 + kc + seg * 8;
            uint32_t so = (uint32_t)((row * SPADK + seg * 8) * 2);
            cp16(TILE_AT(buf, 0) + so, A + ga, ok);
            cp16(TILE_AT(buf, 1) + so, W + gw, true);
        }
        asm volatile("cp.async.commit_group;");
    };

    load_chunk(0, 0);

    for (int c = 0; c < 4; c++) {
        const int cur = c & 1;
        if (c < 3) {
            load_chunk((c + 1) * 64, 1 - cur);
            asm volatile("cp.async.wait_group 1;");
        } else {
            asm volatile("cp.async.wait_group 0;");
        }
        __syncthreads();

        const uint32_t uA = TILE_AT(cur, 0);
        const uint32_t uB = TILE_AT(cur, 1);
#pragma unroll
        for (int ks = 0; ks < 4; ks++) {
            const int k0 = ks * 16;
            uint32_t a[4][4], b[4][2];
#pragma unroll
            for (int mi = 0; mi < 4; mi++)
                ldsm_x4(a[mi], uA + ((arow + mi * 16) * SPADK + k0 + acol) * 2);
#pragma unroll
            for (int nip = 0; nip < 2; nip++) {
                uint32_t bb[4];
                ldsm_x4(bb, uB + ((brow + nip * 16) * SPADK + k0 + bcol) * 2);
                b[nip * 2][0]     = bb[0]; b[nip * 2][1]     = bb[1];
                b[nip * 2 + 1][0] = bb[2]; b[nip * 2 + 1][1] = bb[3];
            }
#pragma unroll
            for (int mi = 0; mi < 4; mi++)
#pragma unroll
                for (int ni = 0; ni < 4; ni++)
                    mma16816(acc[mi][ni], a[mi], b[ni]);
        }
        __syncthreads();
    }

    const int erow = lane >> 2;
    const int ecol = (lane & 3) * 2;
#pragma unroll
    for (int mi = 0; mi < 4; mi++) {
#pragma unroll
        for (int half = 0; half < 2; half++) {
            int n = n0 + wm + mi * 16 + erow + half * 8;
            if (n >= N) continue;
#pragma unroll
            for (int ni = 0; ni < 4; ni++) {
                int col = o0 + wn + ni * 8 + ecol;
                float v0 = acc[mi][ni][half * 2 + 0];
                float v1 = acc[mi][ni][half * 2 + 1];
                if (LAYER == 1) {
                    v0 = fmaxf(v0 + bias[col],     0.f);
                    v1 = fmaxf(v1 + bias[col + 1], 0.f);
                    *reinterpret_cast<__half2*>(g_a2 + (size_t)n * 256 + col) =
                        __halves2half2(__float2half_rn(v0), __float2half_rn(v1));
                } else {
                    if (col < 128) {
                        *reinterpret_cast<__half2*>(g_t16 + (size_t)n * 128 + col) =
                            __halves2half2(__float2half_rn(v0), __float2half_rn(v1));
                    } else {
                        v0 += bias[col - 128];
                        v1 += bias[col - 127];
                        *reinterpret_cast<float2*>(g_r + (size_t)n * 128 + (col - 128)) =
                            make_float2(v0, v1);
                    }
                }
            }
        }
    }
    #undef TILE_AT
}

// ---------------------------------------------------------------------------
// Launcher — 5 kernel launches; graph-capturable; no static state.
// ---------------------------------------------------------------------------
extern "C" void kernel_launch(void* const* d_in, const int* in_sizes, int n_in,
                              void* d_out, int out_size) {
    const float* x   = (const float*)d_in[0];
    const void*  ei  = d_in[1];
    const float* W1l = (const float*)d_in[2];
    const float* b1l = (const float*)d_in[3];
    const float* W1r = (const float*)d_in[4];
    const float* W2l = (const float*)d_in[5];
    const float* b2l = (const float*)d_in[6];
    const float* W2r = (const float*)d_in[7];
    float* out       = (float*)d_out;

    const int N  = in_sizes[0] / IN_CH;
    const int E  = in_sizes[1] / 2;
    const int EB = (E + 255) / 256;
    const int XB = (N * 64 + 255) / 256;

    cudaFuncSetAttribute(mma_gemm_kernel<1>,
                         cudaFuncAttributeMaxDynamicSharedMemorySize, GEMM_SMEM);
    cudaFuncSetAttribute(mma_gemm_kernel<2>,
                         cudaFuncAttributeMaxDynamicSharedMemorySize, GEMM_SMEM);

    fill_prep_kernel<<<EB + 512 + XB, 256>>>(ei, E, N, EB, W1l, W1r, W2l, W2r, x);
    agg1_kernel<<<(N * 32 + 255) / 256, 256>>>(x, N);
    {
        dim3 grid(2, (N + 127) / 128);
        mma_gemm_kernel<1><<<grid, 256, GEMM_SMEM>>>(b1l, N);
        mma_gemm_kernel<2><<<grid, 256, GEMM_SMEM>>>(b2l, N);
    }
    agg2_kernel<<<(N * 32 + 255) / 256, 256>>>(out, N);
}

// round 15
// speedup vs baseline: 11.2220x; 1.0136x over previous
#include <cuda_runtime.h>
#include <cuda_bf16.h>
#include <cuda_fp16.h>
#include <cstdint>

#define MAX_N 50000
#define MAX_E 800000
#define IN_CH 128
#define HID_CH 256
#define OUT_CH 128
#define DMAX 128

// ---------------------------------------------------------------------------
// Device scratch (allocation-free rule). Zero-initialized at module load;
// g_fill is restored to zero by agg2 every call (deterministic invariant).
// ---------------------------------------------------------------------------
__device__ __align__(16) __half g_a1[(size_t)MAX_N * 256];    // layer-1 A, fp16
__device__ __align__(16) __half g_a2[(size_t)MAX_N * 256];    // layer-2 A, fp16
__device__ __align__(16) __half g_w1[256 * 256];              // composite W fp16
__device__ __align__(16) __half g_w2[256 * 256];
__device__ __align__(16) __half g_x16[(size_t)MAX_N * 128];   // x, fp16 (gather copy)
__device__ __align__(16) __half g_t16[(size_t)MAX_N * 128];   // layer-2 t half, fp16
__device__ float g_r[(size_t)MAX_N * 128];                    // layer-2 r half, fp32
__device__ int g_fill[MAX_N];                                 // degree counters
__device__ int g_colpad[(size_t)MAX_N * DMAX];                // padded CSR

// ---------------------------------------------------------------------------
// Helpers
// ---------------------------------------------------------------------------
__device__ __forceinline__ uint32_t smem_to_u32(const void* p) {
    uint32_t a;
    asm("{ .reg .u64 t; cvta.to.shared.u64 t, %1; cvt.u32.u64 %0, t; }"
        : "=r"(a) : "l"(p));
    return a;
}

__device__ __forceinline__ void ldsm_x4(uint32_t* r, uint32_t addr) {
    asm volatile("ldmatrix.sync.aligned.m8n8.x4.shared.b16 {%0,%1,%2,%3}, [%4];"
        : "=r"(r[0]), "=r"(r[1]), "=r"(r[2]), "=r"(r[3]) : "r"(addr));
}

__device__ __forceinline__ void mma16816(float* d, const uint32_t* a,
                                          const uint32_t* b) {
    asm volatile(
        "mma.sync.aligned.m16n8k16.row.col.f32.f16.f16.f32 "
        "{%0,%1,%2,%3}, {%4,%5,%6,%7}, {%8,%9}, {%0,%1,%2,%3};"
        : "+f"(d[0]), "+f"(d[1]), "+f"(d[2]), "+f"(d[3])
        : "r"(a[0]), "r"(a[1]), "r"(a[2]), "r"(a[3]), "r"(b[0]), "r"(b[1]));
}

__device__ __forceinline__ void cp16(uint32_t dst, const void* src, bool pred) {
    int sz = pred ? 16 : 0;
    asm volatile("cp.async.cg.shared.global [%0], [%1], 16, %2;"
        :: "r"(dst), "l"(src), "r"(sz));
}

// ---------------------------------------------------------------------------
// Kernel 1 (single edge pass): padded-CSR fill with per-block dtype self-sniff
//   blocks [0,EB):          edge fill (slot = atomicAdd(fill[dst]))
//   blocks [EB,EB+512):     fp16 weight prep
//   blocks [EB+512,+XB):    x -> fp16 gather copy
// ---------------------------------------------------------------------------
__global__ void fill_prep_kernel(const void* __restrict__ ei, int E, int N, int EB,
                                 const float* __restrict__ W1l,
                                 const float* __restrict__ W1r,
                                 const float* __restrict__ W2l,
                                 const float* __restrict__ W2r,
                                 const float* __restrict__ x) {
    int b = blockIdx.x, t = threadIdx.x;
    if (b < EB) {
        __shared__ int red[256];
        red[t] = reinterpret_cast<const int*>(ei)[2 * t + 1];
        __syncthreads();
        for (int s = 128; s > 0; s >>= 1) {
            if (t < s) red[t] |= red[t + s];
            __syncthreads();
        }
        bool is64 = (red[0] == 0);
        int e = b * 256 + t;
        if (e >= E) return;
        int src, dst;
        if (is64) {
            src = (int)reinterpret_cast<const long long*>(ei)[e];
            dst = (int)reinterpret_cast<const long long*>(ei)[(size_t)E + e];
        } else {
            src = reinterpret_cast<const int*>(ei)[e];
            dst = reinterpret_cast<const int*>(ei)[(size_t)E + e];
        }
        if ((unsigned)src >= (unsigned)N || (unsigned)dst >= (unsigned)N) return;
        int slot = atomicAdd(&g_fill[dst], 1);
        if (slot < DMAX)
            g_colpad[(size_t)dst * DMAX + slot] = src;
    } else if (b < EB + 512) {
        int wb = b - EB;
        int idx = (wb & 255) * 256 + t;
        int o = idx >> 8, k = idx & 255;
        if (wb < 256) {
            float v = (k < 128) ? W1r[o * 128 + k] : W1l[o * 128 + (k - 128)];
            g_w1[idx] = __float2half_rn(v);
        } else {
            float v = (o < 128) ? W2l[o * 256 + k] : W2r[(o - 128) * 256 + k];
            g_w2[idx] = __float2half_rn(v);
        }
    } else {
        int idx = (b - EB - 512) * 256 + t;
        if (idx >= N * 64) return;
        float2 v = reinterpret_cast<const float2*>(x)[idx];
        reinterpret_cast<__half2*>(g_x16)[idx] = __float22half2_rn(v);
    }
}

// ---------------------------------------------------------------------------
// Layer-1 aggregation (padded CSR, unroll-8) -> single fp16 A:
//   cols 0..127 <- fp16(x[n]);  cols 128..255 <- fp16(mean_{s} x16[s])
// ---------------------------------------------------------------------------
__global__ void agg1_kernel(const float* __restrict__ x, int N) {
    int w = (blockIdx.x * blockDim.x + threadIdx.x) >> 5;
    int l = threadIdx.x & 31;
    if (w >= N) return;
    int deg = g_fill[w];
    int end = min(deg, DMAX);
    const int* col = g_colpad + (size_t)w * DMAX;
    const uint2* X2 = reinterpret_cast<const uint2*>(g_x16);
    float2 a0 = make_float2(0.f, 0.f), a1 = make_float2(0.f, 0.f);
    int i = 0;
    for (; i + 7 < end; i += 8) {
        int s[8];
#pragma unroll
        for (int u = 0; u < 8; u++) s[u] = col[i + u];
        uint2 v[8];
#pragma unroll
        for (int u = 0; u < 8; u++) v[u] = X2[(size_t)s[u] * 32 + l];
#pragma unroll
        for (int u = 0; u < 8; u++) {
            float2 f0 = __half22float2(*reinterpret_cast<__half2*>(&v[u].x));
            float2 f1 = __half22float2(*reinterpret_cast<__half2*>(&v[u].y));
            a0.x += f0.x; a0.y += f0.y; a1.x += f1.x; a1.y += f1.y;
        }
    }
    for (; i < end; i++) {
        uint2 v = X2[(size_t)col[i] * 32 + l];
        float2 f0 = __half22float2(*reinterpret_cast<__half2*>(&v.x));
        float2 f1 = __half22float2(*reinterpret_cast<__half2*>(&v.y));
        a0.x += f0.x; a0.y += f0.y; a1.x += f1.x; a1.y += f1.y;
    }
    float inv = 1.f / fmaxf((float)deg, 1.f);
    size_t base = (size_t)w * 256 + 128 + l * 4;
    *reinterpret_cast<__half2*>(g_a1 + base) =
        __halves2half2(__float2half_rn(a0.x * inv), __float2half_rn(a0.y * inv));
    *reinterpret_cast<__half2*>(g_a1 + base + 2) =
        __halves2half2(__float2half_rn(a1.x * inv), __float2half_rn(a1.y * inv));
    float4 xr = reinterpret_cast<const float4*>(x)[(size_t)w * 32 + l];
    base = (size_t)w * 256 + l * 4;
    *reinterpret_cast<__half2*>(g_a1 + base) =
        __halves2half2(__float2half_rn(xr.x), __float2half_rn(xr.y));
    *reinterpret_cast<__half2*>(g_a1 + base + 2) =
        __halves2half2(__float2half_rn(xr.z), __float2half_rn(xr.w));
}

// ---------------------------------------------------------------------------
// Layer-2 aggregation (padded CSR, unroll-8) + combine; restores g_fill to 0.
//   out[n][c] = mean_{s in N(n)} t16[s][c] + r[n][c]
// ---------------------------------------------------------------------------
__global__ void agg2_kernel(float* __restrict__ out, int N) {
    int w = (blockIdx.x * blockDim.x + threadIdx.x) >> 5;
    int l = threadIdx.x & 31;
    if (w >= N) return;
    int deg = g_fill[w];
    int end = min(deg, DMAX);
    const int* col = g_colpad + (size_t)w * DMAX;
    const uint2* T2 = reinterpret_cast<const uint2*>(g_t16);
    float2 a0 = make_float2(0.f, 0.f), a1 = make_float2(0.f, 0.f);
    int i = 0;
    for (; i + 7 < end; i += 8) {
        int s[8];
#pragma unroll
        for (int u = 0; u < 8; u++) s[u] = col[i + u];
        uint2 v[8];
#pragma unroll
        for (int u = 0; u < 8; u++) v[u] = T2[(size_t)s[u] * 32 + l];
#pragma unroll
        for (int u = 0; u < 8; u++) {
            float2 f0 = __half22float2(*reinterpret_cast<__half2*>(&v[u].x));
            float2 f1 = __half22float2(*reinterpret_cast<__half2*>(&v[u].y));
            a0.x += f0.x; a0.y += f0.y; a1.x += f1.x; a1.y += f1.y;
        }
    }
    for (; i < end; i++) {
        uint2 v = T2[(size_t)col[i] * 32 + l];
        float2 f0 = __half22float2(*reinterpret_cast<__half2*>(&v.x));
        float2 f1 = __half22float2(*reinterpret_cast<__half2*>(&v.y));
        a0.x += f0.x; a0.y += f0.y; a1.x += f1.x; a1.y += f1.y;
    }
    float inv = 1.f / fmaxf((float)deg, 1.f);
    float4 r = reinterpret_cast<const float4*>(g_r)[(size_t)w * 32 + l];
    reinterpret_cast<float4*>(out)[(size_t)w * 32 + l] =
        make_float4(a0.x * inv + r.x, a0.y * inv + r.y,
                    a1.x * inv + r.z, a1.y * inv + r.w);
    __syncwarp();
    if (l == 0) g_fill[w] = 0;
}

// ---------------------------------------------------------------------------
// HMMA GEMM, fp16 single pass. R15: CTA tile 64(m) x 128(n), warp tile 32x32
// (8 warps, 2m x 4n), __launch_bounds__(256,3) -> 3 CTAs/SM (occ 37.5%).
// K=256 in 4 chunks of 64, cp.async double-buffered, SPADK=72 rows.
// LAYER 1: epi relu(+b1l) -> fp16 g_a2
// LAYER 2: epi cols<128 -> fp16 g_t16; cols>=128 -> fp32 g_r (+b2l)
// ---------------------------------------------------------------------------
#define SPADK 72
#define A_TILE_B (64 * SPADK * 2)         // 9216
#define B_TILE_B (128 * SPADK * 2)        // 18432
#define BUF_B (A_TILE_B + B_TILE_B)       // 27648
#define GEMM_SMEM (2 * BUF_B)             // 55296

template <int LAYER>
__global__ void __launch_bounds__(256, 3)
mma_gemm_kernel(const float* __restrict__ bias, int N) {
    extern __shared__ char dsmem[];
    const uint32_t sbase = smem_to_u32(dsmem);

    const int tid  = threadIdx.x;
    const int lane = tid & 31;
    const int wid  = tid >> 5;
    const int wm   = (wid & 1) * 32;          // warp m offset (0/32)
    const int wn   = (wid >> 1) * 32;         // warp n offset (0..96)
    const int n0   = blockIdx.y * 64;         // node tile (64 rows)
    const int o0   = blockIdx.x * 128;        // out tile

    const __half* __restrict__ A = (LAYER == 1) ? g_a1 : g_a2;
    const __half* __restrict__ W = (LAYER == 1) ? g_w1 : g_w2;

    #define A_AT(buf) (sbase + (uint32_t)((buf) * BUF_B))
    #define B_AT(buf) (sbase + (uint32_t)((buf) * BUF_B + A_TILE_B))

    // loader: 8 segments of 16B per 64-half row; 32 rows per pass
    const int seg  = tid & 7;
    const int row0 = tid >> 3;                // 0..31

    const int arow = wm + (lane & 15);
    const int acol = (lane >> 4) * 8;
    const int brow = wn + (lane & 7) + ((lane >> 4) << 3);
    const int bcol = ((lane >> 3) & 1) * 8;

    float acc[2][4][4];
#pragma unroll
    for (int mi = 0; mi < 2; mi++)
#pragma unroll
        for (int ni = 0; ni < 4; ni++)
#pragma unroll
            for (int q = 0; q < 4; q++) acc[mi][ni][q] = 0.f;

    auto load_chunk = [&](int kc, int buf) {
        // A: 64 rows (2 passes)
#pragma unroll
        for (int i = 0; i < 2; i++) {
            int row = row0 + i * 32;
            int n = n0 + row;
            bool ok = n < N;
            size_t ga = (size_t)(ok ? n : 0) * 256 + kc + seg * 8;
            uint32_t so = (uint32_t)((row * SPADK + seg * 8) * 2);
            cp16(A_AT(buf) + so, A + ga, ok);
        }
        // B: 128 rows (4 passes)
#pragma unroll
        for (int i = 0; i < 4; i++) {
            int row = row0 + i * 32;
            size_t gw = (size_t)(o0 + row) * 256 + kc + seg * 8;
            uint32_t so = (uint32_t)((row * SPADK + seg * 8) * 2);
            cp16(B_AT(buf) + so, W + gw, true);
        }
        asm volatile("cp.async.commit_group;");
    };

    load_chunk(0, 0);

    for (int c = 0; c < 4; c++) {
        const int cur = c & 1;
        if (c < 3) {
            load_chunk((c + 1) * 64, 1 - cur);
            asm volatile("cp.async.wait_group 1;");
        } else {
            asm volatile("cp.async.wait_group 0;");
        }
        __syncthreads();

        const uint32_t uA = A_AT(cur);
        const uint32_t uB = B_AT(cur);
#pragma unroll
        for (int ks = 0; ks < 4; ks++) {
            const int k0 = ks * 16;
            uint32_t a[2][4], b[4][2];
#pragma unroll
            for (int mi = 0; mi < 2; mi++)
                ldsm_x4(a[mi], uA + ((arow + mi * 16) * SPADK + k0 + acol) * 2);
#pragma unroll
            for (int nip = 0; nip < 2; nip++) {
                uint32_t bb[4];
                ldsm_x4(bb, uB + ((brow + nip * 16) * SPADK + k0 + bcol) * 2);
                b[nip * 2][0]     = bb[0]; b[nip * 2][1]     = bb[1];
                b[nip * 2 + 1][0] = bb[2]; b[nip * 2 + 1][1] = bb[3];
            }
#pragma unroll
            for (int mi = 0; mi < 2; mi++)
#pragma unroll
                for (int ni = 0; ni < 4; ni++)
                    mma16816(acc[mi][ni], a[mi], b[ni]);
        }
        __syncthreads();
    }

    const int erow = lane >> 2;
    const int ecol = (lane & 3) * 2;
#pragma unroll
    for (int mi = 0; mi < 2; mi++) {
#pragma unroll
        for (int half = 0; half < 2; half++) {
            int n = n0 + wm + mi * 16 + erow + half * 8;
            if (n >= N) continue;
#pragma unroll
            for (int ni = 0; ni < 4; ni++) {
                int col = o0 + wn + ni * 8 + ecol;
                float v0 = acc[mi][ni][half * 2 + 0];
                float v1 = acc[mi][ni][half * 2 + 1];
                if (LAYER == 1) {
                    v0 = fmaxf(v0 + bias[col],     0.f);
                    v1 = fmaxf(v1 + bias[col + 1], 0.f);
                    *reinterpret_cast<__half2*>(g_a2 + (size_t)n * 256 + col) =
                        __halves2half2(__float2half_rn(v0), __float2half_rn(v1));
                } else {
                    if (col < 128) {
                        *reinterpret_cast<__half2*>(g_t16 + (size_t)n * 128 + col) =
                            __halves2half2(__float2half_rn(v0), __float2half_rn(v1));
                    } else {
                        v0 += bias[col - 128];
                        v1 += bias[col - 127];
                        *reinterpret_cast<float2*>(g_r + (size_t)n * 128 + (col - 128)) =
                            make_float2(v0, v1);
                    }
                }
            }
        }
    }
    #undef A_AT
    #undef B_AT
}

// ---------------------------------------------------------------------------
// Launcher — 5 kernel launches; graph-capturable; no static state.
// ---------------------------------------------------------------------------
extern "C" void kernel_launch(void* const* d_in, const int* in_sizes, int n_in,
                              void* d_out, int out_size) {
    const float* x   = (const float*)d_in[0];
    const void*  ei  = d_in[1];
    const float* W1l = (const float*)d_in[2];
    const float* b1l = (const float*)d_in[3];
    const float* W1r = (const float*)d_in[4];
    const float* W2l = (const float*)d_in[5];
    const float* b2l = (const float*)d_in[6];
    const float* W2r = (const float*)d_in[7];
    float* out       = (float*)d_out;

    const int N  = in_sizes[0] / IN_CH;
    const int E  = in_sizes[1] / 2;
    const int EB = (E + 255) / 256;
    const int XB = (N * 64 + 255) / 256;

    cudaFuncSetAttribute(mma_gemm_kernel<1>,
                         cudaFuncAttributeMaxDynamicSharedMemorySize, GEMM_SMEM);
    cudaFuncSetAttribute(mma_gemm_kernel<2>,
                         cudaFuncAttributeMaxDynamicSharedMemorySize, GEMM_SMEM);

    fill_prep_kernel<<<EB + 512 + XB, 256>>>(ei, E, N, EB, W1l, W1r, W2l, W2r, x);
    agg1_kernel<<<(N * 32 + 255) / 256, 256>>>(x, N);
    {
        dim3 grid(2, (N + 63) / 64);
        mma_gemm_kernel<1><<<grid, 256, GEMM_SMEM>>>(b1l, N);
        mma_gemm_kernel<2><<<grid, 256, GEMM_SMEM>>>(b2l, N);
    }
    agg2_kernel<<<(N * 32 + 255) / 256, 256>>>(out, N);
}